// round 6
// baseline (speedup 1.0000x reference)
#include <cuda_runtime.h>
#include <math.h>
#include <stdint.h>

#define L_SEQ 32768
#define H_DIM 512
#define P_DIM 256
#define CHUNK 512
#define NCHUNK (L_SEQ / CHUNK)   // 64

// Scratch planes in [P][L] layout. Bu written by gemm1, overwritten in place
// with the scanned state x by scan_apply, consumed by gemm2.
__device__ float g_x_re[(size_t)P_DIM * L_SEQ];
__device__ float g_x_im[(size_t)P_DIM * L_SEQ];
__device__ float g_agg[P_DIM * NCHUNK * 4];
__device__ float g_pre[P_DIM * NCHUNK * 2];

// ---------------- common helpers ----------------

__device__ __forceinline__ void combine_right(float& Ar, float& Ai, float& br, float& bi,
                                              float pAr, float pAi, float pbr, float pbi)
{
    float nAr = Ar*pAr - Ai*pAi;
    float nAi = Ar*pAi + Ai*pAr;
    float nbr = Ar*pbr - Ai*pbi + br;
    float nbi = Ar*pbi + Ai*pbr + bi;
    Ar = nAr; Ai = nAi; br = nbr; bi = nbi;
}

__device__ __forceinline__ void combine_left(float& Ar, float& Ai, float& br, float& bi,
                                             float rAr, float rAi, float rbr, float rbi)
{
    float nAr = rAr*Ar - rAi*Ai;
    float nAi = rAr*Ai + rAi*Ar;
    float nbr = rAr*br - rAi*bi + rbr;
    float nbi = rAr*bi + rAi*br + rbi;
    Ar = nAr; Ai = nAi; br = nbr; bi = nbi;
}

__device__ __forceinline__ void lambda_bar(float lre, float lim, float Dl, float& Ar, float& Ai)
{
    float e = expf(lre * Dl);
    float s, c;
    sincosf(lim * Dl, &s, &c);
    Ar = e * c;
    Ai = e * s;
}

__device__ __forceinline__ uint32_t f2tf32(float x)
{
    uint32_t r;
    asm("cvt.rna.tf32.f32 %0, %1;" : "=r"(r) : "f"(x));
    return r;
}

__device__ __forceinline__ void mma_tf32(float* d, const uint32_t* a, uint32_t b0, uint32_t b1)
{
    asm volatile(
        "mma.sync.aligned.m16n8k8.row.col.f32.tf32.tf32.f32 "
        "{%0,%1,%2,%3}, {%4,%5,%6,%7}, {%8,%9}, {%0,%1,%2,%3};"
        : "+f"(d[0]), "+f"(d[1]), "+f"(d[2]), "+f"(d[3])
        : "r"(a[0]), "r"(a[1]), "r"(a[2]), "r"(a[3]), "r"(b0), "r"(b1));
}

// k-permutation within an 8-group: [k0,k4,k1,k5,k2,k6,k3,k7]
__device__ __forceinline__ int kperm(int k7) { return (k7 < 4) ? (2 * k7) : (2 * (k7 - 4) + 1); }

// ======================== GEMM1 (tf32 mma, ping-pong): Bu = gamma_bar * (u @ B^T) ===============
#define G1_BM 128
#define G1_BN 128
#define G1_BK 32
#define G1_K8P (G1_BM * 8 + 8)   // 1032 floats per k8 plane (128 rows)
#define G1_A_OFF 0
#define G1_BR_OFF (4 * G1_K8P)
#define G1_BI_OFF (G1_BR_OFF + 4 * G1_K8P)
#define G1_BUF (G1_BI_OFF + 4 * G1_K8P)      // 12384 floats per buffer
#define G1_SMEM_BYTES (2 * G1_BUF * 4)       // 99072 B

__global__ __launch_bounds__(512, 1) void gemm1(
    const float* __restrict__ u, const float* __restrict__ Bre, const float* __restrict__ Bim,
    const float* __restrict__ dtv, const float* __restrict__ Lre_g, const float* __restrict__ Lim_g,
    const float* __restrict__ logstep)
{
    extern __shared__ uint32_t smx[];
    const int tid = threadIdx.x;
    const int wid = tid >> 5, lane = tid & 31;
    const int g = lane >> 2, t = lane & 3;
    const int wm = wid >> 2, wn = wid & 3;
    const int bm = blockIdx.y * G1_BM;
    const int bn = blockIdx.x * G1_BN;

    // per-thread fill constants (idx = tid, tid+512; 128 rows x 8 k4-groups)
    const int row0 = tid >> 3,          k40 = tid & 7;
    const int row1 = (tid + 512) >> 3,  k41 = (tid + 512) & 7;
    const float* pA0 = u + (size_t)(bm + row0) * H_DIM + k40 * 4;
    const float* pA1 = u + (size_t)(bm + row1) * H_DIM + k41 * 4;
    const float* pBr0 = Bre + (size_t)(bn + row0) * H_DIM + k40 * 4;
    const float* pBr1 = Bre + (size_t)(bn + row1) * H_DIM + k41 * 4;
    const float* pBi0 = Bim + (size_t)(bn + row0) * H_DIM + k40 * 4;
    const float* pBi1 = Bim + (size_t)(bn + row1) * H_DIM + k41 * 4;
    const int so0 = (k40 >> 1) * G1_K8P + row0 * 8 + (k40 & 1);
    const int so1 = (k41 >> 1) * G1_K8P + row1 * 8 + (k41 & 1);

    float4 aR0, aR1, bR0, bR1, bI0, bI1;

    auto LD = [&](int kt) {
        aR0 = *(const float4*)(pA0 + kt);
        aR1 = *(const float4*)(pA1 + kt);
        bR0 = *(const float4*)(pBr0 + kt);
        bR1 = *(const float4*)(pBr1 + kt);
        bI0 = *(const float4*)(pBi0 + kt);
        bI1 = *(const float4*)(pBi1 + kt);
    };
    auto ST = [&](uint32_t* s) {
        uint32_t* a = s + G1_A_OFF;
        a[so0 + 0] = f2tf32(aR0.x); a[so0 + 2] = f2tf32(aR0.y);
        a[so0 + 4] = f2tf32(aR0.z); a[so0 + 6] = f2tf32(aR0.w);
        a[so1 + 0] = f2tf32(aR1.x); a[so1 + 2] = f2tf32(aR1.y);
        a[so1 + 4] = f2tf32(aR1.z); a[so1 + 6] = f2tf32(aR1.w);
        uint32_t* br = s + G1_BR_OFF;
        br[so0 + 0] = f2tf32(bR0.x); br[so0 + 2] = f2tf32(bR0.y);
        br[so0 + 4] = f2tf32(bR0.z); br[so0 + 6] = f2tf32(bR0.w);
        br[so1 + 0] = f2tf32(bR1.x); br[so1 + 2] = f2tf32(bR1.y);
        br[so1 + 4] = f2tf32(bR1.z); br[so1 + 6] = f2tf32(bR1.w);
        uint32_t* bi = s + G1_BI_OFF;
        bi[so0 + 0] = f2tf32(bI0.x); bi[so0 + 2] = f2tf32(bI0.y);
        bi[so0 + 4] = f2tf32(bI0.z); bi[so0 + 6] = f2tf32(bI0.w);
        bi[so1 + 0] = f2tf32(bI1.x); bi[so1 + 2] = f2tf32(bI1.y);
        bi[so1 + 4] = f2tf32(bI1.z); bi[so1 + 6] = f2tf32(bI1.w);
    };

    float accr[2][4][4];
    float acci[2][4][4];
#pragma unroll
    for (int i = 0; i < 2; i++)
#pragma unroll
        for (int j = 0; j < 4; j++)
#pragma unroll
            for (int r = 0; r < 4; r++) { accr[i][j][r] = 0.0f; acci[i][j][r] = 0.0f; }

    LD(0);
    ST(smx);
    __syncthreads();

    const int NS = H_DIM / G1_BK;  // 16
    for (int s = 0; s < NS; s++) {
        uint32_t* cur = smx + (s & 1) * G1_BUF;
        if (s + 1 < NS) LD((s + 1) * G1_BK);

#pragma unroll
        for (int k8 = 0; k8 < 4; k8++) {
            uint32_t a[2][4];
#pragma unroll
            for (int mt = 0; mt < 2; mt++) {
                int row = wm * 32 + mt * 16 + g;
                const uint32_t* p0 = cur + G1_A_OFF + k8 * G1_K8P + row * 8 + 2 * t;
                uint2 lo = *(const uint2*)p0;
                uint2 hi = *(const uint2*)(p0 + 64);
                a[mt][0] = lo.x; a[mt][2] = lo.y;
                a[mt][1] = hi.x; a[mt][3] = hi.y;
            }
#pragma unroll
            for (int nt = 0; nt < 4; nt++) {
                int row = wn * 32 + nt * 8 + g;
                uint2 br = *(const uint2*)(cur + G1_BR_OFF + k8 * G1_K8P + row * 8 + 2 * t);
                uint2 bi = *(const uint2*)(cur + G1_BI_OFF + k8 * G1_K8P + row * 8 + 2 * t);
#pragma unroll
                for (int mt = 0; mt < 2; mt++) {
                    mma_tf32(accr[mt][nt], a[mt], br.x, br.y);
                    mma_tf32(acci[mt][nt], a[mt], bi.x, bi.y);
                }
            }
        }

        if (s + 1 < NS) ST(smx + ((s + 1) & 1) * G1_BUF);
        __syncthreads();
    }

    // epilogue: gamma_bar multiply, store to [P][L] planes
    float dts[2][2];
#pragma unroll
    for (int mt = 0; mt < 2; mt++)
#pragma unroll
        for (int rh = 0; rh < 2; rh++)
            dts[mt][rh] = dtv[bm + wm * 32 + mt * 16 + g + rh * 8];

#pragma unroll
    for (int nt = 0; nt < 4; nt++) {
#pragma unroll
        for (int c = 0; c < 2; c++) {
            int p = bn + wn * 32 + nt * 8 + 2 * t + c;
            float lre = Lre_g[p], lim = Lim_g[p];
            float stp = expf(logstep[p]);
            float inv = 1.0f / (lre * lre + lim * lim);
#pragma unroll
            for (int mt = 0; mt < 2; mt++) {
#pragma unroll
                for (int rh = 0; rh < 2; rh++) {
                    int l = bm + wm * 32 + mt * 16 + g + rh * 8;
                    float Dl = dts[mt][rh] * stp;
                    float Ar, Ai;
                    lambda_bar(lre, lim, Dl, Ar, Ai);
                    float gr = ((Ar - 1.0f) * lre + Ai * lim) * inv;
                    float gi = (Ai * lre - (Ar - 1.0f) * lim) * inv;
                    int reg = rh * 2 + c;
                    float ar = accr[mt][nt][reg], ai = acci[mt][nt][reg];
                    size_t o = (size_t)p * L_SEQ + l;
                    g_x_re[o] = gr * ar - gi * ai;
                    g_x_im[o] = gr * ai + gi * ar;
                }
            }
        }
    }
}

// ======================== Scan phase A ========================
__global__ __launch_bounds__(512) void scan_agg(
    const float* __restrict__ dtv, const float* __restrict__ Lre_g,
    const float* __restrict__ Lim_g, const float* __restrict__ logstep)
{
    const int p = blockIdx.y;
    const int chunk = blockIdx.x;
    const int tid = threadIdx.x;
    const int l = chunk * CHUNK + tid;

    float lre = Lre_g[p], lim = Lim_g[p];
    float stp = expf(logstep[p]);
    float Ar, Ai;
    lambda_bar(lre, lim, dtv[l] * stp, Ar, Ai);
    float br = g_x_re[(size_t)p * L_SEQ + l];
    float bi = g_x_im[(size_t)p * L_SEQ + l];

#pragma unroll
    for (int off = 1; off < 32; off <<= 1) {
        float rAr = __shfl_down_sync(0xFFFFFFFFu, Ar, off);
        float rAi = __shfl_down_sync(0xFFFFFFFFu, Ai, off);
        float rbr = __shfl_down_sync(0xFFFFFFFFu, br, off);
        float rbi = __shfl_down_sync(0xFFFFFFFFu, bi, off);
        combine_left(Ar, Ai, br, bi, rAr, rAi, rbr, rbi);
    }

    __shared__ float sA_r[16], sA_i[16], sb_r[16], sb_i[16];
    int lane = tid & 31, wid = tid >> 5;
    if (lane == 0) { sA_r[wid] = Ar; sA_i[wid] = Ai; sb_r[wid] = br; sb_i[wid] = bi; }
    __syncthreads();

    if (wid == 0) {
        float aAr = (lane < 16) ? sA_r[lane] : 1.0f;
        float aAi = (lane < 16) ? sA_i[lane] : 0.0f;
        float abr = (lane < 16) ? sb_r[lane] : 0.0f;
        float abi = (lane < 16) ? sb_i[lane] : 0.0f;
#pragma unroll
        for (int off = 1; off < 16; off <<= 1) {
            float rAr = __shfl_down_sync(0xFFFFFFFFu, aAr, off);
            float rAi = __shfl_down_sync(0xFFFFFFFFu, aAi, off);
            float rbr = __shfl_down_sync(0xFFFFFFFFu, abr, off);
            float rbi = __shfl_down_sync(0xFFFFFFFFu, abi, off);
            combine_left(aAr, aAi, abr, abi, rAr, rAi, rbr, rbi);
        }
        if (lane == 0) {
            size_t o = ((size_t)p * NCHUNK + chunk) * 4;
            g_agg[o + 0] = aAr; g_agg[o + 1] = aAi;
            g_agg[o + 2] = abr; g_agg[o + 3] = abi;
        }
    }
}

// ======================== Scan phase B ========================
__global__ __launch_bounds__(64) void chunk_prefix()
{
    const int p = blockIdx.x;
    const int tid = threadIdx.x;
    size_t o = ((size_t)p * NCHUNK + tid) * 4;
    float Ar = g_agg[o + 0], Ai = g_agg[o + 1];
    float br = g_agg[o + 2], bi = g_agg[o + 3];

    int lane = tid & 31, wid = tid >> 5;
#pragma unroll
    for (int off = 1; off < 32; off <<= 1) {
        float pAr = __shfl_up_sync(0xFFFFFFFFu, Ar, off);
        float pAi = __shfl_up_sync(0xFFFFFFFFu, Ai, off);
        float pbr = __shfl_up_sync(0xFFFFFFFFu, br, off);
        float pbi = __shfl_up_sync(0xFFFFFFFFu, bi, off);
        if (lane >= off) combine_right(Ar, Ai, br, bi, pAr, pAi, pbr, pbi);
    }

    __shared__ float w0[4];
    __shared__ float sb[NCHUNK][2];
    if (wid == 0 && lane == 31) { w0[0] = Ar; w0[1] = Ai; w0[2] = br; w0[3] = bi; }
    __syncthreads();
    if (wid == 1) combine_right(Ar, Ai, br, bi, w0[0], w0[1], w0[2], w0[3]);
    sb[tid][0] = br; sb[tid][1] = bi;
    __syncthreads();

    float pr = tid ? sb[tid - 1][0] : 0.0f;
    float pi = tid ? sb[tid - 1][1] : 0.0f;
    size_t q = ((size_t)p * NCHUNK + tid) * 2;
    g_pre[q] = pr; g_pre[q + 1] = pi;
}

// ======================== Scan phase C ========================
__global__ __launch_bounds__(512) void scan_apply(
    const float* __restrict__ dtv, const float* __restrict__ Lre_g,
    const float* __restrict__ Lim_g, const float* __restrict__ logstep)
{
    const int p = blockIdx.y;
    const int chunk = blockIdx.x;
    const int tid = threadIdx.x;
    const int l = chunk * CHUNK + tid;

    float lre = Lre_g[p], lim = Lim_g[p];
    float stp = expf(logstep[p]);
    float Ar, Ai;
    lambda_bar(lre, lim, dtv[l] * stp, Ar, Ai);
    float br = g_x_re[(size_t)p * L_SEQ + l];
    float bi = g_x_im[(size_t)p * L_SEQ + l];

    int lane = tid & 31, wid = tid >> 5;
#pragma unroll
    for (int off = 1; off < 32; off <<= 1) {
        float pAr = __shfl_up_sync(0xFFFFFFFFu, Ar, off);
        float pAi = __shfl_up_sync(0xFFFFFFFFu, Ai, off);
        float pbr = __shfl_up_sync(0xFFFFFFFFu, br, off);
        float pbi = __shfl_up_sync(0xFFFFFFFFu, bi, off);
        if (lane >= off) combine_right(Ar, Ai, br, bi, pAr, pAi, pbr, pbi);
    }

    __shared__ float sA_r[16], sA_i[16], sb_r[16], sb_i[16];
    if (lane == 31) { sA_r[wid] = Ar; sA_i[wid] = Ai; sb_r[wid] = br; sb_i[wid] = bi; }
    __syncthreads();

    if (wid == 0) {
        float aAr = (lane < 16) ? sA_r[lane] : 1.0f;
        float aAi = (lane < 16) ? sA_i[lane] : 0.0f;
        float abr = (lane < 16) ? sb_r[lane] : 0.0f;
        float abi = (lane < 16) ? sb_i[lane] : 0.0f;
#pragma unroll
        for (int off = 1; off < 16; off <<= 1) {
            float pAr = __shfl_up_sync(0xFFFFFFFFu, aAr, off);
            float pAi = __shfl_up_sync(0xFFFFFFFFu, aAi, off);
            float pbr = __shfl_up_sync(0xFFFFFFFFu, abr, off);
            float pbi = __shfl_up_sync(0xFFFFFFFFu, abi, off);
            if (lane >= off && lane < 16) combine_right(aAr, aAi, abr, abi, pAr, pAi, pbr, pbi);
        }
        if (lane < 16) { sA_r[lane] = aAr; sA_i[lane] = aAi; sb_r[lane] = abr; sb_i[lane] = abi; }
    }
    __syncthreads();

    if (wid > 0)
        combine_right(Ar, Ai, br, bi, sA_r[wid - 1], sA_i[wid - 1], sb_r[wid - 1], sb_i[wid - 1]);

    size_t q = ((size_t)p * NCHUNK + chunk) * 2;
    float pr = g_pre[q], pi = g_pre[q + 1];
    float xr = Ar * pr - Ai * pi + br;
    float xi = Ar * pi + Ai * pr + bi;
    g_x_re[(size_t)p * L_SEQ + l] = xr;
    g_x_im[(size_t)p * L_SEQ + l] = xi;
}

// ======================== GEMM2 (tf32 mma, ping-pong): y = 2*(xre Cre^T - xim Cim^T) + D*u =====
// Symmetric 128x128 tiling; Cim negated at smem fill so one accumulator chain works.
#define G2_BM 128
#define G2_BN 128
#define G2_BK 32
#define G2_K8P (128 * 8 + 8)     // 1032
#define G2_AR_OFF 0
#define G2_AI_OFF (4 * G2_K8P)
#define G2_BR_OFF (8 * G2_K8P)
#define G2_BI_OFF (12 * G2_K8P)
#define G2_BUF (16 * G2_K8P)               // 16512 floats per buffer
#define G2_SMEM_BYTES (2 * G2_BUF * 4)     // 132096 B

__global__ __launch_bounds__(512, 1) void gemm2(
    const float* __restrict__ Cre, const float* __restrict__ Cim,
    const float* __restrict__ u, const float* __restrict__ Dg,
    float* __restrict__ out)
{
    extern __shared__ uint32_t smx[];
    const int tid = threadIdx.x;
    const int wid = tid >> 5, lane = tid & 31;
    const int g = lane >> 2, t = lane & 3;
    const int wm = wid >> 2, wn = wid & 3;
    const int bm = blockIdx.y * G2_BM;   // l
    const int bn = blockIdx.x * G2_BN;   // h

    // A fill constants (x planes, [P][L]): idx -> l4 group (idx&31), k=p_local (idx>>5)
    const int al0 = (tid & 31) * 4,          ak0 = tid >> 5;          // k 0..15
    const int al1 = ((tid + 512) & 31) * 4,  ak1 = (tid + 512) >> 5;  // k 16..31
    const float* pXr0 = g_x_re + (size_t)ak0 * L_SEQ + bm + al0;
    const float* pXr1 = g_x_re + (size_t)ak1 * L_SEQ + bm + al1;
    const float* pXi0 = g_x_im + (size_t)ak0 * L_SEQ + bm + al0;
    const float* pXi1 = g_x_im + (size_t)ak1 * L_SEQ + bm + al1;
    const int ao0 = (ak0 >> 3) * G2_K8P + al0 * 8 + kperm(ak0 & 7);
    const int ao1 = (ak1 >> 3) * G2_K8P + al1 * 8 + kperm(ak1 & 7);

    // B fill constants (C planes, (H,P)): 128 rows h x 8 k4 groups
    const int brw0 = tid >> 3,         bk40 = tid & 7;
    const int brw1 = (tid + 512) >> 3, bk41 = (tid + 512) & 7;
    const float* pCr0 = Cre + (size_t)(bn + brw0) * P_DIM + bk40 * 4;
    const float* pCr1 = Cre + (size_t)(bn + brw1) * P_DIM + bk41 * 4;
    const float* pCi0 = Cim + (size_t)(bn + brw0) * P_DIM + bk40 * 4;
    const float* pCi1 = Cim + (size_t)(bn + brw1) * P_DIM + bk41 * 4;
    const int bo0 = (bk40 >> 1) * G2_K8P + brw0 * 8 + (bk40 & 1);
    const int bo1 = (bk41 >> 1) * G2_K8P + brw1 * 8 + (bk41 & 1);

    float4 xR0, xR1, xI0, xI1, cR0, cR1, cI0, cI1;

    auto LD = [&](int kt) {
        size_t ks = (size_t)kt * L_SEQ;
        xR0 = *(const float4*)(pXr0 + ks);
        xR1 = *(const float4*)(pXr1 + ks);
        xI0 = *(const float4*)(pXi0 + ks);
        xI1 = *(const float4*)(pXi1 + ks);
        cR0 = *(const float4*)(pCr0 + kt);
        cR1 = *(const float4*)(pCr1 + kt);
        cI0 = *(const float4*)(pCi0 + kt);
        cI1 = *(const float4*)(pCi1 + kt);
    };
    auto ST = [&](uint32_t* s) {
        uint32_t* ar = s + G2_AR_OFF;
        ar[ao0 + 0]  = f2tf32(xR0.x); ar[ao0 + 8]  = f2tf32(xR0.y);
        ar[ao0 + 16] = f2tf32(xR0.z); ar[ao0 + 24] = f2tf32(xR0.w);
        ar[ao1 + 0]  = f2tf32(xR1.x); ar[ao1 + 8]  = f2tf32(xR1.y);
        ar[ao1 + 16] = f2tf32(xR1.z); ar[ao1 + 24] = f2tf32(xR1.w);
        uint32_t* ai = s + G2_AI_OFF;
        ai[ao0 + 0]  = f2tf32(xI0.x); ai[ao0 + 8]  = f2tf32(xI0.y);
        ai[ao0 + 16] = f2tf32(xI0.z); ai[ao0 + 24] = f2tf32(xI0.w);
        ai[ao1 + 0]  = f2tf32(xI1.x); ai[ao1 + 8]  = f2tf32(xI1.y);
        ai[ao1 + 16] = f2tf32(xI1.z); ai[ao1 + 24] = f2tf32(xI1.w);
        uint32_t* br = s + G2_BR_OFF;
        br[bo0 + 0] = f2tf32(cR0.x); br[bo0 + 2] = f2tf32(cR0.y);
        br[bo0 + 4] = f2tf32(cR0.z); br[bo0 + 6] = f2tf32(cR0.w);
        br[bo1 + 0] = f2tf32(cR1.x); br[bo1 + 2] = f2tf32(cR1.y);
        br[bo1 + 4] = f2tf32(cR1.z); br[bo1 + 6] = f2tf32(cR1.w);
        uint32_t* bi = s + G2_BI_OFF;
        bi[bo0 + 0] = f2tf32(-cI0.x); bi[bo0 + 2] = f2tf32(-cI0.y);
        bi[bo0 + 4] = f2tf32(-cI0.z); bi[bo0 + 6] = f2tf32(-cI0.w);
        bi[bo1 + 0] = f2tf32(-cI1.x); bi[bo1 + 2] = f2tf32(-cI1.y);
        bi[bo1 + 4] = f2tf32(-cI1.z); bi[bo1 + 6] = f2tf32(-cI1.w);
    };

    float acc[2][4][4];
#pragma unroll
    for (int i = 0; i < 2; i++)
#pragma unroll
        for (int j = 0; j < 4; j++)
#pragma unroll
            for (int r = 0; r < 4; r++) acc[i][j][r] = 0.0f;

    LD(0);
    ST(smx);
    __syncthreads();

    const int NS = P_DIM / G2_BK;  // 8
    for (int s = 0; s < NS; s++) {
        uint32_t* cur = smx + (s & 1) * G2_BUF;
        if (s + 1 < NS) LD((s + 1) * G2_BK);

#pragma unroll
        for (int k8 = 0; k8 < 4; k8++) {
            uint32_t ar[2][4], ai[2][4];
#pragma unroll
            for (int mt = 0; mt < 2; mt++) {
                int row = wm * 32 + mt * 16 + g;
                const uint32_t* pr = cur + G2_AR_OFF + k8 * G2_K8P + row * 8 + 2 * t;
                uint2 lo = *(const uint2*)pr;
                uint2 hi = *(const uint2*)(pr + 64);
                ar[mt][0] = lo.x; ar[mt][2] = lo.y; ar[mt][1] = hi.x; ar[mt][3] = hi.y;
                const uint32_t* pi = cur + G2_AI_OFF + k8 * G2_K8P + row * 8 + 2 * t;
                uint2 lo2 = *(const uint2*)pi;
                uint2 hi2 = *(const uint2*)(pi + 64);
                ai[mt][0] = lo2.x; ai[mt][2] = lo2.y; ai[mt][1] = hi2.x; ai[mt][3] = hi2.y;
            }
#pragma unroll
            for (int nt = 0; nt < 4; nt++) {
                int row = wn * 32 + nt * 8 + g;
                uint2 br = *(const uint2*)(cur + G2_BR_OFF + k8 * G2_K8P + row * 8 + 2 * t);
                uint2 bi = *(const uint2*)(cur + G2_BI_OFF + k8 * G2_K8P + row * 8 + 2 * t);
#pragma unroll
                for (int mt = 0; mt < 2; mt++) {
                    mma_tf32(acc[mt][nt], ar[mt], br.x, br.y);
                    mma_tf32(acc[mt][nt], ai[mt], bi.x, bi.y);
                }
            }
        }

        if (s + 1 < NS) ST(smx + ((s + 1) & 1) * G2_BUF);
        __syncthreads();
    }

    // epilogue: y = 2*acc + D*u
#pragma unroll
    for (int mt = 0; mt < 2; mt++) {
#pragma unroll
        for (int rh = 0; rh < 2; rh++) {
            int l = bm + wm * 32 + mt * 16 + g + rh * 8;
#pragma unroll
            for (int nt = 0; nt < 4; nt++) {
                int h0 = bn + wn * 32 + nt * 8 + 2 * t;
                float2 uu = *(const float2*)(u + (size_t)l * H_DIM + h0);
                float2 dd = *(const float2*)(Dg + h0);
                float2 o;
                o.x = 2.0f * acc[mt][nt][rh * 2 + 0] + dd.x * uu.x;
                o.y = 2.0f * acc[mt][nt][rh * 2 + 1] + dd.y * uu.y;
                *(float2*)(out + (size_t)l * H_DIM + h0) = o;
            }
        }
    }
}

// ======================== launch ========================
extern "C" void kernel_launch(void* const* d_in, const int* in_sizes, int n_in,
                              void* d_out, int out_size)
{
    const float* u   = (const float*)d_in[0];  // (L, H)
    const float* dtv = (const float*)d_in[1];  // (L,)
    const float* Lre = (const float*)d_in[2];  // (P,)
    const float* Lim = (const float*)d_in[3];  // (P,)
    const float* Bre = (const float*)d_in[4];  // (P, H)
    const float* Bim = (const float*)d_in[5];  // (P, H)
    const float* Cre = (const float*)d_in[6];  // (H, P)
    const float* Cim = (const float*)d_in[7];  // (H, P)
    const float* Dg  = (const float*)d_in[8];  // (H,)
    const float* lst = (const float*)d_in[9];  // (P,)
    float* out = (float*)d_out;                // (L, H)

    static int attr_done = 0;
    if (!attr_done) {
        cudaFuncSetAttribute(gemm1, cudaFuncAttributeMaxDynamicSharedMemorySize, G1_SMEM_BYTES);
        cudaFuncSetAttribute(gemm2, cudaFuncAttributeMaxDynamicSharedMemorySize, G2_SMEM_BYTES);
        attr_done = 1;
    }

    gemm1<<<dim3(P_DIM / G1_BN, L_SEQ / G1_BM), 512, G1_SMEM_BYTES>>>(u, Bre, Bim, dtv, Lre, Lim, lst);
    scan_agg<<<dim3(NCHUNK, P_DIM), 512>>>(dtv, Lre, Lim, lst);
    chunk_prefix<<<P_DIM, 64>>>();
    scan_apply<<<dim3(NCHUNK, P_DIM), 512>>>(dtv, Lre, Lim, lst);
    gemm2<<<dim3(H_DIM / G2_BN, L_SEQ / G2_BM), 512, G2_SMEM_BYTES>>>(Cre, Cim, u, Dg, out);
}

// round 7
// speedup vs baseline: 1.3334x; 1.3334x over previous
#include <cuda_runtime.h>
#include <math.h>
#include <stdint.h>

#define L_SEQ 32768
#define H_DIM 512
#define P_DIM 256
#define VPT 8
#define SCAN_T 256
#define CHUNK (SCAN_T * VPT)        // 2048
#define NCHUNK (L_SEQ / CHUNK)      // 16

// Scratch planes in [P][L] layout. Bu written by gemm1, overwritten in place
// with the scanned state x by scan_apply, consumed by gemm2.
__device__ float g_x_re[(size_t)P_DIM * L_SEQ];
__device__ float g_x_im[(size_t)P_DIM * L_SEQ];
__device__ float g_agg[P_DIM * NCHUNK * 4];
__device__ float g_pre[P_DIM * NCHUNK * 2];

// ---------------- common helpers ----------------

// result = later(A,b) composed with earlier(p*): (A*pA, A*pb + b)
__device__ __forceinline__ void combine_right(float& Ar, float& Ai, float& br, float& bi,
                                              float pAr, float pAi, float pbr, float pbi)
{
    float nAr = Ar*pAr - Ai*pAi;
    float nAi = Ar*pAi + Ai*pAr;
    float nbr = Ar*pbr - Ai*pbi + br;
    float nbi = Ar*pbi + Ai*pbr + bi;
    Ar = nAr; Ai = nAi; br = nbr; bi = nbi;
}

// self earlier, r* later: (rA*A, rA*b + rb)
__device__ __forceinline__ void combine_left(float& Ar, float& Ai, float& br, float& bi,
                                             float rAr, float rAi, float rbr, float rbi)
{
    float nAr = rAr*Ar - rAi*Ai;
    float nAi = rAr*Ai + rAi*Ar;
    float nbr = rAr*br - rAi*bi + rbr;
    float nbi = rAr*bi + rAi*br + rbi;
    Ar = nAr; Ai = nAi; br = nbr; bi = nbi;
}

__device__ __forceinline__ void lambda_bar(float lre, float lim, float Dl, float& Ar, float& Ai)
{
    float e = expf(lre * Dl);
    float s, c;
    sincosf(lim * Dl, &s, &c);
    Ar = e * c;
    Ai = e * s;
}

__device__ __forceinline__ uint32_t f2tf32(float x)
{
    uint32_t r;
    asm("cvt.rna.tf32.f32 %0, %1;" : "=r"(r) : "f"(x));
    return r;
}

__device__ __forceinline__ void mma_tf32(float* d, const uint32_t* a, uint32_t b0, uint32_t b1)
{
    asm volatile(
        "mma.sync.aligned.m16n8k8.row.col.f32.tf32.tf32.f32 "
        "{%0,%1,%2,%3}, {%4,%5,%6,%7}, {%8,%9}, {%0,%1,%2,%3};"
        : "+f"(d[0]), "+f"(d[1]), "+f"(d[2]), "+f"(d[3])
        : "r"(a[0]), "r"(a[1]), "r"(a[2]), "r"(a[3]), "r"(b0), "r"(b1));
}

// k-permutation within an 8-group: [k0,k4,k1,k5,k2,k6,k3,k7]
__device__ __forceinline__ int kperm(int k7) { return (k7 < 4) ? (2 * k7) : (2 * (k7 - 4) + 1); }

// ======================== GEMM1 (tf32 mma): Bu = gamma_bar * (u @ B^T) ========================
// (R5-proven single-buffer version)
#define G1_BM 128
#define G1_BN 128
#define G1_BK 32
#define G1_AK8 (G1_BM * 8 + 8)   // 1032
#define G1_BK8 (G1_BN * 8 + 8)   // 1032
#define G1_A_OFF 0
#define G1_BR_OFF (4 * G1_AK8)
#define G1_BI_OFF (G1_BR_OFF + 4 * G1_BK8)
#define G1_SMEM_FLOATS (G1_BI_OFF + 4 * G1_BK8)
#define G1_SMEM_BYTES (G1_SMEM_FLOATS * 4)

__global__ __launch_bounds__(512, 1) void gemm1(
    const float* __restrict__ u, const float* __restrict__ Bre, const float* __restrict__ Bim,
    const float* __restrict__ dtv, const float* __restrict__ Lre_g, const float* __restrict__ Lim_g,
    const float* __restrict__ logstep)
{
    extern __shared__ uint32_t sm1[];
    const int tid = threadIdx.x;
    const int wid = tid >> 5, lane = tid & 31;
    const int g = lane >> 2, t = lane & 3;
    const int wm = wid >> 2, wn = wid & 3;
    const int bm = blockIdx.y * G1_BM;
    const int bn = blockIdx.x * G1_BN;

    float accr[2][4][4];
    float acci[2][4][4];
#pragma unroll
    for (int i = 0; i < 2; i++)
#pragma unroll
        for (int j = 0; j < 4; j++)
#pragma unroll
            for (int r = 0; r < 4; r++) { accr[i][j][r] = 0.0f; acci[i][j][r] = 0.0f; }

    for (int kt = 0; kt < H_DIM; kt += G1_BK) {
#pragma unroll
        for (int r = 0; r < 2; r++) {
            int idx = tid + r * 512;
            int row = idx >> 3, k4 = idx & 7;
            float4 v = *(const float4*)(u + (size_t)(bm + row) * H_DIM + kt + k4 * 4);
            int base = G1_A_OFF + (k4 >> 1) * G1_AK8 + row * 8 + (k4 & 1);
            sm1[base + 0] = f2tf32(v.x); sm1[base + 2] = f2tf32(v.y);
            sm1[base + 4] = f2tf32(v.z); sm1[base + 6] = f2tf32(v.w);
        }
#pragma unroll
        for (int r = 0; r < 2; r++) {
            int idx = tid + r * 512;
            int row = idx >> 3, k4 = idx & 7;
            int off = (k4 >> 1) * G1_BK8 + row * 8 + (k4 & 1);
            float4 vr = *(const float4*)(Bre + (size_t)(bn + row) * H_DIM + kt + k4 * 4);
            sm1[G1_BR_OFF + off + 0] = f2tf32(vr.x); sm1[G1_BR_OFF + off + 2] = f2tf32(vr.y);
            sm1[G1_BR_OFF + off + 4] = f2tf32(vr.z); sm1[G1_BR_OFF + off + 6] = f2tf32(vr.w);
            float4 vi = *(const float4*)(Bim + (size_t)(bn + row) * H_DIM + kt + k4 * 4);
            sm1[G1_BI_OFF + off + 0] = f2tf32(vi.x); sm1[G1_BI_OFF + off + 2] = f2tf32(vi.y);
            sm1[G1_BI_OFF + off + 4] = f2tf32(vi.z); sm1[G1_BI_OFF + off + 6] = f2tf32(vi.w);
        }
        __syncthreads();

#pragma unroll
        for (int k8 = 0; k8 < 4; k8++) {
            uint32_t a[2][4];
#pragma unroll
            for (int mt = 0; mt < 2; mt++) {
                int row = wm * 32 + mt * 16 + g;
                const uint32_t* p0 = &sm1[G1_A_OFF + k8 * G1_AK8 + row * 8 + 2 * t];
                uint2 lo = *(const uint2*)p0;
                uint2 hi = *(const uint2*)(p0 + 64);
                a[mt][0] = lo.x; a[mt][2] = lo.y;
                a[mt][1] = hi.x; a[mt][3] = hi.y;
            }
#pragma unroll
            for (int nt = 0; nt < 4; nt++) {
                int row = wn * 32 + nt * 8 + g;
                uint2 br = *(const uint2*)&sm1[G1_BR_OFF + k8 * G1_BK8 + row * 8 + 2 * t];
                uint2 bi = *(const uint2*)&sm1[G1_BI_OFF + k8 * G1_BK8 + row * 8 + 2 * t];
#pragma unroll
                for (int mt = 0; mt < 2; mt++) {
                    mma_tf32(accr[mt][nt], a[mt], br.x, br.y);
                    mma_tf32(acci[mt][nt], a[mt], bi.x, bi.y);
                }
            }
        }
        __syncthreads();
    }

    float dts[2][2];
#pragma unroll
    for (int mt = 0; mt < 2; mt++)
#pragma unroll
        for (int rh = 0; rh < 2; rh++)
            dts[mt][rh] = dtv[bm + wm * 32 + mt * 16 + g + rh * 8];

#pragma unroll
    for (int nt = 0; nt < 4; nt++) {
#pragma unroll
        for (int c = 0; c < 2; c++) {
            int p = bn + wn * 32 + nt * 8 + 2 * t + c;
            float lre = Lre_g[p], lim = Lim_g[p];
            float stp = expf(logstep[p]);
            float inv = 1.0f / (lre * lre + lim * lim);
#pragma unroll
            for (int mt = 0; mt < 2; mt++) {
#pragma unroll
                for (int rh = 0; rh < 2; rh++) {
                    int l = bm + wm * 32 + mt * 16 + g + rh * 8;
                    float Dl = dts[mt][rh] * stp;
                    float Ar, Ai;
                    lambda_bar(lre, lim, Dl, Ar, Ai);
                    float gr = ((Ar - 1.0f) * lre + Ai * lim) * inv;
                    float gi = (Ai * lre - (Ar - 1.0f) * lim) * inv;
                    int reg = rh * 2 + c;
                    float ar = accr[mt][nt][reg], ai = acci[mt][nt][reg];
                    size_t o = (size_t)p * L_SEQ + l;
                    g_x_re[o] = gr * ar - gi * ai;
                    g_x_im[o] = gr * ai + gi * ar;
                }
            }
        }
    }
}

// ======================== Scan phase A: serial-8 per thread, then reduce ========================
__global__ __launch_bounds__(SCAN_T) void scan_agg(
    const float* __restrict__ dtv, const float* __restrict__ Lre_g,
    const float* __restrict__ Lim_g, const float* __restrict__ logstep)
{
    const int p = blockIdx.y;
    const int chunk = blockIdx.x;
    const int tid = threadIdx.x;
    const int l0 = chunk * CHUNK + tid * VPT;

    const float lre = Lre_g[p], lim = Lim_g[p];
    const float stp = expf(logstep[p]);
    const float* xr = g_x_re + (size_t)p * L_SEQ + l0;
    const float* xi = g_x_im + (size_t)p * L_SEQ + l0;

    float dt[VPT], bvr[VPT], bvi[VPT];
    {
        float4 d0 = *(const float4*)(dtv + l0);
        float4 d1 = *(const float4*)(dtv + l0 + 4);
        dt[0]=d0.x; dt[1]=d0.y; dt[2]=d0.z; dt[3]=d0.w;
        dt[4]=d1.x; dt[5]=d1.y; dt[6]=d1.z; dt[7]=d1.w;
        float4 r0 = *(const float4*)(xr), r1 = *(const float4*)(xr + 4);
        bvr[0]=r0.x; bvr[1]=r0.y; bvr[2]=r0.z; bvr[3]=r0.w;
        bvr[4]=r1.x; bvr[5]=r1.y; bvr[6]=r1.z; bvr[7]=r1.w;
        float4 i0 = *(const float4*)(xi), i1 = *(const float4*)(xi + 4);
        bvi[0]=i0.x; bvi[1]=i0.y; bvi[2]=i0.z; bvi[3]=i0.w;
        bvi[4]=i1.x; bvi[5]=i1.y; bvi[6]=i1.z; bvi[7]=i1.w;
    }

    // serial inclusive aggregate over VPT elements
    float Ar, Ai, br, bi;
    lambda_bar(lre, lim, dt[0] * stp, Ar, Ai);
    br = bvr[0]; bi = bvi[0];
#pragma unroll
    for (int e = 1; e < VPT; e++) {
        float Aer, Aei;
        lambda_bar(lre, lim, dt[e] * stp, Aer, Aei);
        float nAr = Aer*Ar - Aei*Ai;
        float nAi = Aer*Ai + Aei*Ar;
        float nbr = Aer*br - Aei*bi + bvr[e];
        float nbi = Aer*bi + Aei*br + bvi[e];
        Ar = nAr; Ai = nAi; br = nbr; bi = nbi;
    }

    // warp reduce (ordered, lane 0 ends with warp aggregate)
#pragma unroll
    for (int off = 1; off < 32; off <<= 1) {
        float rAr = __shfl_down_sync(0xFFFFFFFFu, Ar, off);
        float rAi = __shfl_down_sync(0xFFFFFFFFu, Ai, off);
        float rbr = __shfl_down_sync(0xFFFFFFFFu, br, off);
        float rbi = __shfl_down_sync(0xFFFFFFFFu, bi, off);
        combine_left(Ar, Ai, br, bi, rAr, rAi, rbr, rbi);
    }

    __shared__ float sA_r[8], sA_i[8], sb_r[8], sb_i[8];
    int lane = tid & 31, wid = tid >> 5;
    if (lane == 0) { sA_r[wid] = Ar; sA_i[wid] = Ai; sb_r[wid] = br; sb_i[wid] = bi; }
    __syncthreads();

    if (wid == 0) {
        float aAr = (lane < 8) ? sA_r[lane] : 1.0f;
        float aAi = (lane < 8) ? sA_i[lane] : 0.0f;
        float abr = (lane < 8) ? sb_r[lane] : 0.0f;
        float abi = (lane < 8) ? sb_i[lane] : 0.0f;
#pragma unroll
        for (int off = 1; off < 8; off <<= 1) {
            float rAr = __shfl_down_sync(0xFFFFFFFFu, aAr, off);
            float rAi = __shfl_down_sync(0xFFFFFFFFu, aAi, off);
            float rbr = __shfl_down_sync(0xFFFFFFFFu, abr, off);
            float rbi = __shfl_down_sync(0xFFFFFFFFu, abi, off);
            combine_left(aAr, aAi, abr, abi, rAr, rAi, rbr, rbi);
        }
        if (lane == 0) {
            size_t o = ((size_t)p * NCHUNK + chunk) * 4;
            g_agg[o + 0] = aAr; g_agg[o + 1] = aAi;
            g_agg[o + 2] = abr; g_agg[o + 3] = abi;
        }
    }
}

// ======================== Scan phase B: per-p exclusive scan over 16 chunk aggregates ===========
__global__ __launch_bounds__(32) void chunk_prefix()
{
    const int p = blockIdx.x;
    const int lane = threadIdx.x;

    float Ar = 1.0f, Ai = 0.0f, br = 0.0f, bi = 0.0f;
    if (lane < NCHUNK) {
        size_t o = ((size_t)p * NCHUNK + lane) * 4;
        Ar = g_agg[o + 0]; Ai = g_agg[o + 1];
        br = g_agg[o + 2]; bi = g_agg[o + 3];
    }

#pragma unroll
    for (int off = 1; off < NCHUNK; off <<= 1) {
        float pAr = __shfl_up_sync(0xFFFFFFFFu, Ar, off);
        float pAi = __shfl_up_sync(0xFFFFFFFFu, Ai, off);
        float pbr = __shfl_up_sync(0xFFFFFFFFu, br, off);
        float pbi = __shfl_up_sync(0xFFFFFFFFu, bi, off);
        if (lane >= off) combine_right(Ar, Ai, br, bi, pAr, pAi, pbr, pbi);
    }

    // exclusive shift: prefix for chunk c = inclusive of c-1
    float er = __shfl_up_sync(0xFFFFFFFFu, br, 1);
    float ei = __shfl_up_sync(0xFFFFFFFFu, bi, 1);
    if (lane == 0) { er = 0.0f; ei = 0.0f; }
    if (lane < NCHUNK) {
        size_t q = ((size_t)p * NCHUNK + lane) * 2;
        g_pre[q] = er; g_pre[q + 1] = ei;
    }
}

// ======================== Scan phase C: serial-8 inclusive + prefix apply ========================
__global__ __launch_bounds__(SCAN_T) void scan_apply(
    const float* __restrict__ dtv, const float* __restrict__ Lre_g,
    const float* __restrict__ Lim_g, const float* __restrict__ logstep)
{
    const int p = blockIdx.y;
    const int chunk = blockIdx.x;
    const int tid = threadIdx.x;
    const int l0 = chunk * CHUNK + tid * VPT;
    const int lane = tid & 31, wid = tid >> 5;

    const float lre = Lre_g[p], lim = Lim_g[p];
    const float stp = expf(logstep[p]);
    float* xr = g_x_re + (size_t)p * L_SEQ + l0;
    float* xi = g_x_im + (size_t)p * L_SEQ + l0;

    float dt[VPT], bvr[VPT], bvi[VPT];
    {
        float4 d0 = *(const float4*)(dtv + l0);
        float4 d1 = *(const float4*)(dtv + l0 + 4);
        dt[0]=d0.x; dt[1]=d0.y; dt[2]=d0.z; dt[3]=d0.w;
        dt[4]=d1.x; dt[5]=d1.y; dt[6]=d1.z; dt[7]=d1.w;
        float4 r0 = *(const float4*)(xr), r1 = *(const float4*)(xr + 4);
        bvr[0]=r0.x; bvr[1]=r0.y; bvr[2]=r0.z; bvr[3]=r0.w;
        bvr[4]=r1.x; bvr[5]=r1.y; bvr[6]=r1.z; bvr[7]=r1.w;
        float4 i0 = *(const float4*)(xi), i1 = *(const float4*)(xi + 4);
        bvi[0]=i0.x; bvi[1]=i0.y; bvi[2]=i0.z; bvi[3]=i0.w;
        bvi[4]=i1.x; bvi[5]=i1.y; bvi[6]=i1.z; bvi[7]=i1.w;
    }

    // serial inclusive scan within thread; keep per-element inclusive (A,b)
    float IAr[VPT], IAi[VPT], Ibr[VPT], Ibi[VPT];
    {
        float Aer, Aei;
        lambda_bar(lre, lim, dt[0] * stp, Aer, Aei);
        IAr[0] = Aer; IAi[0] = Aei; Ibr[0] = bvr[0]; Ibi[0] = bvi[0];
#pragma unroll
        for (int e = 1; e < VPT; e++) {
            lambda_bar(lre, lim, dt[e] * stp, Aer, Aei);
            IAr[e] = Aer*IAr[e-1] - Aei*IAi[e-1];
            IAi[e] = Aer*IAi[e-1] + Aei*IAr[e-1];
            Ibr[e] = Aer*Ibr[e-1] - Aei*Ibi[e-1] + bvr[e];
            Ibi[e] = Aer*Ibi[e-1] + Aei*Ibr[e-1] + bvi[e];
        }
    }

    // warp inclusive scan over thread aggregates
    float Ar = IAr[VPT-1], Ai = IAi[VPT-1], br = Ibr[VPT-1], bi = Ibi[VPT-1];
#pragma unroll
    for (int off = 1; off < 32; off <<= 1) {
        float pAr = __shfl_up_sync(0xFFFFFFFFu, Ar, off);
        float pAi = __shfl_up_sync(0xFFFFFFFFu, Ai, off);
        float pbr = __shfl_up_sync(0xFFFFFFFFu, br, off);
        float pbi = __shfl_up_sync(0xFFFFFFFFu, bi, off);
        if (lane >= off) combine_right(Ar, Ai, br, bi, pAr, pAi, pbr, pbi);
    }

    // warp-exclusive for this thread
    float EwAr = __shfl_up_sync(0xFFFFFFFFu, Ar, 1);
    float EwAi = __shfl_up_sync(0xFFFFFFFFu, Ai, 1);
    float Ewbr = __shfl_up_sync(0xFFFFFFFFu, br, 1);
    float Ewbi = __shfl_up_sync(0xFFFFFFFFu, bi, 1);
    if (lane == 0) { EwAr = 1.0f; EwAi = 0.0f; Ewbr = 0.0f; Ewbi = 0.0f; }

    // block: warp inclusive-lasts to smem
    __shared__ float sW[8][4];
    if (lane == 31) { sW[wid][0] = Ar; sW[wid][1] = Ai; sW[wid][2] = br; sW[wid][3] = bi; }
    __syncthreads();

    // block prefix for this warp (serial combine of earlier warps, ascending)
    float PAr = 1.0f, PAi = 0.0f, Pbr = 0.0f, Pbi = 0.0f;
#pragma unroll
    for (int w = 0; w < 7; w++) {
        if (w < wid) {
            float wAr = sW[w][0], wAi = sW[w][1], wbr = sW[w][2], wbi = sW[w][3];
            float nAr = wAr*PAr - wAi*PAi;
            float nAi = wAr*PAi + wAi*PAr;
            float nbr = wAr*Pbr - wAi*Pbi + wbr;
            float nbi = wAr*Pbi + wAi*Pbr + wbi;
            PAr = nAr; PAi = nAi; Pbr = nbr; Pbi = nbi;
        }
    }

    // E = Ew ∘ P  (P earlier)
    float EAr = EwAr*PAr - EwAi*PAi;
    float EAi = EwAr*PAi + EwAi*PAr;
    float Ebr = EwAr*Pbr - EwAi*Pbi + Ewbr;
    float Ebi = EwAr*Pbi + EwAi*Pbr + Ewbi;

    // x_prev = E.A * chunk_prefix + E.b
    size_t q = ((size_t)p * NCHUNK + chunk) * 2;
    float pcr = g_pre[q], pci = g_pre[q + 1];
    float xpr = EAr*pcr - EAi*pci + Ebr;
    float xpi = EAr*pci + EAi*pcr + Ebi;

    // apply: x[e] = IA[e] * x_prev + Ib[e]
    float o_r[VPT], o_i[VPT];
#pragma unroll
    for (int e = 0; e < VPT; e++) {
        o_r[e] = IAr[e]*xpr - IAi[e]*xpi + Ibr[e];
        o_i[e] = IAr[e]*xpi + IAi[e]*xpr + Ibi[e];
    }
    *(float4*)(xr)     = make_float4(o_r[0], o_r[1], o_r[2], o_r[3]);
    *(float4*)(xr + 4) = make_float4(o_r[4], o_r[5], o_r[6], o_r[7]);
    *(float4*)(xi)     = make_float4(o_i[0], o_i[1], o_i[2], o_i[3]);
    *(float4*)(xi + 4) = make_float4(o_i[4], o_i[5], o_i[6], o_i[7]);
}

// ======================== GEMM2 (tf32 mma): y = 2*(xre Cre^T - xim Cim^T) + D*u ========================
// (R5-proven single-buffer version, BN=512 so x streamed from DRAM once)
#define G2_BM 64
#define G2_BN 512
#define G2_BK 32
#define G2_AK8 (G2_BM * 8 + 8)    // 520
#define G2_BK8 (G2_BN * 8 + 8)    // 4104
#define G2_AR_OFF 0
#define G2_AI_OFF (4 * G2_AK8)
#define G2_BR_OFF (2 * 4 * G2_AK8)
#define G2_BI_OFF (G2_BR_OFF + 4 * G2_BK8)
#define G2_SMEM_FLOATS (G2_BI_OFF + 4 * G2_BK8)
#define G2_SMEM_BYTES (G2_SMEM_FLOATS * 4)

__global__ __launch_bounds__(512, 1) void gemm2(
    const float* __restrict__ Cre, const float* __restrict__ Cim,
    const float* __restrict__ u, const float* __restrict__ Dg,
    float* __restrict__ out)
{
    extern __shared__ uint32_t sm2[];
    const int tid = threadIdx.x;
    const int wid = tid >> 5, lane = tid & 31;
    const int g = lane >> 2, t = lane & 3;
    const int wm = wid >> 3, wn = wid & 7;
    const int bm = blockIdx.x * G2_BM;

    float acc[2][8][4];
#pragma unroll
    for (int i = 0; i < 2; i++)
#pragma unroll
        for (int j = 0; j < 8; j++)
#pragma unroll
            for (int r = 0; r < 4; r++) acc[i][j][r] = 0.0f;

    for (int kt = 0; kt < P_DIM; kt += G2_BK) {
        {
            int k = tid & 31;
            int l4 = (tid >> 5) * 4;
            int k8 = k >> 3, pos = kperm(k & 7);
            float4 vr = *(const float4*)(g_x_re + (size_t)(kt + k) * L_SEQ + bm + l4);
            float4 vi = *(const float4*)(g_x_im + (size_t)(kt + k) * L_SEQ + bm + l4);
            int br_ = G2_AR_OFF + k8 * G2_AK8 + l4 * 8 + pos;
            int bi_ = G2_AI_OFF + k8 * G2_AK8 + l4 * 8 + pos;
            sm2[br_ + 0]  = f2tf32(vr.x); sm2[br_ + 8]  = f2tf32(vr.y);
            sm2[br_ + 16] = f2tf32(vr.z); sm2[br_ + 24] = f2tf32(vr.w);
            sm2[bi_ + 0]  = f2tf32(-vi.x); sm2[bi_ + 8]  = f2tf32(-vi.y);
            sm2[bi_ + 16] = f2tf32(-vi.z); sm2[bi_ + 24] = f2tf32(-vi.w);
        }
#pragma unroll
        for (int j = 0; j < 8; j++) {
            int idx = tid + j * 512;
            int row = idx >> 3, k4 = idx & 7;
            int off = (k4 >> 1) * G2_BK8 + row * 8 + (k4 & 1);
            float4 vr = *(const float4*)(Cre + (size_t)row * P_DIM + kt + k4 * 4);
            sm2[G2_BR_OFF + off + 0] = f2tf32(vr.x); sm2[G2_BR_OFF + off + 2] = f2tf32(vr.y);
            sm2[G2_BR_OFF + off + 4] = f2tf32(vr.z); sm2[G2_BR_OFF + off + 6] = f2tf32(vr.w);
            float4 vi = *(const float4*)(Cim + (size_t)row * P_DIM + kt + k4 * 4);
            sm2[G2_BI_OFF + off + 0] = f2tf32(vi.x); sm2[G2_BI_OFF + off + 2] = f2tf32(vi.y);
            sm2[G2_BI_OFF + off + 4] = f2tf32(vi.z); sm2[G2_BI_OFF + off + 6] = f2tf32(vi.w);
        }
        __syncthreads();

#pragma unroll
        for (int k8 = 0; k8 < 4; k8++) {
            uint32_t ar[2][4], ai[2][4];
#pragma unroll
            for (int mt = 0; mt < 2; mt++) {
                int row = wm * 32 + mt * 16 + g;
                const uint32_t* pr = &sm2[G2_AR_OFF + k8 * G2_AK8 + row * 8 + 2 * t];
                uint2 lo = *(const uint2*)pr;
                uint2 hi = *(const uint2*)(pr + 64);
                ar[mt][0] = lo.x; ar[mt][2] = lo.y; ar[mt][1] = hi.x; ar[mt][3] = hi.y;
                const uint32_t* pi = &sm2[G2_AI_OFF + k8 * G2_AK8 + row * 8 + 2 * t];
                uint2 lo2 = *(const uint2*)pi;
                uint2 hi2 = *(const uint2*)(pi + 64);
                ai[mt][0] = lo2.x; ai[mt][2] = lo2.y; ai[mt][1] = hi2.x; ai[mt][3] = hi2.y;
            }
#pragma unroll
            for (int nt = 0; nt < 8; nt++) {
                int row = wn * 64 + nt * 8 + g;
                uint2 br = *(const uint2*)&sm2[G2_BR_OFF + k8 * G2_BK8 + row * 8 + 2 * t];
                uint2 bi = *(const uint2*)&sm2[G2_BI_OFF + k8 * G2_BK8 + row * 8 + 2 * t];
#pragma unroll
                for (int mt = 0; mt < 2; mt++) {
                    mma_tf32(acc[mt][nt], ar[mt], br.x, br.y);
                    mma_tf32(acc[mt][nt], ai[mt], bi.x, bi.y);
                }
            }
        }
        __syncthreads();
    }

#pragma unroll
    for (int mt = 0; mt < 2; mt++) {
#pragma unroll
        for (int rh = 0; rh < 2; rh++) {
            int l = bm + wm * 32 + mt * 16 + g + rh * 8;
#pragma unroll
            for (int nt = 0; nt < 8; nt++) {
                int h0 = wn * 64 + nt * 8 + 2 * t;
                float2 uu = *(const float2*)(u + (size_t)l * H_DIM + h0);
                float2 dd = *(const float2*)(Dg + h0);
                float2 o;
                o.x = 2.0f * acc[mt][nt][rh * 2 + 0] + dd.x * uu.x;
                o.y = 2.0f * acc[mt][nt][rh * 2 + 1] + dd.y * uu.y;
                *(float2*)(out + (size_t)l * H_DIM + h0) = o;
            }
        }
    }
}

// ======================== launch ========================
extern "C" void kernel_launch(void* const* d_in, const int* in_sizes, int n_in,
                              void* d_out, int out_size)
{
    const float* u   = (const float*)d_in[0];  // (L, H)
    const float* dtv = (const float*)d_in[1];  // (L,)
    const float* Lre = (const float*)d_in[2];  // (P,)
    const float* Lim = (const float*)d_in[3];  // (P,)
    const float* Bre = (const float*)d_in[4];  // (P, H)
    const float* Bim = (const float*)d_in[5];  // (P, H)
    const float* Cre = (const float*)d_in[6];  // (H, P)
    const float* Cim = (const float*)d_in[7];  // (H, P)
    const float* Dg  = (const float*)d_in[8];  // (H,)
    const float* lst = (const float*)d_in[9];  // (P,)
    float* out = (float*)d_out;                // (L, H)

    static int attr_done = 0;
    if (!attr_done) {
        cudaFuncSetAttribute(gemm1, cudaFuncAttributeMaxDynamicSharedMemorySize, G1_SMEM_BYTES);
        cudaFuncSetAttribute(gemm2, cudaFuncAttributeMaxDynamicSharedMemorySize, G2_SMEM_BYTES);
        attr_done = 1;
    }

    gemm1<<<dim3(P_DIM / G1_BN, L_SEQ / G1_BM), 512, G1_SMEM_BYTES>>>(u, Bre, Bim, dtv, Lre, Lim, lst);
    scan_agg<<<dim3(NCHUNK, P_DIM), SCAN_T>>>(dtv, Lre, Lim, lst);
    chunk_prefix<<<P_DIM, 32>>>();
    scan_apply<<<dim3(NCHUNK, P_DIM), SCAN_T>>>(dtv, Lre, Lim, lst);
    gemm2<<<L_SEQ / G2_BM, 512, G2_SMEM_BYTES>>>(Cre, Cim, u, Dg, out);
}

// round 8
// speedup vs baseline: 2.0289x; 1.5217x over previous
#include <cuda_runtime.h>
#include <math.h>
#include <stdint.h>

#define L_SEQ 32768
#define H_DIM 512
#define P_DIM 256
#define VPT 8
#define SCAN_T 256
#define CHUNK (SCAN_T * VPT)        // 2048
#define NCHUNK (L_SEQ / CHUNK)      // 16

// Scratch planes in [P][L] layout. Bu written by gemm1, overwritten in place
// with the scanned state x by scan_apply, consumed by gemm2.
__device__ float g_x_re[(size_t)P_DIM * L_SEQ];
__device__ float g_x_im[(size_t)P_DIM * L_SEQ];
__device__ float g_agg[P_DIM * NCHUNK * 4];
__device__ float g_pre[P_DIM * NCHUNK * 2];

// ---------------- common helpers ----------------

__device__ __forceinline__ void combine_right(float& Ar, float& Ai, float& br, float& bi,
                                              float pAr, float pAi, float pbr, float pbi)
{
    float nAr = Ar*pAr - Ai*pAi;
    float nAi = Ar*pAi + Ai*pAr;
    float nbr = Ar*pbr - Ai*pbi + br;
    float nbi = Ar*pbi + Ai*pbr + bi;
    Ar = nAr; Ai = nAi; br = nbr; bi = nbi;
}

__device__ __forceinline__ void combine_left(float& Ar, float& Ai, float& br, float& bi,
                                             float rAr, float rAi, float rbr, float rbi)
{
    float nAr = rAr*Ar - rAi*Ai;
    float nAi = rAr*Ai + rAi*Ar;
    float nbr = rAr*br - rAi*bi + rbr;
    float nbi = rAr*bi + rAi*br + rbi;
    Ar = nAr; Ai = nAi; br = nbr; bi = nbi;
}

__device__ __forceinline__ void lambda_bar(float lre, float lim, float Dl, float& Ar, float& Ai)
{
    float e = expf(lre * Dl);
    float s, c;
    sincosf(lim * Dl, &s, &c);
    Ar = e * c;
    Ai = e * s;
}

// pack two fp32 into bf16x2 word: lo = first (even k), hi = second (odd k)
__device__ __forceinline__ uint32_t packbf(float lo, float hi)
{
    uint32_t r;
    asm("cvt.rn.bf16x2.f32 %0, %1, %2;" : "=r"(r) : "f"(hi), "f"(lo));
    return r;
}

// bf16 m16n8k16: a = 4 regs (bf16x2), b = 2 regs, c/d = 4 fp32
__device__ __forceinline__ void mma_bf16(float* d, const uint32_t* a, uint32_t b0, uint32_t b1)
{
    asm volatile(
        "mma.sync.aligned.m16n8k16.row.col.f32.bf16.bf16.f32 "
        "{%0,%1,%2,%3}, {%4,%5,%6,%7}, {%8,%9}, {%0,%1,%2,%3};"
        : "+f"(d[0]), "+f"(d[1]), "+f"(d[2]), "+f"(d[3])
        : "r"(a[0]), "r"(a[1]), "r"(a[2]), "r"(a[3]), "r"(b0), "r"(b1));
}

// word-permutation within an 8-group: position(w) = w<4 ? 2w : 2(w-4)+1
// -> LDS.64 at position 2t yields (w_t, w_{t+4}) = (k 2t..2t+1, k 2t+8..2t+9)
__device__ __forceinline__ int kperm(int w) { return (w < 4) ? (2 * w) : (2 * (w - 4) + 1); }

// ======================== GEMM1 (bf16 mma): Bu = gamma_bar * (u @ B^T) ========================
// D[l,p] = sum_h u[l,h]*B[p,h]. BK=32 = 2 k16-groups. Word = bf16 pair (k, k+1).
#define G1_BM 128
#define G1_BN 128
#define G1_BK 32
#define G1_GW (G1_BM * 8 + 8)     // 1032 words per k16-group plane
#define G1_A_OFF 0
#define G1_BR_OFF (2 * G1_GW)
#define G1_BI_OFF (4 * G1_GW)
#define G1_SMEM_WORDS (6 * G1_GW) // 6192
#define G1_SMEM_BYTES (G1_SMEM_WORDS * 4)

__global__ __launch_bounds__(512, 1) void gemm1(
    const float* __restrict__ u, const float* __restrict__ Bre, const float* __restrict__ Bim,
    const float* __restrict__ dtv, const float* __restrict__ Lre_g, const float* __restrict__ Lim_g,
    const float* __restrict__ logstep)
{
    extern __shared__ uint32_t sm1[];
    const int tid = threadIdx.x;
    const int wid = tid >> 5, lane = tid & 31;
    const int g = lane >> 2, t = lane & 3;
    const int wm = wid >> 2, wn = wid & 3;     // 4x4 warps, warp tile 32l x 32p
    const int bm = blockIdx.y * G1_BM;
    const int bn = blockIdx.x * G1_BN;

    float accr[2][4][4];
    float acci[2][4][4];
#pragma unroll
    for (int i = 0; i < 2; i++)
#pragma unroll
        for (int j = 0; j < 4; j++)
#pragma unroll
            for (int r = 0; r < 4; r++) { accr[i][j][r] = 0.0f; acci[i][j][r] = 0.0f; }

    for (int kt = 0; kt < H_DIM; kt += G1_BK) {
        // fill A (u) and B planes: 128 rows x 8 float4-groups (each float4 -> 2 words)
#pragma unroll
        for (int r = 0; r < 2; r++) {
            int idx = tid + r * 512;
            int row = idx >> 3, c = idx & 7;
            int grp = c >> 2, w0 = (c & 3) * 2;
            int base = grp * G1_GW + row * 8;
            int p0 = kperm(w0), p1 = kperm(w0 + 1);
            float4 v = *(const float4*)(u + (size_t)(bm + row) * H_DIM + kt + c * 4);
            sm1[G1_A_OFF + base + p0] = packbf(v.x, v.y);
            sm1[G1_A_OFF + base + p1] = packbf(v.z, v.w);
            float4 vr = *(const float4*)(Bre + (size_t)(bn + row) * H_DIM + kt + c * 4);
            sm1[G1_BR_OFF + base + p0] = packbf(vr.x, vr.y);
            sm1[G1_BR_OFF + base + p1] = packbf(vr.z, vr.w);
            float4 vi = *(const float4*)(Bim + (size_t)(bn + row) * H_DIM + kt + c * 4);
            sm1[G1_BI_OFF + base + p0] = packbf(vi.x, vi.y);
            sm1[G1_BI_OFF + base + p1] = packbf(vi.z, vi.w);
        }
        __syncthreads();

#pragma unroll
        for (int k16 = 0; k16 < 2; k16++) {
            uint32_t a[2][4];
#pragma unroll
            for (int mt = 0; mt < 2; mt++) {
                int row = wm * 32 + mt * 16 + g;
                const uint32_t* p0 = &sm1[G1_A_OFF + k16 * G1_GW + row * 8 + 2 * t];
                uint2 lo = *(const uint2*)p0;
                uint2 hi = *(const uint2*)(p0 + 64);   // row + 8
                a[mt][0] = lo.x; a[mt][2] = lo.y;
                a[mt][1] = hi.x; a[mt][3] = hi.y;
            }
#pragma unroll
            for (int nt = 0; nt < 4; nt++) {
                int row = wn * 32 + nt * 8 + g;
                uint2 br = *(const uint2*)&sm1[G1_BR_OFF + k16 * G1_GW + row * 8 + 2 * t];
                uint2 bi = *(const uint2*)&sm1[G1_BI_OFF + k16 * G1_GW + row * 8 + 2 * t];
#pragma unroll
                for (int mt = 0; mt < 2; mt++) {
                    mma_bf16(accr[mt][nt], a[mt], br.x, br.y);
                    mma_bf16(acci[mt][nt], a[mt], bi.x, bi.y);
                }
            }
        }
        __syncthreads();
    }

    // epilogue: gamma_bar multiply, store to [P][L] planes (exact fp32)
    float dts[2][2];
#pragma unroll
    for (int mt = 0; mt < 2; mt++)
#pragma unroll
        for (int rh = 0; rh < 2; rh++)
            dts[mt][rh] = dtv[bm + wm * 32 + mt * 16 + g + rh * 8];

#pragma unroll
    for (int nt = 0; nt < 4; nt++) {
#pragma unroll
        for (int c = 0; c < 2; c++) {
            int p = bn + wn * 32 + nt * 8 + 2 * t + c;
            float lre = Lre_g[p], lim = Lim_g[p];
            float stp = expf(logstep[p]);
            float inv = 1.0f / (lre * lre + lim * lim);
#pragma unroll
            for (int mt = 0; mt < 2; mt++) {
#pragma unroll
                for (int rh = 0; rh < 2; rh++) {
                    int l = bm + wm * 32 + mt * 16 + g + rh * 8;
                    float Dl = dts[mt][rh] * stp;
                    float Ar, Ai;
                    lambda_bar(lre, lim, Dl, Ar, Ai);
                    float gr = ((Ar - 1.0f) * lre + Ai * lim) * inv;
                    float gi = (Ai * lre - (Ar - 1.0f) * lim) * inv;
                    int reg = rh * 2 + c;
                    float ar = accr[mt][nt][reg], ai = acci[mt][nt][reg];
                    size_t o = (size_t)p * L_SEQ + l;
                    g_x_re[o] = gr * ar - gi * ai;
                    g_x_im[o] = gr * ai + gi * ar;
                }
            }
        }
    }
}

// ======================== Scan phase A: serial-8 per thread, then reduce ========================
__global__ __launch_bounds__(SCAN_T) void scan_agg(
    const float* __restrict__ dtv, const float* __restrict__ Lre_g,
    const float* __restrict__ Lim_g, const float* __restrict__ logstep)
{
    const int p = blockIdx.y;
    const int chunk = blockIdx.x;
    const int tid = threadIdx.x;
    const int l0 = chunk * CHUNK + tid * VPT;

    const float lre = Lre_g[p], lim = Lim_g[p];
    const float stp = expf(logstep[p]);
    const float* xr = g_x_re + (size_t)p * L_SEQ + l0;
    const float* xi = g_x_im + (size_t)p * L_SEQ + l0;

    float dt[VPT], bvr[VPT], bvi[VPT];
    {
        float4 d0 = *(const float4*)(dtv + l0);
        float4 d1 = *(const float4*)(dtv + l0 + 4);
        dt[0]=d0.x; dt[1]=d0.y; dt[2]=d0.z; dt[3]=d0.w;
        dt[4]=d1.x; dt[5]=d1.y; dt[6]=d1.z; dt[7]=d1.w;
        float4 r0 = *(const float4*)(xr), r1 = *(const float4*)(xr + 4);
        bvr[0]=r0.x; bvr[1]=r0.y; bvr[2]=r0.z; bvr[3]=r0.w;
        bvr[4]=r1.x; bvr[5]=r1.y; bvr[6]=r1.z; bvr[7]=r1.w;
        float4 i0 = *(const float4*)(xi), i1 = *(const float4*)(xi + 4);
        bvi[0]=i0.x; bvi[1]=i0.y; bvi[2]=i0.z; bvi[3]=i0.w;
        bvi[4]=i1.x; bvi[5]=i1.y; bvi[6]=i1.z; bvi[7]=i1.w;
    }

    float Ar, Ai, br, bi;
    lambda_bar(lre, lim, dt[0] * stp, Ar, Ai);
    br = bvr[0]; bi = bvi[0];
#pragma unroll
    for (int e = 1; e < VPT; e++) {
        float Aer, Aei;
        lambda_bar(lre, lim, dt[e] * stp, Aer, Aei);
        float nAr = Aer*Ar - Aei*Ai;
        float nAi = Aer*Ai + Aei*Ar;
        float nbr = Aer*br - Aei*bi + bvr[e];
        float nbi = Aer*bi + Aei*br + bvi[e];
        Ar = nAr; Ai = nAi; br = nbr; bi = nbi;
    }

#pragma unroll
    for (int off = 1; off < 32; off <<= 1) {
        float rAr = __shfl_down_sync(0xFFFFFFFFu, Ar, off);
        float rAi = __shfl_down_sync(0xFFFFFFFFu, Ai, off);
        float rbr = __shfl_down_sync(0xFFFFFFFFu, br, off);
        float rbi = __shfl_down_sync(0xFFFFFFFFu, bi, off);
        combine_left(Ar, Ai, br, bi, rAr, rAi, rbr, rbi);
    }

    __shared__ float sA_r[8], sA_i[8], sb_r[8], sb_i[8];
    int lane = tid & 31, wid = tid >> 5;
    if (lane == 0) { sA_r[wid] = Ar; sA_i[wid] = Ai; sb_r[wid] = br; sb_i[wid] = bi; }
    __syncthreads();

    if (wid == 0) {
        float aAr = (lane < 8) ? sA_r[lane] : 1.0f;
        float aAi = (lane < 8) ? sA_i[lane] : 0.0f;
        float abr = (lane < 8) ? sb_r[lane] : 0.0f;
        float abi = (lane < 8) ? sb_i[lane] : 0.0f;
#pragma unroll
        for (int off = 1; off < 8; off <<= 1) {
            float rAr = __shfl_down_sync(0xFFFFFFFFu, aAr, off);
            float rAi = __shfl_down_sync(0xFFFFFFFFu, aAi, off);
            float rbr = __shfl_down_sync(0xFFFFFFFFu, abr, off);
            float rbi = __shfl_down_sync(0xFFFFFFFFu, abi, off);
            combine_left(aAr, aAi, abr, abi, rAr, rAi, rbr, rbi);
        }
        if (lane == 0) {
            size_t o = ((size_t)p * NCHUNK + chunk) * 4;
            g_agg[o + 0] = aAr; g_agg[o + 1] = aAi;
            g_agg[o + 2] = abr; g_agg[o + 3] = abi;
        }
    }
}

// ======================== Scan phase B: per-p exclusive scan over 16 chunk aggregates ===========
__global__ __launch_bounds__(32) void chunk_prefix()
{
    const int p = blockIdx.x;
    const int lane = threadIdx.x;

    float Ar = 1.0f, Ai = 0.0f, br = 0.0f, bi = 0.0f;
    if (lane < NCHUNK) {
        size_t o = ((size_t)p * NCHUNK + lane) * 4;
        Ar = g_agg[o + 0]; Ai = g_agg[o + 1];
        br = g_agg[o + 2]; bi = g_agg[o + 3];
    }

#pragma unroll
    for (int off = 1; off < NCHUNK; off <<= 1) {
        float pAr = __shfl_up_sync(0xFFFFFFFFu, Ar, off);
        float pAi = __shfl_up_sync(0xFFFFFFFFu, Ai, off);
        float pbr = __shfl_up_sync(0xFFFFFFFFu, br, off);
        float pbi = __shfl_up_sync(0xFFFFFFFFu, bi, off);
        if (lane >= off) combine_right(Ar, Ai, br, bi, pAr, pAi, pbr, pbi);
    }

    float er = __shfl_up_sync(0xFFFFFFFFu, br, 1);
    float ei = __shfl_up_sync(0xFFFFFFFFu, bi, 1);
    if (lane == 0) { er = 0.0f; ei = 0.0f; }
    if (lane < NCHUNK) {
        size_t q = ((size_t)p * NCHUNK + lane) * 2;
        g_pre[q] = er; g_pre[q + 1] = ei;
    }
}

// ======================== Scan phase C: serial-8 inclusive + prefix apply ========================
__global__ __launch_bounds__(SCAN_T) void scan_apply(
    const float* __restrict__ dtv, const float* __restrict__ Lre_g,
    const float* __restrict__ Lim_g, const float* __restrict__ logstep)
{
    const int p = blockIdx.y;
    const int chunk = blockIdx.x;
    const int tid = threadIdx.x;
    const int l0 = chunk * CHUNK + tid * VPT;
    const int lane = tid & 31, wid = tid >> 5;

    const float lre = Lre_g[p], lim = Lim_g[p];
    const float stp = expf(logstep[p]);
    float* xr = g_x_re + (size_t)p * L_SEQ + l0;
    float* xi = g_x_im + (size_t)p * L_SEQ + l0;

    float dt[VPT], bvr[VPT], bvi[VPT];
    {
        float4 d0 = *(const float4*)(dtv + l0);
        float4 d1 = *(const float4*)(dtv + l0 + 4);
        dt[0]=d0.x; dt[1]=d0.y; dt[2]=d0.z; dt[3]=d0.w;
        dt[4]=d1.x; dt[5]=d1.y; dt[6]=d1.z; dt[7]=d1.w;
        float4 r0 = *(const float4*)(xr), r1 = *(const float4*)(xr + 4);
        bvr[0]=r0.x; bvr[1]=r0.y; bvr[2]=r0.z; bvr[3]=r0.w;
        bvr[4]=r1.x; bvr[5]=r1.y; bvr[6]=r1.z; bvr[7]=r1.w;
        float4 i0 = *(const float4*)(xi), i1 = *(const float4*)(xi + 4);
        bvi[0]=i0.x; bvi[1]=i0.y; bvi[2]=i0.z; bvi[3]=i0.w;
        bvi[4]=i1.x; bvi[5]=i1.y; bvi[6]=i1.z; bvi[7]=i1.w;
    }

    float IAr[VPT], IAi[VPT], Ibr[VPT], Ibi[VPT];
    {
        float Aer, Aei;
        lambda_bar(lre, lim, dt[0] * stp, Aer, Aei);
        IAr[0] = Aer; IAi[0] = Aei; Ibr[0] = bvr[0]; Ibi[0] = bvi[0];
#pragma unroll
        for (int e = 1; e < VPT; e++) {
            lambda_bar(lre, lim, dt[e] * stp, Aer, Aei);
            IAr[e] = Aer*IAr[e-1] - Aei*IAi[e-1];
            IAi[e] = Aer*IAi[e-1] + Aei*IAr[e-1];
            Ibr[e] = Aer*Ibr[e-1] - Aei*Ibi[e-1] + bvr[e];
            Ibi[e] = Aer*Ibi[e-1] + Aei*Ibr[e-1] + bvi[e];
        }
    }

    float Ar = IAr[VPT-1], Ai = IAi[VPT-1], br = Ibr[VPT-1], bi = Ibi[VPT-1];
#pragma unroll
    for (int off = 1; off < 32; off <<= 1) {
        float pAr = __shfl_up_sync(0xFFFFFFFFu, Ar, off);
        float pAi = __shfl_up_sync(0xFFFFFFFFu, Ai, off);
        float pbr = __shfl_up_sync(0xFFFFFFFFu, br, off);
        float pbi = __shfl_up_sync(0xFFFFFFFFu, bi, off);
        if (lane >= off) combine_right(Ar, Ai, br, bi, pAr, pAi, pbr, pbi);
    }

    float EwAr = __shfl_up_sync(0xFFFFFFFFu, Ar, 1);
    float EwAi = __shfl_up_sync(0xFFFFFFFFu, Ai, 1);
    float Ewbr = __shfl_up_sync(0xFFFFFFFFu, br, 1);
    float Ewbi = __shfl_up_sync(0xFFFFFFFFu, bi, 1);
    if (lane == 0) { EwAr = 1.0f; EwAi = 0.0f; Ewbr = 0.0f; Ewbi = 0.0f; }

    __shared__ float sW[8][4];
    if (lane == 31) { sW[wid][0] = Ar; sW[wid][1] = Ai; sW[wid][2] = br; sW[wid][3] = bi; }
    __syncthreads();

    float PAr = 1.0f, PAi = 0.0f, Pbr = 0.0f, Pbi = 0.0f;
#pragma unroll
    for (int w = 0; w < 7; w++) {
        if (w < wid) {
            float wAr = sW[w][0], wAi = sW[w][1], wbr = sW[w][2], wbi = sW[w][3];
            float nAr = wAr*PAr - wAi*PAi;
            float nAi = wAr*PAi + wAi*PAr;
            float nbr = wAr*Pbr - wAi*Pbi + wbr;
            float nbi = wAr*Pbi + wAi*Pbr + wbi;
            PAr = nAr; PAi = nAi; Pbr = nbr; Pbi = nbi;
        }
    }

    float EAr = EwAr*PAr - EwAi*PAi;
    float EAi = EwAr*PAi + EwAi*PAr;
    float Ebr = EwAr*Pbr - EwAi*Pbi + Ewbr;
    float Ebi = EwAr*Pbi + EwAi*Pbr + Ewbi;

    size_t q = ((size_t)p * NCHUNK + chunk) * 2;
    float pcr = g_pre[q], pci = g_pre[q + 1];
    float xpr = EAr*pcr - EAi*pci + Ebr;
    float xpi = EAr*pci + EAi*pcr + Ebi;

    float o_r[VPT], o_i[VPT];
#pragma unroll
    for (int e = 0; e < VPT; e++) {
        o_r[e] = IAr[e]*xpr - IAi[e]*xpi + Ibr[e];
        o_i[e] = IAr[e]*xpi + IAi[e]*xpr + Ibi[e];
    }
    *(float4*)(xr)     = make_float4(o_r[0], o_r[1], o_r[2], o_r[3]);
    *(float4*)(xr + 4) = make_float4(o_r[4], o_r[5], o_r[6], o_r[7]);
    *(float4*)(xi)     = make_float4(o_i[0], o_i[1], o_i[2], o_i[3]);
    *(float4*)(xi + 4) = make_float4(o_i[4], o_i[5], o_i[6], o_i[7]);
}

// ======================== GEMM2 (bf16 mma): y = 2*(xre Cre^T - xim Cim^T) + D*u ========================
// A = x planes [P][L] (word packs k,k+1 across adjacent p-planes); B = C (H,P) k-contiguous.
// BN=512 so x is streamed from DRAM exactly once.
#define G2_BM 64
#define G2_BN 512
#define G2_BK 32
#define G2_AGW (G2_BM * 8 + 8)    // 520 words per k16-group plane (A)
#define G2_BGW (G2_BN * 8 + 8)    // 4104 words per k16-group plane (B)
#define G2_AR_OFF 0
#define G2_AI_OFF (2 * G2_AGW)                  // 1040
#define G2_BR_OFF (4 * G2_AGW)                  // 2080
#define G2_BI_OFF (G2_BR_OFF + 2 * G2_BGW)      // 10288
#define G2_SMEM_WORDS (G2_BI_OFF + 2 * G2_BGW)  // 18496
#define G2_SMEM_BYTES (G2_SMEM_WORDS * 4)       // 73984

__global__ __launch_bounds__(512, 1) void gemm2(
    const float* __restrict__ Cre, const float* __restrict__ Cim,
    const float* __restrict__ u, const float* __restrict__ Dg,
    float* __restrict__ out)
{
    extern __shared__ uint32_t sm2[];
    const int tid = threadIdx.x;
    const int wid = tid >> 5, lane = tid & 31;
    const int g = lane >> 2, t = lane & 3;
    const int wm = wid >> 3, wn = wid & 7;        // 2x8 warps, warp tile 32l x 64h
    const int bm = blockIdx.x * G2_BM;

    // A fill constants: tt in 0..255 -> j = k-pair 0..15, l4 group 0..15. sel: re/im.
    const int tt = tid & 255;
    const int aj = tt >> 4;                 // word index (k pair) 0..15
    const int al4 = (tt & 15) * 4;          // l offset 0..60
    const int asel = tid >> 8;              // 0: re, 1: im
    const int agrp = aj >> 3, apos = kperm(aj & 7);
    const int abase = (asel ? G2_AI_OFF : G2_AR_OFF) + agrp * G2_AGW + al4 * 8 + apos;
    const float* aplane0 = (asel ? g_x_im : g_x_re);

    float acc[2][8][4];
#pragma unroll
    for (int i = 0; i < 2; i++)
#pragma unroll
        for (int j = 0; j < 8; j++)
#pragma unroll
            for (int r = 0; r < 4; r++) acc[i][j][r] = 0.0f;

    for (int kt = 0; kt < P_DIM; kt += G2_BK) {
        // fill A: word packs (k=kt+2j, k+1) for 4 l's; im negated
        {
            const float* pe = aplane0 + (size_t)(kt + 2 * aj) * L_SEQ + bm + al4;
            const float* po = aplane0 + (size_t)(kt + 2 * aj + 1) * L_SEQ + bm + al4;
            float4 fe = *(const float4*)pe;
            float4 fo = *(const float4*)po;
            float sgn = asel ? -1.0f : 1.0f;
            sm2[abase + 0]  = packbf(sgn * fe.x, sgn * fo.x);
            sm2[abase + 8]  = packbf(sgn * fe.y, sgn * fo.y);
            sm2[abase + 16] = packbf(sgn * fe.z, sgn * fo.z);
            sm2[abase + 24] = packbf(sgn * fe.w, sgn * fo.w);
        }
        // fill B (C planes): 512 rows h x 8 float4-groups
#pragma unroll
        for (int j = 0; j < 8; j++) {
            int idx = tid + j * 512;
            int row = idx >> 3, c = idx & 7;
            int grp = c >> 2, w0 = (c & 3) * 2;
            int base = grp * G2_BGW + row * 8;
            int p0 = kperm(w0), p1 = kperm(w0 + 1);
            float4 vr = *(const float4*)(Cre + (size_t)row * P_DIM + kt + c * 4);
            sm2[G2_BR_OFF + base + p0] = packbf(vr.x, vr.y);
            sm2[G2_BR_OFF + base + p1] = packbf(vr.z, vr.w);
            float4 vi = *(const float4*)(Cim + (size_t)row * P_DIM + kt + c * 4);
            sm2[G2_BI_OFF + base + p0] = packbf(vi.x, vi.y);
            sm2[G2_BI_OFF + base + p1] = packbf(vi.z, vi.w);
        }
        __syncthreads();

#pragma unroll
        for (int k16 = 0; k16 < 2; k16++) {
            uint32_t ar[2][4], ai[2][4];
#pragma unroll
            for (int mt = 0; mt < 2; mt++) {
                int row = wm * 32 + mt * 16 + g;
                const uint32_t* pr = &sm2[G2_AR_OFF + k16 * G2_AGW + row * 8 + 2 * t];
                uint2 lo = *(const uint2*)pr;
                uint2 hi = *(const uint2*)(pr + 64);
                ar[mt][0] = lo.x; ar[mt][2] = lo.y; ar[mt][1] = hi.x; ar[mt][3] = hi.y;
                const uint32_t* pi = &sm2[G2_AI_OFF + k16 * G2_AGW + row * 8 + 2 * t];
                uint2 lo2 = *(const uint2*)pi;
                uint2 hi2 = *(const uint2*)(pi + 64);
                ai[mt][0] = lo2.x; ai[mt][2] = lo2.y; ai[mt][1] = hi2.x; ai[mt][3] = hi2.y;
            }
#pragma unroll
            for (int nt = 0; nt < 8; nt++) {
                int row = wn * 64 + nt * 8 + g;
                uint2 br = *(const uint2*)&sm2[G2_BR_OFF + k16 * G2_BGW + row * 8 + 2 * t];
                uint2 bi = *(const uint2*)&sm2[G2_BI_OFF + k16 * G2_BGW + row * 8 + 2 * t];
#pragma unroll
                for (int mt = 0; mt < 2; mt++) {
                    mma_bf16(acc[mt][nt], ar[mt], br.x, br.y);
                    mma_bf16(acc[mt][nt], ai[mt], bi.x, bi.y);
                }
            }
        }
        __syncthreads();
    }

    // epilogue: y = 2*acc + D*u
#pragma unroll
    for (int mt = 0; mt < 2; mt++) {
#pragma unroll
        for (int rh = 0; rh < 2; rh++) {
            int l = bm + wm * 32 + mt * 16 + g + rh * 8;
#pragma unroll
            for (int nt = 0; nt < 8; nt++) {
                int h0 = wn * 64 + nt * 8 + 2 * t;
                float2 uu = *(const float2*)(u + (size_t)l * H_DIM + h0);
                float2 dd = *(const float2*)(Dg + h0);
                float2 o;
                o.x = 2.0f * acc[mt][nt][rh * 2 + 0] + dd.x * uu.x;
                o.y = 2.0f * acc[mt][nt][rh * 2 + 1] + dd.y * uu.y;
                *(float2*)(out + (size_t)l * H_DIM + h0) = o;
            }
        }
    }
}

// ======================== launch ========================
extern "C" void kernel_launch(void* const* d_in, const int* in_sizes, int n_in,
                              void* d_out, int out_size)
{
    const float* u   = (const float*)d_in[0];  // (L, H)
    const float* dtv = (const float*)d_in[1];  // (L,)
    const float* Lre = (const float*)d_in[2];  // (P,)
    const float* Lim = (const float*)d_in[3];  // (P,)
    const float* Bre = (const float*)d_in[4];  // (P, H)
    const float* Bim = (const float*)d_in[5];  // (P, H)
    const float* Cre = (const float*)d_in[6];  // (H, P)
    const float* Cim = (const float*)d_in[7];  // (H, P)
    const float* Dg  = (const float*)d_in[8];  // (H,)
    const float* lst = (const float*)d_in[9];  // (P,)
    float* out = (float*)d_out;                // (L, H)

    static int attr_done = 0;
    if (!attr_done) {
        cudaFuncSetAttribute(gemm1, cudaFuncAttributeMaxDynamicSharedMemorySize, G1_SMEM_BYTES);
        cudaFuncSetAttribute(gemm2, cudaFuncAttributeMaxDynamicSharedMemorySize, G2_SMEM_BYTES);
        attr_done = 1;
    }

    gemm1<<<dim3(P_DIM / G1_BN, L_SEQ / G1_BM), 512, G1_SMEM_BYTES>>>(u, Bre, Bim, dtv, Lre, Lim, lst);
    scan_agg<<<dim3(NCHUNK, P_DIM), SCAN_T>>>(dtv, Lre, Lim, lst);
    chunk_prefix<<<P_DIM, 32>>>();
    scan_apply<<<dim3(NCHUNK, P_DIM), SCAN_T>>>(dtv, Lre, Lim, lst);
    gemm2<<<L_SEQ / G2_BM, 512, G2_SMEM_BYTES>>>(Cre, Cim, u, Dg, out);
}

// round 11
// speedup vs baseline: 2.0628x; 1.0167x over previous
#include <cuda_runtime.h>
#include <math.h>
#include <stdint.h>

#define L_SEQ 32768
#define H_DIM 512
#define P_DIM 256
#define VPT 8
#define SCAN_T 256
#define CHUNK (SCAN_T * VPT)        // 2048
#define NCHUNK (L_SEQ / CHUNK)      // 16

// fp32 scratch planes [P][L]: Bu written by gemm1, read by scan.
__device__ float g_x_re[(size_t)P_DIM * L_SEQ];
__device__ float g_x_im[(size_t)P_DIM * L_SEQ];
__device__ float g_agg[P_DIM * NCHUNK * 4];
__device__ float g_pre[P_DIM * NCHUNK * 2];

// bf16 pre-converted operands
__device__ uint16_t g_ubf[(size_t)L_SEQ * H_DIM];     // u as bf16
__device__ uint16_t g_Brbf[P_DIM * H_DIM];
__device__ uint16_t g_Bibf[P_DIM * H_DIM];
__device__ uint16_t g_Crbf[H_DIM * P_DIM];
__device__ uint16_t g_Cibf[H_DIM * P_DIM];
// bf16 scanned state planes [P][L] (written by scan_apply, read by gemm2)
__device__ uint16_t g_xrbf[(size_t)P_DIM * L_SEQ];
__device__ uint16_t g_xibf[(size_t)P_DIM * L_SEQ];

// ---------------- common helpers ----------------

__device__ __forceinline__ void combine_right(float& Ar, float& Ai, float& br, float& bi,
                                              float pAr, float pAi, float pbr, float pbi)
{
    float nAr = Ar*pAr - Ai*pAi;
    float nAi = Ar*pAi + Ai*pAr;
    float nbr = Ar*pbr - Ai*pbi + br;
    float nbi = Ar*pbi + Ai*pbr + bi;
    Ar = nAr; Ai = nAi; br = nbr; bi = nbi;
}

__device__ __forceinline__ void combine_left(float& Ar, float& Ai, float& br, float& bi,
                                             float rAr, float rAi, float rbr, float rbi)
{
    float nAr = rAr*Ar - rAi*Ai;
    float nAi = rAr*Ai + rAi*Ar;
    float nbr = rAr*br - rAi*bi + rbr;
    float nbi = rAr*bi + rAi*br + rbi;
    Ar = nAr; Ai = nAi; br = nbr; bi = nbi;
}

__device__ __forceinline__ void lambda_bar(float lre, float lim, float Dl, float& Ar, float& Ai)
{
    float e = expf(lre * Dl);
    float s, c;
    sincosf(lim * Dl, &s, &c);
    Ar = e * c;
    Ai = e * s;
}

// pack two fp32 into bf16x2 word: lo = first, hi = second
__device__ __forceinline__ uint32_t packbf(float lo, float hi)
{
    uint32_t r;
    asm("cvt.rn.bf16x2.f32 %0, %1, %2;" : "=r"(r) : "f"(hi), "f"(lo));
    return r;
}

__device__ __forceinline__ void mma_bf16(float* d, const uint32_t* a, uint32_t b0, uint32_t b1)
{
    asm volatile(
        "mma.sync.aligned.m16n8k16.row.col.f32.bf16.bf16.f32 "
        "{%0,%1,%2,%3}, {%4,%5,%6,%7}, {%8,%9}, {%0,%1,%2,%3};"
        : "+f"(d[0]), "+f"(d[1]), "+f"(d[2]), "+f"(d[3])
        : "r"(a[0]), "r"(a[1]), "r"(a[2]), "r"(a[3]), "r"(b0), "r"(b1));
}

// word-permutation within an 8-group: position(w) = w<4 ? 2w : 2(w-4)+1
__device__ __forceinline__ int kperm(int w) { return (w < 4) ? (2 * w) : (2 * (w - 4) + 1); }

// ======================== converters ========================
__global__ __launch_bounds__(256) void convert_u(const float* __restrict__ u)
{
    size_t i = ((size_t)blockIdx.x * 256 + threadIdx.x) * 4;
    float4 v = *(const float4*)(u + i);
    *(uint2*)(g_ubf + i) = make_uint2(packbf(v.x, v.y), packbf(v.z, v.w));
}

__global__ __launch_bounds__(256) void convert_mats(
    const float* __restrict__ Bre, const float* __restrict__ Bim,
    const float* __restrict__ Cre, const float* __restrict__ Cim)
{
    int i = (blockIdx.x * 256 + threadIdx.x) * 4;
    const float* s;
    uint16_t* d;
    if (blockIdx.y == 0)      { s = Bre; d = g_Brbf; }
    else if (blockIdx.y == 1) { s = Bim; d = g_Bibf; }
    else if (blockIdx.y == 2) { s = Cre; d = g_Crbf; }
    else                      { s = Cim; d = g_Cibf; }
    float4 v = *(const float4*)(s + i);
    *(uint2*)(d + i) = make_uint2(packbf(v.x, v.y), packbf(v.z, v.w));
}

// ======================== GEMM1 (bf16 mma): Bu = gamma_bar * (u @ B^T) ========================
#define G1_BM 128
#define G1_BN 128
#define G1_BK 32
#define G1_GW (G1_BM * 8 + 8)     // 1032 words per k16-group plane
#define G1_A_OFF 0
#define G1_BR_OFF (2 * G1_GW)
#define G1_BI_OFF (4 * G1_GW)
#define G1_SMEM_WORDS (6 * G1_GW)
#define G1_SMEM_BYTES (G1_SMEM_WORDS * 4)

__global__ __launch_bounds__(512, 1) void gemm1(
    const float* __restrict__ dtv, const float* __restrict__ Lre_g, const float* __restrict__ Lim_g,
    const float* __restrict__ logstep)
{
    extern __shared__ uint32_t sm1[];
    const int tid = threadIdx.x;
    const int wid = tid >> 5, lane = tid & 31;
    const int g = lane >> 2, t = lane & 3;
    const int wm = wid >> 2, wn = wid & 3;     // 4x4 warps, warp tile 32l x 32p
    const int bm = blockIdx.y * G1_BM;
    const int bn = blockIdx.x * G1_BN;

    float accr[2][4][4];
    float acci[2][4][4];
#pragma unroll
    for (int i = 0; i < 2; i++)
#pragma unroll
        for (int j = 0; j < 4; j++)
#pragma unroll
            for (int r = 0; r < 4; r++) { accr[i][j][r] = 0.0f; acci[i][j][r] = 0.0f; }

    for (int kt = 0; kt < H_DIM; kt += G1_BK) {
        // fill: bf16 words direct from pre-converted globals (no cvt)
#pragma unroll
        for (int r = 0; r < 2; r++) {
            int idx = tid + r * 512;
            int row = idx >> 3, c = idx & 7;
            int grp = c >> 2, w0 = (c & 3) * 2;
            int base = grp * G1_GW + row * 8;
            int p0 = kperm(w0), p1 = kperm(w0 + 1);
            uint2 a = *(const uint2*)(g_ubf + (size_t)(bm + row) * H_DIM + kt + c * 4);
            sm1[G1_A_OFF + base + p0] = a.x;
            sm1[G1_A_OFF + base + p1] = a.y;
            uint2 br = *(const uint2*)(g_Brbf + (size_t)(bn + row) * H_DIM + kt + c * 4);
            sm1[G1_BR_OFF + base + p0] = br.x;
            sm1[G1_BR_OFF + base + p1] = br.y;
            uint2 bi = *(const uint2*)(g_Bibf + (size_t)(bn + row) * H_DIM + kt + c * 4);
            sm1[G1_BI_OFF + base + p0] = bi.x;
            sm1[G1_BI_OFF + base + p1] = bi.y;
        }
        __syncthreads();

#pragma unroll
        for (int k16 = 0; k16 < 2; k16++) {
            uint32_t a[2][4];
#pragma unroll
            for (int mt = 0; mt < 2; mt++) {
                int row = wm * 32 + mt * 16 + g;
                const uint32_t* p0 = &sm1[G1_A_OFF + k16 * G1_GW + row * 8 + 2 * t];
                uint2 lo = *(const uint2*)p0;
                uint2 hi = *(const uint2*)(p0 + 64);   // row + 8
                a[mt][0] = lo.x; a[mt][2] = lo.y;
                a[mt][1] = hi.x; a[mt][3] = hi.y;
            }
#pragma unroll
            for (int nt = 0; nt < 4; nt++) {
                int row = wn * 32 + nt * 8 + g;
                uint2 br = *(const uint2*)&sm1[G1_BR_OFF + k16 * G1_GW + row * 8 + 2 * t];
                uint2 bi = *(const uint2*)&sm1[G1_BI_OFF + k16 * G1_GW + row * 8 + 2 * t];
#pragma unroll
                for (int mt = 0; mt < 2; mt++) {
                    mma_bf16(accr[mt][nt], a[mt], br.x, br.y);
                    mma_bf16(acci[mt][nt], a[mt], bi.x, bi.y);
                }
            }
        }
        __syncthreads();
    }

    // epilogue: gamma_bar multiply, store fp32 Bu to [P][L] planes
    float dts[2][2];
#pragma unroll
    for (int mt = 0; mt < 2; mt++)
#pragma unroll
        for (int rh = 0; rh < 2; rh++)
            dts[mt][rh] = dtv[bm + wm * 32 + mt * 16 + g + rh * 8];

#pragma unroll
    for (int nt = 0; nt < 4; nt++) {
#pragma unroll
        for (int c = 0; c < 2; c++) {
            int p = bn + wn * 32 + nt * 8 + 2 * t + c;
            float lre = Lre_g[p], lim = Lim_g[p];
            float stp = expf(logstep[p]);
            float inv = 1.0f / (lre * lre + lim * lim);
#pragma unroll
            for (int mt = 0; mt < 2; mt++) {
#pragma unroll
                for (int rh = 0; rh < 2; rh++) {
                    int l = bm + wm * 32 + mt * 16 + g + rh * 8;
                    float Dl = dts[mt][rh] * stp;
                    float Ar, Ai;
                    lambda_bar(lre, lim, Dl, Ar, Ai);
                    float gr = ((Ar - 1.0f) * lre + Ai * lim) * inv;
                    float gi = (Ai * lre - (Ar - 1.0f) * lim) * inv;
                    int reg = rh * 2 + c;
                    float ar = accr[mt][nt][reg], ai = acci[mt][nt][reg];
                    size_t o = (size_t)p * L_SEQ + l;
                    g_x_re[o] = gr * ar - gi * ai;
                    g_x_im[o] = gr * ai + gi * ar;
                }
            }
        }
    }
}

// ======================== Scan phase A: serial-8 per thread, then reduce ========================
__global__ __launch_bounds__(SCAN_T) void scan_agg(
    const float* __restrict__ dtv, const float* __restrict__ Lre_g,
    const float* __restrict__ Lim_g, const float* __restrict__ logstep)
{
    const int p = blockIdx.y;
    const int chunk = blockIdx.x;
    const int tid = threadIdx.x;
    const int l0 = chunk * CHUNK + tid * VPT;

    const float lre = Lre_g[p], lim = Lim_g[p];
    const float stp = expf(logstep[p]);
    const float* xr = g_x_re + (size_t)p * L_SEQ + l0;
    const float* xi = g_x_im + (size_t)p * L_SEQ + l0;

    float dt[VPT], bvr[VPT], bvi[VPT];
    {
        float4 d0 = *(const float4*)(dtv + l0);
        float4 d1 = *(const float4*)(dtv + l0 + 4);
        dt[0]=d0.x; dt[1]=d0.y; dt[2]=d0.z; dt[3]=d0.w;
        dt[4]=d1.x; dt[5]=d1.y; dt[6]=d1.z; dt[7]=d1.w;
        float4 r0 = *(const float4*)(xr), r1 = *(const float4*)(xr + 4);
        bvr[0]=r0.x; bvr[1]=r0.y; bvr[2]=r0.z; bvr[3]=r0.w;
        bvr[4]=r1.x; bvr[5]=r1.y; bvr[6]=r1.z; bvr[7]=r1.w;
        float4 i0 = *(const float4*)(xi), i1 = *(const float4*)(xi + 4);
        bvi[0]=i0.x; bvi[1]=i0.y; bvi[2]=i0.z; bvi[3]=i0.w;
        bvi[4]=i1.x; bvi[5]=i1.y; bvi[6]=i1.z; bvi[7]=i1.w;
    }

    float Ar, Ai, br, bi;
    lambda_bar(lre, lim, dt[0] * stp, Ar, Ai);
    br = bvr[0]; bi = bvi[0];
#pragma unroll
    for (int e = 1; e < VPT; e++) {
        float Aer, Aei;
        lambda_bar(lre, lim, dt[e] * stp, Aer, Aei);
        float nAr = Aer*Ar - Aei*Ai;
        float nAi = Aer*Ai + Aei*Ar;
        float nbr = Aer*br - Aei*bi + bvr[e];
        float nbi = Aer*bi + Aei*br + bvi[e];
        Ar = nAr; Ai = nAi; br = nbr; bi = nbi;
    }

#pragma unroll
    for (int off = 1; off < 32; off <<= 1) {
        float rAr = __shfl_down_sync(0xFFFFFFFFu, Ar, off);
        float rAi = __shfl_down_sync(0xFFFFFFFFu, Ai, off);
        float rbr = __shfl_down_sync(0xFFFFFFFFu, br, off);
        float rbi = __shfl_down_sync(0xFFFFFFFFu, bi, off);
        combine_left(Ar, Ai, br, bi, rAr, rAi, rbr, rbi);
    }

    __shared__ float sA_r[8], sA_i[8], sb_r[8], sb_i[8];
    int lane = tid & 31, wid = tid >> 5;
    if (lane == 0) { sA_r[wid] = Ar; sA_i[wid] = Ai; sb_r[wid] = br; sb_i[wid] = bi; }
    __syncthreads();

    if (wid == 0) {
        float aAr = (lane < 8) ? sA_r[lane] : 1.0f;
        float aAi = (lane < 8) ? sA_i[lane] : 0.0f;
        float abr = (lane < 8) ? sb_r[lane] : 0.0f;
        float abi = (lane < 8) ? sb_i[lane] : 0.0f;
#pragma unroll
        for (int off = 1; off < 8; off <<= 1) {
            float rAr = __shfl_down_sync(0xFFFFFFFFu, aAr, off);
            float rAi = __shfl_down_sync(0xFFFFFFFFu, aAi, off);
            float rbr = __shfl_down_sync(0xFFFFFFFFu, abr, off);
            float rbi = __shfl_down_sync(0xFFFFFFFFu, abi, off);
            combine_left(aAr, aAi, abr, abi, rAr, rAi, rbr, rbi);
        }
        if (lane == 0) {
            size_t o = ((size_t)p * NCHUNK + chunk) * 4;
            g_agg[o + 0] = aAr; g_agg[o + 1] = aAi;
            g_agg[o + 2] = abr; g_agg[o + 3] = abi;
        }
    }
}

// ======================== Scan phase B ========================
__global__ __launch_bounds__(32) void chunk_prefix()
{
    const int p = blockIdx.x;
    const int lane = threadIdx.x;

    float Ar = 1.0f, Ai = 0.0f, br = 0.0f, bi = 0.0f;
    if (lane < NCHUNK) {
        size_t o = ((size_t)p * NCHUNK + lane) * 4;
        Ar = g_agg[o + 0]; Ai = g_agg[o + 1];
        br = g_agg[o + 2]; bi = g_agg[o + 3];
    }

#pragma unroll
    for (int off = 1; off < NCHUNK; off <<= 1) {
        float pAr = __shfl_up_sync(0xFFFFFFFFu, Ar, off);
        float pAi = __shfl_up_sync(0xFFFFFFFFu, Ai, off);
        float pbr = __shfl_up_sync(0xFFFFFFFFu, br, off);
        float pbi = __shfl_up_sync(0xFFFFFFFFu, bi, off);
        if (lane >= off) combine_right(Ar, Ai, br, bi, pAr, pAi, pbr, pbi);
    }

    float er = __shfl_up_sync(0xFFFFFFFFu, br, 1);
    float ei = __shfl_up_sync(0xFFFFFFFFu, bi, 1);
    if (lane == 0) { er = 0.0f; ei = 0.0f; }
    if (lane < NCHUNK) {
        size_t q = ((size_t)p * NCHUNK + lane) * 2;
        g_pre[q] = er; g_pre[q + 1] = ei;
    }
}

// ======================== Scan phase C: serial-8 inclusive + prefix apply ========================
// Writes x directly as bf16 planes (gemm2's format); fp32 write-back dropped.
__global__ __launch_bounds__(SCAN_T) void scan_apply(
    const float* __restrict__ dtv, const float* __restrict__ Lre_g,
    const float* __restrict__ Lim_g, const float* __restrict__ logstep)
{
    const int p = blockIdx.y;
    const int chunk = blockIdx.x;
    const int tid = threadIdx.x;
    const int l0 = chunk * CHUNK + tid * VPT;
    const int lane = tid & 31, wid = tid >> 5;

    const float lre = Lre_g[p], lim = Lim_g[p];
    const float stp = expf(logstep[p]);
    const float* xr = g_x_re + (size_t)p * L_SEQ + l0;
    const float* xi = g_x_im + (size_t)p * L_SEQ + l0;

    float dt[VPT], bvr[VPT], bvi[VPT];
    {
        float4 d0 = *(const float4*)(dtv + l0);
        float4 d1 = *(const float4*)(dtv + l0 + 4);
        dt[0]=d0.x; dt[1]=d0.y; dt[2]=d0.z; dt[3]=d0.w;
        dt[4]=d1.x; dt[5]=d1.y; dt[6]=d1.z; dt[7]=d1.w;
        float4 r0 = *(const float4*)(xr), r1 = *(const float4*)(xr + 4);
        bvr[0]=r0.x; bvr[1]=r0.y; bvr[2]=r0.z; bvr[3]=r0.w;
        bvr[4]=r1.x; bvr[5]=r1.y; bvr[6]=r1.z; bvr[7]=r1.w;
        float4 i0 = *(const float4*)(xi), i1 = *(const float4*)(xi + 4);
        bvi[0]=i0.x; bvi[1]=i0.y; bvi[2]=i0.z; bvi[3]=i0.w;
        bvi[4]=i1.x; bvi[5]=i1.y; bvi[6]=i1.z; bvi[7]=i1.w;
    }

    float IAr[VPT], IAi[VPT], Ibr[VPT], Ibi[VPT];
    {
        float Aer, Aei;
        lambda_bar(lre, lim, dt[0] * stp, Aer, Aei);
        IAr[0] = Aer; IAi[0] = Aei; Ibr[0] = bvr[0]; Ibi[0] = bvi[0];
#pragma unroll
        for (int e = 1; e < VPT; e++) {
            lambda_bar(lre, lim, dt[e] * stp, Aer, Aei);
            IAr[e] = Aer*IAr[e-1] - Aei*IAi[e-1];
            IAi[e] = Aer*IAi[e-1] + Aei*IAr[e-1];
            Ibr[e] = Aer*Ibr[e-1] - Aei*Ibi[e-1] + bvr[e];
            Ibi[e] = Aer*Ibi[e-1] + Aei*Ibr[e-1] + bvi[e];
        }
    }

    float Ar = IAr[VPT-1], Ai = IAi[VPT-1], br = Ibr[VPT-1], bi = Ibi[VPT-1];
#pragma unroll
    for (int off = 1; off < 32; off <<= 1) {
        float pAr = __shfl_up_sync(0xFFFFFFFFu, Ar, off);
        float pAi = __shfl_up_sync(0xFFFFFFFFu, Ai, off);
        float pbr = __shfl_up_sync(0xFFFFFFFFu, br, off);
        float pbi = __shfl_up_sync(0xFFFFFFFFu, bi, off);
        if (lane >= off) combine_right(Ar, Ai, br, bi, pAr, pAi, pbr, pbi);
    }

    float EwAr = __shfl_up_sync(0xFFFFFFFFu, Ar, 1);
    float EwAi = __shfl_up_sync(0xFFFFFFFFu, Ai, 1);
    float Ewbr = __shfl_up_sync(0xFFFFFFFFu, br, 1);
    float Ewbi = __shfl_up_sync(0xFFFFFFFFu, bi, 1);
    if (lane == 0) { EwAr = 1.0f; EwAi = 0.0f; Ewbr = 0.0f; Ewbi = 0.0f; }

    __shared__ float sW[8][4];
    if (lane == 31) { sW[wid][0] = Ar; sW[wid][1] = Ai; sW[wid][2] = br; sW[wid][3] = bi; }
    __syncthreads();

    float PAr = 1.0f, PAi = 0.0f, Pbr = 0.0f, Pbi = 0.0f;
#pragma unroll
    for (int w = 0; w < 7; w++) {
        if (w < wid) {
            float wAr = sW[w][0], wAi = sW[w][1], wbr = sW[w][2], wbi = sW[w][3];
            float nAr = wAr*PAr - wAi*PAi;
            float nAi = wAr*PAi + wAi*PAr;
            float nbr = wAr*Pbr - wAi*Pbi + wbr;
            float nbi = wAr*Pbi + wAi*Pbr + wbi;
            PAr = nAr; PAi = nAi; Pbr = nbr; Pbi = nbi;
        }
    }

    float EAr = EwAr*PAr - EwAi*PAi;
    float EAi = EwAr*PAi + EwAi*PAr;
    float Ebr = EwAr*Pbr - EwAi*Pbi + Ewbr;
    float Ebi = EwAr*Pbi + EwAi*Pbr + Ewbi;

    size_t q = ((size_t)p * NCHUNK + chunk) * 2;
    float pcr = g_pre[q], pci = g_pre[q + 1];
    float xpr = EAr*pcr - EAi*pci + Ebr;
    float xpi = EAr*pci + EAi*pcr + Ebi;

    float o_r[VPT], o_i[VPT];
#pragma unroll
    for (int e = 0; e < VPT; e++) {
        o_r[e] = IAr[e]*xpr - IAi[e]*xpi + Ibr[e];
        o_i[e] = IAr[e]*xpi + IAi[e]*xpr + Ibi[e];
    }
    // write bf16 planes (coalesced 16B per thread)
    *(uint4*)(g_xrbf + (size_t)p * L_SEQ + l0) =
        make_uint4(packbf(o_r[0], o_r[1]), packbf(o_r[2], o_r[3]),
                   packbf(o_r[4], o_r[5]), packbf(o_r[6], o_r[7]));
    *(uint4*)(g_xibf + (size_t)p * L_SEQ + l0) =
        make_uint4(packbf(o_i[0], o_i[1]), packbf(o_i[2], o_i[3]),
                   packbf(o_i[4], o_i[5]), packbf(o_i[6], o_i[7]));
}

// ======================== GEMM2 (bf16 mma): y = 2*(xre Cre^T - xim Cim^T) + D*u ========================
#define G2_BM 64
#define G2_BN 512
#define G2_BK 32
#define G2_AGW (G2_BM * 8 + 8)    // 520 words per k16-group plane (A)
#define G2_BGW (G2_BN * 8 + 8)    // 4104 words per k16-group plane (B)
#define G2_AR_OFF 0
#define G2_AI_OFF (2 * G2_AGW)
#define G2_BR_OFF (4 * G2_AGW)
#define G2_BI_OFF (G2_BR_OFF + 2 * G2_BGW)
#define G2_SMEM_WORDS (G2_BI_OFF + 2 * G2_BGW)
#define G2_SMEM_BYTES (G2_SMEM_WORDS * 4)

__global__ __launch_bounds__(512, 1) void gemm2(
    const float* __restrict__ u, const float* __restrict__ Dg,
    float* __restrict__ out)
{
    extern __shared__ uint32_t sm2[];
    const int tid = threadIdx.x;
    const int wid = tid >> 5, lane = tid & 31;
    const int g = lane >> 2, t = lane & 3;
    const int wm = wid >> 3, wn = wid & 7;        // 2x8 warps, warp tile 32l x 64h
    const int bm = blockIdx.x * G2_BM;

    // A fill constants
    const int tt = tid & 255;
    const int aj = tt >> 4;                 // k-pair index 0..15
    const int al4 = (tt & 15) * 4;          // l offset
    const int asel = tid >> 8;              // 0: re, 1: im (negated)
    const int abase = (asel ? G2_AI_OFF : G2_AR_OFF)
                      + (aj >> 3) * G2_AGW + al4 * 8 + kperm(aj & 7);
    const uint16_t* aplane = asel ? g_xibf : g_xrbf;
    const uint32_t aneg = asel ? 0x80008000u : 0u;

    float acc[2][8][4];
#pragma unroll
    for (int i = 0; i < 2; i++)
#pragma unroll
        for (int j = 0; j < 8; j++)
#pragma unroll
            for (int r = 0; r < 4; r++) acc[i][j][r] = 0.0f;

    for (int kt = 0; kt < P_DIM; kt += G2_BK) {
        // fill A: pack (p, p+1) bf16 pairs from planes; im negated via sign XOR
        {
            const uint16_t* pe = aplane + (size_t)(kt + 2 * aj) * L_SEQ + bm + al4;
            const uint16_t* po = pe + L_SEQ;
            ushort4 fe = *(const ushort4*)pe;
            ushort4 fo = *(const ushort4*)po;
            sm2[abase + 0]  = (((uint32_t)fe.x) | ((uint32_t)fo.x << 16)) ^ aneg;
            sm2[abase + 8]  = (((uint32_t)fe.y) | ((uint32_t)fo.y << 16)) ^ aneg;
            sm2[abase + 16] = (((uint32_t)fe.z) | ((uint32_t)fo.z << 16)) ^ aneg;
            sm2[abase + 24] = (((uint32_t)fe.w) | ((uint32_t)fo.w << 16)) ^ aneg;
        }
        // fill B (C planes): bf16 words direct
#pragma unroll
        for (int j = 0; j < 8; j++) {
            int idx = tid + j * 512;
            int row = idx >> 3, c = idx & 7;
            int grp = c >> 2, w0 = (c & 3) * 2;
            int base = grp * G2_BGW + row * 8;
            int p0 = kperm(w0), p1 = kperm(w0 + 1);
            uint2 vr = *(const uint2*)(g_Crbf + (size_t)row * P_DIM + kt + c * 4);
            sm2[G2_BR_OFF + base + p0] = vr.x;
            sm2[G2_BR_OFF + base + p1] = vr.y;
            uint2 vi = *(const uint2*)(g_Cibf + (size_t)row * P_DIM + kt + c * 4);
            sm2[G2_BI_OFF + base + p0] = vi.x;
            sm2[G2_BI_OFF + base + p1] = vi.y;
        }
        __syncthreads();

#pragma unroll
        for (int k16 = 0; k16 < 2; k16++) {
            uint32_t ar[2][4], ai[2][4];
#pragma unroll
            for (int mt = 0; mt < 2; mt++) {
                int row = wm * 32 + mt * 16 + g;
                const uint32_t* pr = &sm2[G2_AR_OFF + k16 * G2_AGW + row * 8 + 2 * t];
                uint2 lo = *(const uint2*)pr;
                uint2 hi = *(const uint2*)(pr + 64);
                ar[mt][0] = lo.x; ar[mt][2] = lo.y; ar[mt][1] = hi.x; ar[mt][3] = hi.y;
                const uint32_t* pi = &sm2[G2_AI_OFF + k16 * G2_AGW + row * 8 + 2 * t];
                uint2 lo2 = *(const uint2*)pi;
                uint2 hi2 = *(const uint2*)(pi + 64);
                ai[mt][0] = lo2.x; ai[mt][2] = lo2.y; ai[mt][1] = hi2.x; ai[mt][3] = hi2.y;
            }
#pragma unroll
            for (int nt = 0; nt < 8; nt++) {
                int row = wn * 64 + nt * 8 + g;
                uint2 br = *(const uint2*)&sm2[G2_BR_OFF + k16 * G2_BGW + row * 8 + 2 * t];
                uint2 bi = *(const uint2*)&sm2[G2_BI_OFF + k16 * G2_BGW + row * 8 + 2 * t];
#pragma unroll
                for (int mt = 0; mt < 2; mt++) {
                    mma_bf16(acc[mt][nt], ar[mt], br.x, br.y);
                    mma_bf16(acc[mt][nt], ai[mt], bi.x, bi.y);
                }
            }
        }
        __syncthreads();
    }

    // epilogue: y = 2*acc + D*u
#pragma unroll
    for (int mt = 0; mt < 2; mt++) {
#pragma unroll
        for (int rh = 0; rh < 2; rh++) {
            int l = bm + wm * 32 + mt * 16 + g + rh * 8;
#pragma unroll
            for (int nt = 0; nt < 8; nt++) {
                int h0 = wn * 64 + nt * 8 + 2 * t;
                float2 uu = *(const float2*)(u + (size_t)l * H_DIM + h0);
                float2 dd = *(const float2*)(Dg + h0);
                float2 o;
                o.x = 2.0f * acc[mt][nt][rh * 2 + 0] + dd.x * uu.x;
                o.y = 2.0f * acc[mt][nt][rh * 2 + 1] + dd.y * uu.y;
                *(float2*)(out + (size_t)l * H_DIM + h0) = o;
            }
        }
    }
}

// ======================== launch ========================
extern "C" void kernel_launch(void* const* d_in, const int* in_sizes, int n_in,
                              void* d_out, int out_size)
{
    const float* u   = (const float*)d_in[0];  // (L, H)
    const float* dtv = (const float*)d_in[1];  // (L,)
    const float* Lre = (const float*)d_in[2];  // (P,)
    const float* Lim = (const float*)d_in[3];  // (P,)
    const float* Bre = (const float*)d_in[4];  // (P, H)
    const float* Bim = (const float*)d_in[5];  // (P, H)
    const float* Cre = (const float*)d_in[6];  // (H, P)
    const float* Cim = (const float*)d_in[7];  // (H, P)
    const float* Dg  = (const float*)d_in[8];  // (H,)
    const float* lst = (const float*)d_in[9];  // (P,)
    float* out = (float*)d_out;                // (L, H)

    static int attr_done = 0;
    if (!attr_done) {
        cudaFuncSetAttribute(gemm1, cudaFuncAttributeMaxDynamicSharedMemorySize, G1_SMEM_BYTES);
        cudaFuncSetAttribute(gemm2, cudaFuncAttributeMaxDynamicSharedMemorySize, G2_SMEM_BYTES);
        attr_done = 1;
    }

    convert_u<<<(L_SEQ * H_DIM / 4) / 256, 256>>>(u);
    convert_mats<<<dim3((P_DIM * H_DIM / 4) / 256, 4), 256>>>(Bre, Bim, Cre, Cim);
    gemm1<<<dim3(P_DIM / G1_BN, L_SEQ / G1_BM), 512, G1_SMEM_BYTES>>>(dtv, Lre, Lim, lst);
    scan_agg<<<dim3(NCHUNK, P_DIM), SCAN_T>>>(dtv, Lre, Lim, lst);
    chunk_prefix<<<P_DIM, 32>>>();
    scan_apply<<<dim3(NCHUNK, P_DIM), SCAN_T>>>(dtv, Lre, Lim, lst);
    gemm2<<<L_SEQ / G2_BM, 512, G2_SMEM_BYTES>>>(u, Dg, out);
}

// round 12
// speedup vs baseline: 2.5382x; 1.2305x over previous
#include <cuda_runtime.h>
#include <math.h>
#include <stdint.h>

#define L_SEQ 32768
#define H_DIM 512
#define P_DIM 256
#define VPT 8
#define SCAN_T 256
#define CHUNK (SCAN_T * VPT)        // 2048
#define NCHUNK (L_SEQ / CHUNK)      // 16

// fp32 scratch planes [P][L]: Bu written by gemm1, read by scan.
__device__ float g_x_re[(size_t)P_DIM * L_SEQ];
__device__ float g_x_im[(size_t)P_DIM * L_SEQ];
__device__ float g_agg[P_DIM * NCHUNK * 4];
__device__ float g_pre[P_DIM * NCHUNK * 2];

// pre-permuted bf16 operand images (smem-tile layout: [k16-group][row][8 words])
__device__ uint32_t g_up[(size_t)32 * L_SEQ * 8];        // u:  kg 0..31 (h), row l
__device__ uint32_t g_Bp[2 * 32 * 256 * 8];              // B:  plane, kg (h), row p
__device__ uint32_t g_Cp[2 * 16 * 512 * 8];              // C:  plane, kg (p), row h
// bf16 scanned state planes [P][L] (written by scan_apply, read by gemm2 A fill)
__device__ uint16_t g_xrbf[(size_t)P_DIM * L_SEQ];
__device__ uint16_t g_xibf[(size_t)P_DIM * L_SEQ];

// ---------------- common helpers ----------------

__device__ __forceinline__ void combine_right(float& Ar, float& Ai, float& br, float& bi,
                                              float pAr, float pAi, float pbr, float pbi)
{
    float nAr = Ar*pAr - Ai*pAi;
    float nAi = Ar*pAi + Ai*pAr;
    float nbr = Ar*pbr - Ai*pbi + br;
    float nbi = Ar*pbi + Ai*pbr + bi;
    Ar = nAr; Ai = nAi; br = nbr; bi = nbi;
}

__device__ __forceinline__ void combine_left(float& Ar, float& Ai, float& br, float& bi,
                                             float rAr, float rAi, float rbr, float rbi)
{
    float nAr = rAr*Ar - rAi*Ai;
    float nAi = rAr*Ai + rAi*Ar;
    float nbr = rAr*br - rAi*bi + rbr;
    float nbi = rAr*bi + rAi*br + rbi;
    Ar = nAr; Ai = nAi; br = nbr; bi = nbi;
}

__device__ __forceinline__ void lambda_bar(float lre, float lim, float Dl, float& Ar, float& Ai)
{
    float e = expf(lre * Dl);
    float s, c;
    sincosf(lim * Dl, &s, &c);
    Ar = e * c;
    Ai = e * s;
}

__device__ __forceinline__ uint32_t packbf(float lo, float hi)
{
    uint32_t r;
    asm("cvt.rn.bf16x2.f32 %0, %1, %2;" : "=r"(r) : "f"(hi), "f"(lo));
    return r;
}

__device__ __forceinline__ void mma_bf16(float* d, const uint32_t* a, uint32_t b0, uint32_t b1)
{
    asm volatile(
        "mma.sync.aligned.m16n8k16.row.col.f32.bf16.bf16.f32 "
        "{%0,%1,%2,%3}, {%4,%5,%6,%7}, {%8,%9}, {%0,%1,%2,%3};"
        : "+f"(d[0]), "+f"(d[1]), "+f"(d[2]), "+f"(d[3])
        : "r"(a[0]), "r"(a[1]), "r"(a[2]), "r"(a[3]), "r"(b0), "r"(b1));
}

// word-permutation within an 8-group: position(w) = w<4 ? 2w : 2(w-4)+1
__device__ __forceinline__ constexpr int kperm(int w) { return (w < 4) ? (2 * w) : (2 * (w - 4) + 1); }

__device__ __forceinline__ uint32_t smem_u32(const void* p) {
    uint32_t a;
    asm("{ .reg .u64 t; cvta.to.shared.u64 t, %1; cvt.u32.u64 %0, t; }" : "=r"(a) : "l"(p));
    return a;
}

#define CP_ASYNC16(dst, src) \
    asm volatile("cp.async.cg.shared.global [%0], [%1], 16;" :: "r"(dst), "l"(src) : "memory")
#define CP_COMMIT() asm volatile("cp.async.commit_group;" ::: "memory")
#define CP_WAIT1()  asm volatile("cp.async.wait_group 1;" ::: "memory")
#define CP_WAIT0()  asm volatile("cp.async.wait_group 0;" ::: "memory")

// ======================== converters (permuting) ========================
__global__ __launch_bounds__(256) void convert_u_p(const float* __restrict__ u)
{
    int id = blockIdx.x * 256 + threadIdx.x;   // 32 kg x 32768 l
    int kg = id >> 15;
    int l  = id & 32767;
    const float* src = u + (size_t)l * H_DIM + kg * 16;
    float4 v0 = *(const float4*)(src + 0);
    float4 v1 = *(const float4*)(src + 4);
    float4 v2 = *(const float4*)(src + 8);
    float4 v3 = *(const float4*)(src + 12);
    uint32_t w[8];
    w[kperm(0)] = packbf(v0.x, v0.y); w[kperm(1)] = packbf(v0.z, v0.w);
    w[kperm(2)] = packbf(v1.x, v1.y); w[kperm(3)] = packbf(v1.z, v1.w);
    w[kperm(4)] = packbf(v2.x, v2.y); w[kperm(5)] = packbf(v2.z, v2.w);
    w[kperm(6)] = packbf(v3.x, v3.y); w[kperm(7)] = packbf(v3.z, v3.w);
    uint32_t* dst = g_up + ((size_t)kg * L_SEQ + l) * 8;
    *(uint4*)(dst)     = make_uint4(w[0], w[1], w[2], w[3]);
    *(uint4*)(dst + 4) = make_uint4(w[4], w[5], w[6], w[7]);
}

__global__ __launch_bounds__(256) void convert_B_p(
    const float* __restrict__ Bre, const float* __restrict__ Bim)
{
    int kg = blockIdx.x;      // 0..31 (h groups)
    int pl = blockIdx.y;      // 0..1
    int p  = threadIdx.x;     // 0..255
    const float* src = (pl ? Bim : Bre) + (size_t)p * H_DIM + kg * 16;
    float4 v0 = *(const float4*)(src + 0);
    float4 v1 = *(const float4*)(src + 4);
    float4 v2 = *(const float4*)(src + 8);
    float4 v3 = *(const float4*)(src + 12);
    uint32_t w[8];
    w[kperm(0)] = packbf(v0.x, v0.y); w[kperm(1)] = packbf(v0.z, v0.w);
    w[kperm(2)] = packbf(v1.x, v1.y); w[kperm(3)] = packbf(v1.z, v1.w);
    w[kperm(4)] = packbf(v2.x, v2.y); w[kperm(5)] = packbf(v2.z, v2.w);
    w[kperm(6)] = packbf(v3.x, v3.y); w[kperm(7)] = packbf(v3.z, v3.w);
    uint32_t* dst = g_Bp + ((size_t)(pl * 32 + kg) * 256 + p) * 8;
    *(uint4*)(dst)     = make_uint4(w[0], w[1], w[2], w[3]);
    *(uint4*)(dst + 4) = make_uint4(w[4], w[5], w[6], w[7]);
}

__global__ __launch_bounds__(512) void convert_C_p(
    const float* __restrict__ Cre, const float* __restrict__ Cim)
{
    int kg = blockIdx.x;      // 0..15 (p groups)
    int pl = blockIdx.y;
    int h  = threadIdx.x;     // 0..511
    const float* src = (pl ? Cim : Cre) + (size_t)h * P_DIM + kg * 16;
    float4 v0 = *(const float4*)(src + 0);
    float4 v1 = *(const float4*)(src + 4);
    float4 v2 = *(const float4*)(src + 8);
    float4 v3 = *(const float4*)(src + 12);
    uint32_t w[8];
    w[kperm(0)] = packbf(v0.x, v0.y); w[kperm(1)] = packbf(v0.z, v0.w);
    w[kperm(2)] = packbf(v1.x, v1.y); w[kperm(3)] = packbf(v1.z, v1.w);
    w[kperm(4)] = packbf(v2.x, v2.y); w[kperm(5)] = packbf(v2.z, v2.w);
    w[kperm(6)] = packbf(v3.x, v3.y); w[kperm(7)] = packbf(v3.z, v3.w);
    uint32_t* dst = g_Cp + ((size_t)(pl * 16 + kg) * 512 + h) * 8;
    *(uint4*)(dst)     = make_uint4(w[0], w[1], w[2], w[3]);
    *(uint4*)(dst + 4) = make_uint4(w[4], w[5], w[6], w[7]);
}

// ======================== GEMM1 (bf16 mma + cp.async ping-pong) ========================
// Bu = gamma_bar * (u @ B^T). BM=128 l, BN=128 p, BK=32 h. NS=16 steps.
// Buffer (words): A[0..2047] (2 grp x 128 row x 8), Br[2048..4095], Bi[4096..6143]
#define G1_BUFW 6144
#define G1_SMEM_BYTES (2 * G1_BUFW * 4)   // 49152

__global__ __launch_bounds__(512, 1) void gemm1(
    const float* __restrict__ dtv, const float* __restrict__ Lre_g, const float* __restrict__ Lim_g,
    const float* __restrict__ logstep)
{
    extern __shared__ uint32_t sm1[];
    const uint32_t smb = smem_u32(sm1);
    const int tid = threadIdx.x;
    const int wid = tid >> 5, lane = tid & 31;
    const int g = lane >> 2, t = lane & 3;
    const int wm = wid >> 2, wn = wid & 3;     // 4x4 warps, warp tile 32l x 32p
    const int bm = blockIdx.y * 128;
    const int bn = blockIdx.x * 128;

    const int cg = tid >> 8, co = tid & 255;   // copy: group sel + 16B-chunk offset

    float accr[2][4][4];
    float acci[2][4][4];
#pragma unroll
    for (int i = 0; i < 2; i++)
#pragma unroll
        for (int j = 0; j < 4; j++)
#pragma unroll
            for (int r = 0; r < 4; r++) { accr[i][j][r] = 0.0f; acci[i][j][r] = 0.0f; }

    auto copy_step = [&](int s, int buf) {
        uint32_t sb = smb + buf * (G1_BUFW * 4);
        int kg = 2 * s + cg;
        // A: 2 x 4KB
        CP_ASYNC16(sb + cg * 4096 + co * 16,
                   (const char*)(g_up + ((size_t)kg * L_SEQ + bm) * 8) + co * 16);
        // Br: 2 x 4KB
        CP_ASYNC16(sb + 8192 + cg * 4096 + co * 16,
                   (const char*)(g_Bp + ((size_t)kg * 256 + bn) * 8) + co * 16);
        // Bi: 2 x 4KB
        CP_ASYNC16(sb + 16384 + cg * 4096 + co * 16,
                   (const char*)(g_Bp + ((size_t)(32 + kg) * 256 + bn) * 8) + co * 16);
    };

    copy_step(0, 0);
    CP_COMMIT();

    for (int s = 0; s < 16; s++) {
        if (s + 1 < 16) { copy_step(s + 1, (s + 1) & 1); CP_COMMIT(); CP_WAIT1(); }
        else            { CP_WAIT0(); }
        __syncthreads();

        const uint32_t* cur = sm1 + (s & 1) * G1_BUFW;
#pragma unroll
        for (int k16 = 0; k16 < 2; k16++) {
            uint32_t a[2][4];
#pragma unroll
            for (int mt = 0; mt < 2; mt++) {
                int row = wm * 32 + mt * 16 + g;
                const uint32_t* p0 = cur + k16 * 1024 + row * 8 + 2 * t;
                uint2 lo = *(const uint2*)p0;
                uint2 hi = *(const uint2*)(p0 + 64);   // row + 8
                a[mt][0] = lo.x; a[mt][2] = lo.y;
                a[mt][1] = hi.x; a[mt][3] = hi.y;
            }
#pragma unroll
            for (int nt = 0; nt < 4; nt++) {
                int row = wn * 32 + nt * 8 + g;
                uint2 br = *(const uint2*)(cur + 2048 + k16 * 1024 + row * 8 + 2 * t);
                uint2 bi = *(const uint2*)(cur + 4096 + k16 * 1024 + row * 8 + 2 * t);
#pragma unroll
                for (int mt = 0; mt < 2; mt++) {
                    mma_bf16(accr[mt][nt], a[mt], br.x, br.y);
                    mma_bf16(acci[mt][nt], a[mt], bi.x, bi.y);
                }
            }
        }
        __syncthreads();
    }

    // epilogue: gamma_bar multiply, store fp32 Bu to [P][L] planes
    float dts[2][2];
#pragma unroll
    for (int mt = 0; mt < 2; mt++)
#pragma unroll
        for (int rh = 0; rh < 2; rh++)
            dts[mt][rh] = dtv[bm + wm * 32 + mt * 16 + g + rh * 8];

#pragma unroll
    for (int nt = 0; nt < 4; nt++) {
#pragma unroll
        for (int c = 0; c < 2; c++) {
            int p = bn + wn * 32 + nt * 8 + 2 * t + c;
            float lre = Lre_g[p], lim = Lim_g[p];
            float stp = expf(logstep[p]);
            float inv = 1.0f / (lre * lre + lim * lim);
#pragma unroll
            for (int mt = 0; mt < 2; mt++) {
#pragma unroll
                for (int rh = 0; rh < 2; rh++) {
                    int l = bm + wm * 32 + mt * 16 + g + rh * 8;
                    float Dl = dts[mt][rh] * stp;
                    float Ar, Ai;
                    lambda_bar(lre, lim, Dl, Ar, Ai);
                    float gr = ((Ar - 1.0f) * lre + Ai * lim) * inv;
                    float gi = (Ai * lre - (Ar - 1.0f) * lim) * inv;
                    int reg = rh * 2 + c;
                    float ar = accr[mt][nt][reg], ai = acci[mt][nt][reg];
                    size_t o = (size_t)p * L_SEQ + l;
                    g_x_re[o] = gr * ar - gi * ai;
                    g_x_im[o] = gr * ai + gi * ar;
                }
            }
        }
    }
}

// ======================== Scan phase A: serial-8 per thread, then reduce ========================
__global__ __launch_bounds__(SCAN_T) void scan_agg(
    const float* __restrict__ dtv, const float* __restrict__ Lre_g,
    const float* __restrict__ Lim_g, const float* __restrict__ logstep)
{
    const int p = blockIdx.y;
    const int chunk = blockIdx.x;
    const int tid = threadIdx.x;
    const int l0 = chunk * CHUNK + tid * VPT;

    const float lre = Lre_g[p], lim = Lim_g[p];
    const float stp = expf(logstep[p]);
    const float* xr = g_x_re + (size_t)p * L_SEQ + l0;
    const float* xi = g_x_im + (size_t)p * L_SEQ + l0;

    float dt[VPT], bvr[VPT], bvi[VPT];
    {
        float4 d0 = *(const float4*)(dtv + l0);
        float4 d1 = *(const float4*)(dtv + l0 + 4);
        dt[0]=d0.x; dt[1]=d0.y; dt[2]=d0.z; dt[3]=d0.w;
        dt[4]=d1.x; dt[5]=d1.y; dt[6]=d1.z; dt[7]=d1.w;
        float4 r0 = *(const float4*)(xr), r1 = *(const float4*)(xr + 4);
        bvr[0]=r0.x; bvr[1]=r0.y; bvr[2]=r0.z; bvr[3]=r0.w;
        bvr[4]=r1.x; bvr[5]=r1.y; bvr[6]=r1.z; bvr[7]=r1.w;
        float4 i0 = *(const float4*)(xi), i1 = *(const float4*)(xi + 4);
        bvi[0]=i0.x; bvi[1]=i0.y; bvi[2]=i0.z; bvi[3]=i0.w;
        bvi[4]=i1.x; bvi[5]=i1.y; bvi[6]=i1.z; bvi[7]=i1.w;
    }

    float Ar, Ai, br, bi;
    lambda_bar(lre, lim, dt[0] * stp, Ar, Ai);
    br = bvr[0]; bi = bvi[0];
#pragma unroll
    for (int e = 1; e < VPT; e++) {
        float Aer, Aei;
        lambda_bar(lre, lim, dt[e] * stp, Aer, Aei);
        float nAr = Aer*Ar - Aei*Ai;
        float nAi = Aer*Ai + Aei*Ar;
        float nbr = Aer*br - Aei*bi + bvr[e];
        float nbi = Aer*bi + Aei*br + bvi[e];
        Ar = nAr; Ai = nAi; br = nbr; bi = nbi;
    }

#pragma unroll
    for (int off = 1; off < 32; off <<= 1) {
        float rAr = __shfl_down_sync(0xFFFFFFFFu, Ar, off);
        float rAi = __shfl_down_sync(0xFFFFFFFFu, Ai, off);
        float rbr = __shfl_down_sync(0xFFFFFFFFu, br, off);
        float rbi = __shfl_down_sync(0xFFFFFFFFu, bi, off);
        combine_left(Ar, Ai, br, bi, rAr, rAi, rbr, rbi);
    }

    __shared__ float sA_r[8], sA_i[8], sb_r[8], sb_i[8];
    int lane = tid & 31, wid = tid >> 5;
    if (lane == 0) { sA_r[wid] = Ar; sA_i[wid] = Ai; sb_r[wid] = br; sb_i[wid] = bi; }
    __syncthreads();

    if (wid == 0) {
        float aAr = (lane < 8) ? sA_r[lane] : 1.0f;
        float aAi = (lane < 8) ? sA_i[lane] : 0.0f;
        float abr = (lane < 8) ? sb_r[lane] : 0.0f;
        float abi = (lane < 8) ? sb_i[lane] : 0.0f;
#pragma unroll
        for (int off = 1; off < 8; off <<= 1) {
            float rAr = __shfl_down_sync(0xFFFFFFFFu, aAr, off);
            float rAi = __shfl_down_sync(0xFFFFFFFFu, aAi, off);
            float rbr = __shfl_down_sync(0xFFFFFFFFu, abr, off);
            float rbi = __shfl_down_sync(0xFFFFFFFFu, abi, off);
            combine_left(aAr, aAi, abr, abi, rAr, rAi, rbr, rbi);
        }
        if (lane == 0) {
            size_t o = ((size_t)p * NCHUNK + chunk) * 4;
            g_agg[o + 0] = aAr; g_agg[o + 1] = aAi;
            g_agg[o + 2] = abr; g_agg[o + 3] = abi;
        }
    }
}

// ======================== Scan phase B ========================
__global__ __launch_bounds__(32) void chunk_prefix()
{
    const int p = blockIdx.x;
    const int lane = threadIdx.x;

    float Ar = 1.0f, Ai = 0.0f, br = 0.0f, bi = 0.0f;
    if (lane < NCHUNK) {
        size_t o = ((size_t)p * NCHUNK + lane) * 4;
        Ar = g_agg[o + 0]; Ai = g_agg[o + 1];
        br = g_agg[o + 2]; bi = g_agg[o + 3];
    }

#pragma unroll
    for (int off = 1; off < NCHUNK; off <<= 1) {
        float pAr = __shfl_up_sync(0xFFFFFFFFu, Ar, off);
        float pAi = __shfl_up_sync(0xFFFFFFFFu, Ai, off);
        float pbr = __shfl_up_sync(0xFFFFFFFFu, br, off);
        float pbi = __shfl_up_sync(0xFFFFFFFFu, bi, off);
        if (lane >= off) combine_right(Ar, Ai, br, bi, pAr, pAi, pbr, pbi);
    }

    float er = __shfl_up_sync(0xFFFFFFFFu, br, 1);
    float ei = __shfl_up_sync(0xFFFFFFFFu, bi, 1);
    if (lane == 0) { er = 0.0f; ei = 0.0f; }
    if (lane < NCHUNK) {
        size_t q = ((size_t)p * NCHUNK + lane) * 2;
        g_pre[q] = er; g_pre[q + 1] = ei;
    }
}

// ======================== Scan phase C: serial-8 inclusive + prefix apply ========================
__global__ __launch_bounds__(SCAN_T) void scan_apply(
    const float* __restrict__ dtv, const float* __restrict__ Lre_g,
    const float* __restrict__ Lim_g, const float* __restrict__ logstep)
{
    const int p = blockIdx.y;
    const int chunk = blockIdx.x;
    const int tid = threadIdx.x;
    const int l0 = chunk * CHUNK + tid * VPT;
    const int lane = tid & 31, wid = tid >> 5;

    const float lre = Lre_g[p], lim = Lim_g[p];
    const float stp = expf(logstep[p]);
    const float* xr = g_x_re + (size_t)p * L_SEQ + l0;
    const float* xi = g_x_im + (size_t)p * L_SEQ + l0;

    float dt[VPT], bvr[VPT], bvi[VPT];
    {
        float4 d0 = *(const float4*)(dtv + l0);
        float4 d1 = *(const float4*)(dtv + l0 + 4);
        dt[0]=d0.x; dt[1]=d0.y; dt[2]=d0.z; dt[3]=d0.w;
        dt[4]=d1.x; dt[5]=d1.y; dt[6]=d1.z; dt[7]=d1.w;
        float4 r0 = *(const float4*)(xr), r1 = *(const float4*)(xr + 4);
        bvr[0]=r0.x; bvr[1]=r0.y; bvr[2]=r0.z; bvr[3]=r0.w;
        bvr[4]=r1.x; bvr[5]=r1.y; bvr[6]=r1.z; bvr[7]=r1.w;
        float4 i0 = *(const float4*)(xi), i1 = *(const float4*)(xi + 4);
        bvi[0]=i0.x; bvi[1]=i0.y; bvi[2]=i0.z; bvi[3]=i0.w;
        bvi[4]=i1.x; bvi[5]=i1.y; bvi[6]=i1.z; bvi[7]=i1.w;
    }

    float IAr[VPT], IAi[VPT], Ibr[VPT], Ibi[VPT];
    {
        float Aer, Aei;
        lambda_bar(lre, lim, dt[0] * stp, Aer, Aei);
        IAr[0] = Aer; IAi[0] = Aei; Ibr[0] = bvr[0]; Ibi[0] = bvi[0];
#pragma unroll
        for (int e = 1; e < VPT; e++) {
            lambda_bar(lre, lim, dt[e] * stp, Aer, Aei);
            IAr[e] = Aer*IAr[e-1] - Aei*IAi[e-1];
            IAi[e] = Aer*IAi[e-1] + Aei*IAr[e-1];
            Ibr[e] = Aer*Ibr[e-1] - Aei*Ibi[e-1] + bvr[e];
            Ibi[e] = Aer*Ibi[e-1] + Aei*Ibr[e-1] + bvi[e];
        }
    }

    float Ar = IAr[VPT-1], Ai = IAi[VPT-1], br = Ibr[VPT-1], bi = Ibi[VPT-1];
#pragma unroll
    for (int off = 1; off < 32; off <<= 1) {
        float pAr = __shfl_up_sync(0xFFFFFFFFu, Ar, off);
        float pAi = __shfl_up_sync(0xFFFFFFFFu, Ai, off);
        float pbr = __shfl_up_sync(0xFFFFFFFFu, br, off);
        float pbi = __shfl_up_sync(0xFFFFFFFFu, bi, off);
        if (lane >= off) combine_right(Ar, Ai, br, bi, pAr, pAi, pbr, pbi);
    }

    float EwAr = __shfl_up_sync(0xFFFFFFFFu, Ar, 1);
    float EwAi = __shfl_up_sync(0xFFFFFFFFu, Ai, 1);
    float Ewbr = __shfl_up_sync(0xFFFFFFFFu, br, 1);
    float Ewbi = __shfl_up_sync(0xFFFFFFFFu, bi, 1);
    if (lane == 0) { EwAr = 1.0f; EwAi = 0.0f; Ewbr = 0.0f; Ewbi = 0.0f; }

    __shared__ float sW[8][4];
    if (lane == 31) { sW[wid][0] = Ar; sW[wid][1] = Ai; sW[wid][2] = br; sW[wid][3] = bi; }
    __syncthreads();

    float PAr = 1.0f, PAi = 0.0f, Pbr = 0.0f, Pbi = 0.0f;
#pragma unroll
    for (int w = 0; w < 7; w++) {
        if (w < wid) {
            float wAr = sW[w][0], wAi = sW[w][1], wbr = sW[w][2], wbi = sW[w][3];
            float nAr = wAr*PAr - wAi*PAi;
            float nAi = wAr*PAi + wAi*PAr;
            float nbr = wAr*Pbr - wAi*Pbi + wbr;
            float nbi = wAr*Pbi + wAi*Pbr + wbi;
            PAr = nAr; PAi = nAi; Pbr = nbr; Pbi = nbi;
        }
    }

    float EAr = EwAr*PAr - EwAi*PAi;
    float EAi = EwAr*PAi + EwAi*PAr;
    float Ebr = EwAr*Pbr - EwAi*Pbi + Ewbr;
    float Ebi = EwAr*Pbi + EwAi*Pbr + Ewbi;

    size_t q = ((size_t)p * NCHUNK + chunk) * 2;
    float pcr = g_pre[q], pci = g_pre[q + 1];
    float xpr = EAr*pcr - EAi*pci + Ebr;
    float xpi = EAr*pci + EAi*pcr + Ebi;

    float o_r[VPT], o_i[VPT];
#pragma unroll
    for (int e = 0; e < VPT; e++) {
        o_r[e] = IAr[e]*xpr - IAi[e]*xpi + Ibr[e];
        o_i[e] = IAr[e]*xpi + IAi[e]*xpr + Ibi[e];
    }
    *(uint4*)(g_xrbf + (size_t)p * L_SEQ + l0) =
        make_uint4(packbf(o_r[0], o_r[1]), packbf(o_r[2], o_r[3]),
                   packbf(o_r[4], o_r[5]), packbf(o_r[6], o_r[7]));
    *(uint4*)(g_xibf + (size_t)p * L_SEQ + l0) =
        make_uint4(packbf(o_i[0], o_i[1]), packbf(o_i[2], o_i[3]),
                   packbf(o_i[4], o_i[5]), packbf(o_i[6], o_i[7]));
}

// ======================== GEMM2 (bf16 mma + cp.async ping-pong) ========================
// y = 2*(xre Cre^T - xim Cim^T) + D*u. BM=64 l, BN=512 h, BK=32 p. NS=8 steps.
// Buffer (words): Ar[0..1023] (2grp x 64row x 8), Ai[1024..2047],
//                 Br[2048..10239] (2grp x 512row x 8), Bi[10240..18431]
#define G2_BUFW 18432
#define G2_SMEM_BYTES (2 * G2_BUFW * 4)   // 147456

__global__ __launch_bounds__(512, 1) void gemm2(
    const float* __restrict__ u, const float* __restrict__ Dg,
    float* __restrict__ out)
{
    extern __shared__ uint32_t sm2[];
    const uint32_t smb = smem_u32(sm2);
    const int tid = threadIdx.x;
    const int wid = tid >> 5, lane = tid & 31;
    const int g = lane >> 2, t = lane & 3;
    const int wm = wid >> 3, wn = wid & 7;        // 2x8 warps, warp tile 32l x 64h
    const int bm = blockIdx.x * 64;

    // A staging constants
    const int tt = tid & 255;
    const int aj = tt >> 4;                 // p-pair index 0..15
    const int al4 = (tt & 15) * 4;          // l offset
    const int asel = tid >> 8;              // 0: re, 1: im (negated)
    const int ajp = (aj & 7);
    const int abase = (asel ? 1024 : 0) + (aj >> 3) * 512 + al4 * 8
                      + ((ajp < 4) ? (2 * ajp) : (2 * (ajp - 4) + 1));
    const uint16_t* aplane = asel ? g_xibf : g_xrbf;
    const uint32_t aneg = asel ? 0x80008000u : 0u;

    ushort4 fe, fo;
    auto ldA = [&](int s) {
        const uint16_t* pe = aplane + (size_t)(s * 32 + 2 * aj) * L_SEQ + bm + al4;
        fe = *(const ushort4*)pe;
        fo = *(const ushort4*)(pe + L_SEQ);
    };
    auto stA = [&](int buf) {
        uint32_t* d = sm2 + buf * G2_BUFW + abase;
        d[0]  = (((uint32_t)fe.x) | ((uint32_t)fo.x << 16)) ^ aneg;
        d[8]  = (((uint32_t)fe.y) | ((uint32_t)fo.y << 16)) ^ aneg;
        d[16] = (((uint32_t)fe.z) | ((uint32_t)fo.z << 16)) ^ aneg;
        d[24] = (((uint32_t)fe.w) | ((uint32_t)fo.w << 16)) ^ aneg;
    };
    auto copyB = [&](int s, int buf) {
        uint32_t sb = smb + buf * (G2_BUFW * 4);
#pragma unroll
        for (int j = 0; j < 8; j++) {
            int pl = j >> 2;
            int c = tid + (j & 3) * 512;   // 0..2047 within plane (32KB)
            CP_ASYNC16(sb + (2048 + pl * 8192) * 4 + c * 16,
                       (const char*)(g_Cp + (size_t)(pl * 16 + 2 * s) * 512 * 8) + c * 16);
        }
    };

    float acc[2][8][4];
#pragma unroll
    for (int i = 0; i < 2; i++)
#pragma unroll
        for (int j = 0; j < 8; j++)
#pragma unroll
            for (int r = 0; r < 4; r++) acc[i][j][r] = 0.0f;

    ldA(0);
    copyB(0, 0);
    CP_COMMIT();
    stA(0);

    for (int s = 0; s < 8; s++) {
        if (s + 1 < 8) { copyB(s + 1, (s + 1) & 1); CP_COMMIT(); ldA(s + 1); CP_WAIT1(); }
        else           { CP_WAIT0(); }
        __syncthreads();

        const uint32_t* cur = sm2 + (s & 1) * G2_BUFW;
#pragma unroll
        for (int k16 = 0; k16 < 2; k16++) {
            uint32_t ar[2][4], ai[2][4];
#pragma unroll
            for (int mt = 0; mt < 2; mt++) {
                int row = wm * 32 + mt * 16 + g;
                const uint32_t* pr = cur + k16 * 512 + row * 8 + 2 * t;
                uint2 lo = *(const uint2*)pr;
                uint2 hi = *(const uint2*)(pr + 64);
                ar[mt][0] = lo.x; ar[mt][2] = lo.y; ar[mt][1] = hi.x; ar[mt][3] = hi.y;
                const uint32_t* pi = cur + 1024 + k16 * 512 + row * 8 + 2 * t;
                uint2 lo2 = *(const uint2*)pi;
                uint2 hi2 = *(const uint2*)(pi + 64);
                ai[mt][0] = lo2.x; ai[mt][2] = lo2.y; ai[mt][1] = hi2.x; ai[mt][3] = hi2.y;
            }
#pragma unroll
            for (int nt = 0; nt < 8; nt++) {
                int row = wn * 64 + nt * 8 + g;
                uint2 br = *(const uint2*)(cur + 2048 + k16 * 4096 + row * 8 + 2 * t);
                uint2 bi = *(const uint2*)(cur + 10240 + k16 * 4096 + row * 8 + 2 * t);
#pragma unroll
                for (int mt = 0; mt < 2; mt++) {
                    mma_bf16(acc[mt][nt], ar[mt], br.x, br.y);
                    mma_bf16(acc[mt][nt], ai[mt], bi.x, bi.y);
                }
            }
        }

        if (s + 1 < 8) stA((s + 1) & 1);
        __syncthreads();
    }

    // epilogue: y = 2*acc + D*u
#pragma unroll
    for (int mt = 0; mt < 2; mt++) {
#pragma unroll
        for (int rh = 0; rh < 2; rh++) {
            int l = bm + wm * 32 + mt * 16 + g + rh * 8;
#pragma unroll
            for (int nt = 0; nt < 8; nt++) {
                int h0 = wn * 64 + nt * 8 + 2 * t;
                float2 uu = *(const float2*)(u + (size_t)l * H_DIM + h0);
                float2 dd = *(const float2*)(Dg + h0);
                float2 o;
                o.x = 2.0f * acc[mt][nt][rh * 2 + 0] + dd.x * uu.x;
                o.y = 2.0f * acc[mt][nt][rh * 2 + 1] + dd.y * uu.y;
                *(float2*)(out + (size_t)l * H_DIM + h0) = o;
            }
        }
    }
}

// ======================== launch ========================
extern "C" void kernel_launch(void* const* d_in, const int* in_sizes, int n_in,
                              void* d_out, int out_size)
{
    const float* u   = (const float*)d_in[0];  // (L, H)
    const float* dtv = (const float*)d_in[1];  // (L,)
    const float* Lre = (const float*)d_in[2];  // (P,)
    const float* Lim = (const float*)d_in[3];  // (P,)
    const float* Bre = (const float*)d_in[4];  // (P, H)
    const float* Bim = (const float*)d_in[5];  // (P, H)
    const float* Cre = (const float*)d_in[6];  // (H, P)
    const float* Cim = (const float*)d_in[7];  // (H, P)
    const float* Dg  = (const float*)d_in[8];  // (H,)
    const float* lst = (const float*)d_in[9];  // (P,)
    float* out = (float*)d_out;                // (L, H)

    static int attr_done = 0;
    if (!attr_done) {
        cudaFuncSetAttribute(gemm1, cudaFuncAttributeMaxDynamicSharedMemorySize, G1_SMEM_BYTES);
        cudaFuncSetAttribute(gemm2, cudaFuncAttributeMaxDynamicSharedMemorySize, G2_SMEM_BYTES);
        attr_done = 1;
    }

    convert_u_p<<<(32 * L_SEQ) / 256, 256>>>(u);
    convert_B_p<<<dim3(32, 2), 256>>>(Bre, Bim);
    convert_C_p<<<dim3(16, 2), 512>>>(Cre, Cim);
    gemm1<<<dim3(P_DIM / 128, L_SEQ / 128), 512, G1_SMEM_BYTES>>>(dtv, Lre, Lim, lst);
    scan_agg<<<dim3(NCHUNK, P_DIM), SCAN_T>>>(dtv, Lre, Lim, lst);
    chunk_prefix<<<P_DIM, 32>>>();
    scan_apply<<<dim3(NCHUNK, P_DIM), SCAN_T>>>(dtv, Lre, Lim, lst);
    gemm2<<<L_SEQ / 64, 512, G2_SMEM_BYTES>>>(u, Dg, out);
}

// round 13
// speedup vs baseline: 3.0643x; 1.2073x over previous
#include <cuda_runtime.h>
#include <math.h>
#include <stdint.h>

#define L_SEQ 32768
#define H_DIM 512
#define P_DIM 256
#define VPT 8
#define SCAN_T 256
#define CHUNK (SCAN_T * VPT)        // 2048
#define NCHUNK (L_SEQ / CHUNK)      // 16

// fp32 scratch planes [P][L]: Bu written by gemm1, read by scan.
__device__ float g_x_re[(size_t)P_DIM * L_SEQ];
__device__ float g_x_im[(size_t)P_DIM * L_SEQ];
__device__ float g_agg[P_DIM * NCHUNK * 4];
__device__ float g_pre[P_DIM * NCHUNK * 2];

// pre-permuted bf16 operand images (smem-tile layout: [k16-group][row][8 words])
__device__ uint32_t g_up[(size_t)32 * L_SEQ * 8];        // u:  kg 0..31 (h), row l
__device__ uint32_t g_Bp[2 * 32 * 256 * 8];              // B:  plane, kg (h), row p
__device__ uint32_t g_Cp[2 * 16 * 512 * 8];              // C:  plane, kg (p), row h
// bf16 scanned state planes [P][L] (scan_apply -> pack_x)
__device__ uint16_t g_xrbf[(size_t)P_DIM * L_SEQ];
__device__ uint16_t g_xibf[(size_t)P_DIM * L_SEQ];
// packed gemm2 A image: [plane][kg 0..15][l][8 words], im plane pre-negated
__device__ uint32_t g_xp[(size_t)2 * 16 * L_SEQ * 8];

// ---------------- common helpers ----------------

__device__ __forceinline__ void combine_right(float& Ar, float& Ai, float& br, float& bi,
                                              float pAr, float pAi, float pbr, float pbi)
{
    float nAr = Ar*pAr - Ai*pAi;
    float nAi = Ar*pAi + Ai*pAr;
    float nbr = Ar*pbr - Ai*pbi + br;
    float nbi = Ar*pbi + Ai*pbr + bi;
    Ar = nAr; Ai = nAi; br = nbr; bi = nbi;
}

__device__ __forceinline__ void combine_left(float& Ar, float& Ai, float& br, float& bi,
                                             float rAr, float rAi, float rbr, float rbi)
{
    float nAr = rAr*Ar - rAi*Ai;
    float nAi = rAr*Ai + rAi*Ar;
    float nbr = rAr*br - rAi*bi + rbr;
    float nbi = rAr*bi + rAi*br + rbi;
    Ar = nAr; Ai = nAi; br = nbr; bi = nbi;
}

__device__ __forceinline__ void lambda_bar(float lre, float lim, float Dl, float& Ar, float& Ai)
{
    float e = expf(lre * Dl);
    float s, c;
    sincosf(lim * Dl, &s, &c);
    Ar = e * c;
    Ai = e * s;
}

__device__ __forceinline__ uint32_t packbf(float lo, float hi)
{
    uint32_t r;
    asm("cvt.rn.bf16x2.f32 %0, %1, %2;" : "=r"(r) : "f"(hi), "f"(lo));
    return r;
}

__device__ __forceinline__ void mma_bf16(float* d, const uint32_t* a, uint32_t b0, uint32_t b1)
{
    asm volatile(
        "mma.sync.aligned.m16n8k16.row.col.f32.bf16.bf16.f32 "
        "{%0,%1,%2,%3}, {%4,%5,%6,%7}, {%8,%9}, {%0,%1,%2,%3};"
        : "+f"(d[0]), "+f"(d[1]), "+f"(d[2]), "+f"(d[3])
        : "r"(a[0]), "r"(a[1]), "r"(a[2]), "r"(a[3]), "r"(b0), "r"(b1));
}

__device__ __forceinline__ constexpr int kperm(int w) { return (w < 4) ? (2 * w) : (2 * (w - 4) + 1); }

__device__ __forceinline__ uint32_t smem_u32(const void* p) {
    uint32_t a;
    asm("{ .reg .u64 t; cvta.to.shared.u64 t, %1; cvt.u32.u64 %0, t; }" : "=r"(a) : "l"(p));
    return a;
}

#define CP_ASYNC16(dst, src) \
    asm volatile("cp.async.cg.shared.global [%0], [%1], 16;" :: "r"(dst), "l"(src) : "memory")
#define CP_COMMIT() asm volatile("cp.async.commit_group;" ::: "memory")
#define CP_WAIT1()  asm volatile("cp.async.wait_group 1;" ::: "memory")
#define CP_WAIT0()  asm volatile("cp.async.wait_group 0;" ::: "memory")

// ======================== converters (permuting) ========================
__global__ __launch_bounds__(256) void convert_u_p(const float* __restrict__ u)
{
    int id = blockIdx.x * 256 + threadIdx.x;   // 32 kg x 32768 l
    int kg = id >> 15;
    int l  = id & 32767;
    const float* src = u + (size_t)l * H_DIM + kg * 16;
    float4 v0 = *(const float4*)(src + 0);
    float4 v1 = *(const float4*)(src + 4);
    float4 v2 = *(const float4*)(src + 8);
    float4 v3 = *(const float4*)(src + 12);
    uint32_t w[8];
    w[kperm(0)] = packbf(v0.x, v0.y); w[kperm(1)] = packbf(v0.z, v0.w);
    w[kperm(2)] = packbf(v1.x, v1.y); w[kperm(3)] = packbf(v1.z, v1.w);
    w[kperm(4)] = packbf(v2.x, v2.y); w[kperm(5)] = packbf(v2.z, v2.w);
    w[kperm(6)] = packbf(v3.x, v3.y); w[kperm(7)] = packbf(v3.z, v3.w);
    uint32_t* dst = g_up + ((size_t)kg * L_SEQ + l) * 8;
    *(uint4*)(dst)     = make_uint4(w[0], w[1], w[2], w[3]);
    *(uint4*)(dst + 4) = make_uint4(w[4], w[5], w[6], w[7]);
}

__global__ __launch_bounds__(256) void convert_B_p(
    const float* __restrict__ Bre, const float* __restrict__ Bim)
{
    int kg = blockIdx.x;      // 0..31 (h groups)
    int pl = blockIdx.y;      // 0..1
    int p  = threadIdx.x;     // 0..255
    const float* src = (pl ? Bim : Bre) + (size_t)p * H_DIM + kg * 16;
    float4 v0 = *(const float4*)(src + 0);
    float4 v1 = *(const float4*)(src + 4);
    float4 v2 = *(const float4*)(src + 8);
    float4 v3 = *(const float4*)(src + 12);
    uint32_t w[8];
    w[kperm(0)] = packbf(v0.x, v0.y); w[kperm(1)] = packbf(v0.z, v0.w);
    w[kperm(2)] = packbf(v1.x, v1.y); w[kperm(3)] = packbf(v1.z, v1.w);
    w[kperm(4)] = packbf(v2.x, v2.y); w[kperm(5)] = packbf(v2.z, v2.w);
    w[kperm(6)] = packbf(v3.x, v3.y); w[kperm(7)] = packbf(v3.z, v3.w);
    uint32_t* dst = g_Bp + ((size_t)(pl * 32 + kg) * 256 + p) * 8;
    *(uint4*)(dst)     = make_uint4(w[0], w[1], w[2], w[3]);
    *(uint4*)(dst + 4) = make_uint4(w[4], w[5], w[6], w[7]);
}

__global__ __launch_bounds__(512) void convert_C_p(
    const float* __restrict__ Cre, const float* __restrict__ Cim)
{
    int kg = blockIdx.x;      // 0..15 (p groups)
    int pl = blockIdx.y;
    int h  = threadIdx.x;     // 0..511
    const float* src = (pl ? Cim : Cre) + (size_t)h * P_DIM + kg * 16;
    float4 v0 = *(const float4*)(src + 0);
    float4 v1 = *(const float4*)(src + 4);
    float4 v2 = *(const float4*)(src + 8);
    float4 v3 = *(const float4*)(src + 12);
    uint32_t w[8];
    w[kperm(0)] = packbf(v0.x, v0.y); w[kperm(1)] = packbf(v0.z, v0.w);
    w[kperm(2)] = packbf(v1.x, v1.y); w[kperm(3)] = packbf(v1.z, v1.w);
    w[kperm(4)] = packbf(v2.x, v2.y); w[kperm(5)] = packbf(v2.z, v2.w);
    w[kperm(6)] = packbf(v3.x, v3.y); w[kperm(7)] = packbf(v3.z, v3.w);
    uint32_t* dst = g_Cp + ((size_t)(pl * 16 + kg) * 512 + h) * 8;
    *(uint4*)(dst)     = make_uint4(w[0], w[1], w[2], w[3]);
    *(uint4*)(dst + 4) = make_uint4(w[4], w[5], w[6], w[7]);
}

// ======================== GEMM1: 256 thr, 2 CTA/SM, 3-stage cp.async ========================
// Bu = gamma_bar * (u @ B^T). BM=128 l, BN=64 p, BK=32 h. 16 steps.
// Buffer (words): A[0..2047] (2grp x 128row x 8), Br[2048..3071] (2grp x 64 x 8), Bi[3072..4095]
#define G1_BUFW 4096
#define G1_SMEM_BYTES (3 * G1_BUFW * 4)   // 49152

__global__ __launch_bounds__(256, 2) void gemm1(
    const float* __restrict__ dtv, const float* __restrict__ Lre_g, const float* __restrict__ Lim_g,
    const float* __restrict__ logstep)
{
    extern __shared__ uint32_t sm1[];
    const uint32_t smb = smem_u32(sm1);
    const int tid = threadIdx.x;
    const int wid = tid >> 5, lane = tid & 31;
    const int g = lane >> 2, t = lane & 3;
    const int wm = wid >> 1, wn = wid & 1;     // 4x2 warps, warp tile 32l x 32p
    const int bm = blockIdx.y * 128;
    const int bn = blockIdx.x * 64;

    float accr[2][4][4];
    float acci[2][4][4];
#pragma unroll
    for (int i = 0; i < 2; i++)
#pragma unroll
        for (int j = 0; j < 4; j++)
#pragma unroll
            for (int r = 0; r < 4; r++) { accr[i][j][r] = 0.0f; acci[i][j][r] = 0.0f; }

    auto copy_step = [&](int s, int buf) {
        uint32_t sb = smb + buf * (G1_BUFW * 4);
        int kg = 2 * s;
        // A: 512 chunks (2 x 4KB)
#pragma unroll
        for (int j = 0; j < 2; j++) {
            int c = tid + j * 256;
            int grp = c >> 8, off = c & 255;
            CP_ASYNC16(sb + grp * 4096 + off * 16,
                       (const char*)(g_up + ((size_t)(kg + grp) * L_SEQ + bm) * 8) + off * 16);
        }
        // Br: 256 chunks (2 x 2KB)
        {
            int grp = tid >> 7, off = tid & 127;
            CP_ASYNC16(sb + 8192 + grp * 2048 + off * 16,
                       (const char*)(g_Bp + ((size_t)(kg + grp) * 256 + bn) * 8) + off * 16);
            CP_ASYNC16(sb + 12288 + grp * 2048 + off * 16,
                       (const char*)(g_Bp + ((size_t)(32 + kg + grp) * 256 + bn) * 8) + off * 16);
        }
    };

    copy_step(0, 0); CP_COMMIT();
    copy_step(1, 1); CP_COMMIT();

    for (int s = 0; s < 16; s++) {
        if (s < 15) CP_WAIT1(); else CP_WAIT0();
        __syncthreads();
        if (s + 2 < 16) { copy_step(s + 2, (s + 2) % 3); CP_COMMIT(); }

        const uint32_t* cur = sm1 + (s % 3) * G1_BUFW;
#pragma unroll
        for (int k16 = 0; k16 < 2; k16++) {
            uint32_t a[2][4];
#pragma unroll
            for (int mt = 0; mt < 2; mt++) {
                int row = wm * 32 + mt * 16 + g;
                const uint32_t* p0 = cur + k16 * 1024 + row * 8 + 2 * t;
                uint2 lo = *(const uint2*)p0;
                uint2 hi = *(const uint2*)(p0 + 64);
                a[mt][0] = lo.x; a[mt][2] = lo.y;
                a[mt][1] = hi.x; a[mt][3] = hi.y;
            }
#pragma unroll
            for (int nt = 0; nt < 4; nt++) {
                int row = wn * 32 + nt * 8 + g;
                uint2 br = *(const uint2*)(cur + 2048 + k16 * 512 + row * 8 + 2 * t);
                uint2 bi = *(const uint2*)(cur + 3072 + k16 * 512 + row * 8 + 2 * t);
#pragma unroll
                for (int mt = 0; mt < 2; mt++) {
                    mma_bf16(accr[mt][nt], a[mt], br.x, br.y);
                    mma_bf16(acci[mt][nt], a[mt], bi.x, bi.y);
                }
            }
        }
    }

    // epilogue: gamma_bar multiply, store fp32 Bu to [P][L] planes
    float dts[2][2];
#pragma unroll
    for (int mt = 0; mt < 2; mt++)
#pragma unroll
        for (int rh = 0; rh < 2; rh++)
            dts[mt][rh] = dtv[bm + wm * 32 + mt * 16 + g + rh * 8];

#pragma unroll
    for (int nt = 0; nt < 4; nt++) {
#pragma unroll
        for (int c = 0; c < 2; c++) {
            int p = bn + wn * 32 + nt * 8 + 2 * t + c;
            float lre = Lre_g[p], lim = Lim_g[p];
            float stp = expf(logstep[p]);
            float inv = 1.0f / (lre * lre + lim * lim);
#pragma unroll
            for (int mt = 0; mt < 2; mt++) {
#pragma unroll
                for (int rh = 0; rh < 2; rh++) {
                    int l = bm + wm * 32 + mt * 16 + g + rh * 8;
                    float Dl = dts[mt][rh] * stp;
                    float Ar, Ai;
                    lambda_bar(lre, lim, Dl, Ar, Ai);
                    float gr = ((Ar - 1.0f) * lre + Ai * lim) * inv;
                    float gi = (Ai * lre - (Ar - 1.0f) * lim) * inv;
                    int reg = rh * 2 + c;
                    float ar = accr[mt][nt][reg], ai = acci[mt][nt][reg];
                    size_t o = (size_t)p * L_SEQ + l;
                    g_x_re[o] = gr * ar - gi * ai;
                    g_x_im[o] = gr * ai + gi * ar;
                }
            }
        }
    }
}

// ======================== Scan phase A ========================
__global__ __launch_bounds__(SCAN_T) void scan_agg(
    const float* __restrict__ dtv, const float* __restrict__ Lre_g,
    const float* __restrict__ Lim_g, const float* __restrict__ logstep)
{
    const int p = blockIdx.y;
    const int chunk = blockIdx.x;
    const int tid = threadIdx.x;
    const int l0 = chunk * CHUNK + tid * VPT;

    const float lre = Lre_g[p], lim = Lim_g[p];
    const float stp = expf(logstep[p]);
    const float* xr = g_x_re + (size_t)p * L_SEQ + l0;
    const float* xi = g_x_im + (size_t)p * L_SEQ + l0;

    float dt[VPT], bvr[VPT], bvi[VPT];
    {
        float4 d0 = *(const float4*)(dtv + l0);
        float4 d1 = *(const float4*)(dtv + l0 + 4);
        dt[0]=d0.x; dt[1]=d0.y; dt[2]=d0.z; dt[3]=d0.w;
        dt[4]=d1.x; dt[5]=d1.y; dt[6]=d1.z; dt[7]=d1.w;
        float4 r0 = *(const float4*)(xr), r1 = *(const float4*)(xr + 4);
        bvr[0]=r0.x; bvr[1]=r0.y; bvr[2]=r0.z; bvr[3]=r0.w;
        bvr[4]=r1.x; bvr[5]=r1.y; bvr[6]=r1.z; bvr[7]=r1.w;
        float4 i0 = *(const float4*)(xi), i1 = *(const float4*)(xi + 4);
        bvi[0]=i0.x; bvi[1]=i0.y; bvi[2]=i0.z; bvi[3]=i0.w;
        bvi[4]=i1.x; bvi[5]=i1.y; bvi[6]=i1.z; bvi[7]=i1.w;
    }

    float Ar, Ai, br, bi;
    lambda_bar(lre, lim, dt[0] * stp, Ar, Ai);
    br = bvr[0]; bi = bvi[0];
#pragma unroll
    for (int e = 1; e < VPT; e++) {
        float Aer, Aei;
        lambda_bar(lre, lim, dt[e] * stp, Aer, Aei);
        float nAr = Aer*Ar - Aei*Ai;
        float nAi = Aer*Ai + Aei*Ar;
        float nbr = Aer*br - Aei*bi + bvr[e];
        float nbi = Aer*bi + Aei*br + bvi[e];
        Ar = nAr; Ai = nAi; br = nbr; bi = nbi;
    }

#pragma unroll
    for (int off = 1; off < 32; off <<= 1) {
        float rAr = __shfl_down_sync(0xFFFFFFFFu, Ar, off);
        float rAi = __shfl_down_sync(0xFFFFFFFFu, Ai, off);
        float rbr = __shfl_down_sync(0xFFFFFFFFu, br, off);
        float rbi = __shfl_down_sync(0xFFFFFFFFu, bi, off);
        combine_left(Ar, Ai, br, bi, rAr, rAi, rbr, rbi);
    }

    __shared__ float sA_r[8], sA_i[8], sb_r[8], sb_i[8];
    int lane = tid & 31, wid = tid >> 5;
    if (lane == 0) { sA_r[wid] = Ar; sA_i[wid] = Ai; sb_r[wid] = br; sb_i[wid] = bi; }
    __syncthreads();

    if (wid == 0) {
        float aAr = (lane < 8) ? sA_r[lane] : 1.0f;
        float aAi = (lane < 8) ? sA_i[lane] : 0.0f;
        float abr = (lane < 8) ? sb_r[lane] : 0.0f;
        float abi = (lane < 8) ? sb_i[lane] : 0.0f;
#pragma unroll
        for (int off = 1; off < 8; off <<= 1) {
            float rAr = __shfl_down_sync(0xFFFFFFFFu, aAr, off);
            float rAi = __shfl_down_sync(0xFFFFFFFFu, aAi, off);
            float rbr = __shfl_down_sync(0xFFFFFFFFu, abr, off);
            float rbi = __shfl_down_sync(0xFFFFFFFFu, abi, off);
            combine_left(aAr, aAi, abr, abi, rAr, rAi, rbr, rbi);
        }
        if (lane == 0) {
            size_t o = ((size_t)p * NCHUNK + chunk) * 4;
            g_agg[o + 0] = aAr; g_agg[o + 1] = aAi;
            g_agg[o + 2] = abr; g_agg[o + 3] = abi;
        }
    }
}

// ======================== Scan phase B ========================
__global__ __launch_bounds__(32) void chunk_prefix()
{
    const int p = blockIdx.x;
    const int lane = threadIdx.x;

    float Ar = 1.0f, Ai = 0.0f, br = 0.0f, bi = 0.0f;
    if (lane < NCHUNK) {
        size_t o = ((size_t)p * NCHUNK + lane) * 4;
        Ar = g_agg[o + 0]; Ai = g_agg[o + 1];
        br = g_agg[o + 2]; bi = g_agg[o + 3];
    }

#pragma unroll
    for (int off = 1; off < NCHUNK; off <<= 1) {
        float pAr = __shfl_up_sync(0xFFFFFFFFu, Ar, off);
        float pAi = __shfl_up_sync(0xFFFFFFFFu, Ai, off);
        float pbr = __shfl_up_sync(0xFFFFFFFFu, br, off);
        float pbi = __shfl_up_sync(0xFFFFFFFFu, bi, off);
        if (lane >= off) combine_right(Ar, Ai, br, bi, pAr, pAi, pbr, pbi);
    }

    float er = __shfl_up_sync(0xFFFFFFFFu, br, 1);
    float ei = __shfl_up_sync(0xFFFFFFFFu, bi, 1);
    if (lane == 0) { er = 0.0f; ei = 0.0f; }
    if (lane < NCHUNK) {
        size_t q = ((size_t)p * NCHUNK + lane) * 2;
        g_pre[q] = er; g_pre[q + 1] = ei;
    }
}

// ======================== Scan phase C ========================
__global__ __launch_bounds__(SCAN_T) void scan_apply(
    const float* __restrict__ dtv, const float* __restrict__ Lre_g,
    const float* __restrict__ Lim_g, const float* __restrict__ logstep)
{
    const int p = blockIdx.y;
    const int chunk = blockIdx.x;
    const int tid = threadIdx.x;
    const int l0 = chunk * CHUNK + tid * VPT;
    const int lane = tid & 31, wid = tid >> 5;

    const float lre = Lre_g[p], lim = Lim_g[p];
    const float stp = expf(logstep[p]);
    const float* xr = g_x_re + (size_t)p * L_SEQ + l0;
    const float* xi = g_x_im + (size_t)p * L_SEQ + l0;

    float dt[VPT], bvr[VPT], bvi[VPT];
    {
        float4 d0 = *(const float4*)(dtv + l0);
        float4 d1 = *(const float4*)(dtv + l0 + 4);
        dt[0]=d0.x; dt[1]=d0.y; dt[2]=d0.z; dt[3]=d0.w;
        dt[4]=d1.x; dt[5]=d1.y; dt[6]=d1.z; dt[7]=d1.w;
        float4 r0 = *(const float4*)(xr), r1 = *(const float4*)(xr + 4);
        bvr[0]=r0.x; bvr[1]=r0.y; bvr[2]=r0.z; bvr[3]=r0.w;
        bvr[4]=r1.x; bvr[5]=r1.y; bvr[6]=r1.z; bvr[7]=r1.w;
        float4 i0 = *(const float4*)(xi), i1 = *(const float4*)(xi + 4);
        bvi[0]=i0.x; bvi[1]=i0.y; bvi[2]=i0.z; bvi[3]=i0.w;
        bvi[4]=i1.x; bvi[5]=i1.y; bvi[6]=i1.z; bvi[7]=i1.w;
    }

    float IAr[VPT], IAi[VPT], Ibr[VPT], Ibi[VPT];
    {
        float Aer, Aei;
        lambda_bar(lre, lim, dt[0] * stp, Aer, Aei);
        IAr[0] = Aer; IAi[0] = Aei; Ibr[0] = bvr[0]; Ibi[0] = bvi[0];
#pragma unroll
        for (int e = 1; e < VPT; e++) {
            lambda_bar(lre, lim, dt[e] * stp, Aer, Aei);
            IAr[e] = Aer*IAr[e-1] - Aei*IAi[e-1];
            IAi[e] = Aer*IAi[e-1] + Aei*IAr[e-1];
            Ibr[e] = Aer*Ibr[e-1] - Aei*Ibi[e-1] + bvr[e];
            Ibi[e] = Aer*Ibi[e-1] + Aei*Ibr[e-1] + bvi[e];
        }
    }

    float Ar = IAr[VPT-1], Ai = IAi[VPT-1], br = Ibr[VPT-1], bi = Ibi[VPT-1];
#pragma unroll
    for (int off = 1; off < 32; off <<= 1) {
        float pAr = __shfl_up_sync(0xFFFFFFFFu, Ar, off);
        float pAi = __shfl_up_sync(0xFFFFFFFFu, Ai, off);
        float pbr = __shfl_up_sync(0xFFFFFFFFu, br, off);
        float pbi = __shfl_up_sync(0xFFFFFFFFu, bi, off);
        if (lane >= off) combine_right(Ar, Ai, br, bi, pAr, pAi, pbr, pbi);
    }

    float EwAr = __shfl_up_sync(0xFFFFFFFFu, Ar, 1);
    float EwAi = __shfl_up_sync(0xFFFFFFFFu, Ai, 1);
    float Ewbr = __shfl_up_sync(0xFFFFFFFFu, br, 1);
    float Ewbi = __shfl_up_sync(0xFFFFFFFFu, bi, 1);
    if (lane == 0) { EwAr = 1.0f; EwAi = 0.0f; Ewbr = 0.0f; Ewbi = 0.0f; }

    __shared__ float sW[8][4];
    if (lane == 31) { sW[wid][0] = Ar; sW[wid][1] = Ai; sW[wid][2] = br; sW[wid][3] = bi; }
    __syncthreads();

    float PAr = 1.0f, PAi = 0.0f, Pbr = 0.0f, Pbi = 0.0f;
#pragma unroll
    for (int w = 0; w < 7; w++) {
        if (w < wid) {
            float wAr = sW[w][0], wAi = sW[w][1], wbr = sW[w][2], wbi = sW[w][3];
            float nAr = wAr*PAr - wAi*PAi;
            float nAi = wAr*PAi + wAi*PAr;
            float nbr = wAr*Pbr - wAi*Pbi + wbr;
            float nbi = wAr*Pbi + wAi*Pbr + wbi;
            PAr = nAr; PAi = nAi; Pbr = nbr; Pbi = nbi;
        }
    }

    float EAr = EwAr*PAr - EwAi*PAi;
    float EAi = EwAr*PAi + EwAi*PAr;
    float Ebr = EwAr*Pbr - EwAi*Pbi + Ewbr;
    float Ebi = EwAr*Pbi + EwAi*Pbr + Ewbi;

    size_t q = ((size_t)p * NCHUNK + chunk) * 2;
    float pcr = g_pre[q], pci = g_pre[q + 1];
    float xpr = EAr*pcr - EAi*pci + Ebr;
    float xpi = EAr*pci + EAi*pcr + Ebi;

    float o_r[VPT], o_i[VPT];
#pragma unroll
    for (int e = 0; e < VPT; e++) {
        o_r[e] = IAr[e]*xpr - IAi[e]*xpi + Ibr[e];
        o_i[e] = IAr[e]*xpi + IAi[e]*xpr + Ibi[e];
    }
    *(uint4*)(g_xrbf + (size_t)p * L_SEQ + l0) =
        make_uint4(packbf(o_r[0], o_r[1]), packbf(o_r[2], o_r[3]),
                   packbf(o_r[4], o_r[5]), packbf(o_r[6], o_r[7]));
    *(uint4*)(g_xibf + (size_t)p * L_SEQ + l0) =
        make_uint4(packbf(o_i[0], o_i[1]), packbf(o_i[2], o_i[3]),
                   packbf(o_i[4], o_i[5]), packbf(o_i[6], o_i[7]));
}

// ======================== pack_x: build gemm2 A image (pair-packed, perm, im negated) ==========
__global__ __launch_bounds__(256) void pack_x()
{
    int id = blockIdx.x * 256 + threadIdx.x;   // 2 pl x 16 kg x 8192 l4
    int l4 = id & 8191;
    int kg = (id >> 13) & 15;
    int pl = id >> 17;
    const uint16_t* base = (pl ? g_xibf : g_xrbf) + (size_t)(kg * 16) * L_SEQ + l4 * 4;
    const uint32_t neg = pl ? 0x80008000u : 0u;

    ushort4 fe[8], fo[8];
#pragma unroll
    for (int jp = 0; jp < 8; jp++) {
        fe[jp] = *(const ushort4*)(base + (size_t)(2 * jp) * L_SEQ);
        fo[jp] = *(const ushort4*)(base + (size_t)(2 * jp + 1) * L_SEQ);
    }
    uint32_t* dst = g_xp + ((size_t)(pl * 16 + kg) * L_SEQ + l4 * 4) * 8;
#pragma unroll
    for (int li = 0; li < 4; li++) {
        uint32_t row[8];
#pragma unroll
        for (int jp = 0; jp < 8; jp++) {
            uint16_t e = (li == 0) ? fe[jp].x : (li == 1) ? fe[jp].y : (li == 2) ? fe[jp].z : fe[jp].w;
            uint16_t o = (li == 0) ? fo[jp].x : (li == 1) ? fo[jp].y : (li == 2) ? fo[jp].z : fo[jp].w;
            row[kperm(jp)] = (((uint32_t)e) | ((uint32_t)o << 16)) ^ neg;
        }
        *(uint4*)(dst + li * 8)     = make_uint4(row[0], row[1], row[2], row[3]);
        *(uint4*)(dst + li * 8 + 4) = make_uint4(row[4], row[5], row[6], row[7]);
    }
}

// ======================== GEMM2: 256 thr, 2 CTA/SM, 2-stage cp.async ========================
// y = 2*(xre Cre^T - xim Cim^T) + D*u. BM=64 l, BN=256 h, BK=32 p. 8 steps.
// Buffer (words): Ar[0..1023] (2grp x 64 x 8), Ai[1024..2047],
//                 Br[2048..6143] (2grp x 256 x 8), Bi[6144..10239]
#define G2_BUFW 10240
#define G2_SMEM_BYTES (2 * G2_BUFW * 4)   // 81920

__global__ __launch_bounds__(256, 2) void gemm2(
    const float* __restrict__ u, const float* __restrict__ Dg,
    float* __restrict__ out)
{
    extern __shared__ uint32_t sm2[];
    const uint32_t smb = smem_u32(sm2);
    const int tid = threadIdx.x;
    const int wid = tid >> 5, lane = tid & 31;
    const int g = lane >> 2, t = lane & 3;
    const int wm = wid >> 2, wn = wid & 3;        // 2x4 warps, warp tile 32l x 64h
    const int bn = blockIdx.x * 256;
    const int bm = blockIdx.y * 64;

    float acc[2][8][4];
#pragma unroll
    for (int i = 0; i < 2; i++)
#pragma unroll
        for (int j = 0; j < 8; j++)
#pragma unroll
            for (int r = 0; r < 4; r++) acc[i][j][r] = 0.0f;

    auto copy_step = [&](int s, int buf) {
        uint32_t sb = smb + buf * (G2_BUFW * 4);
        int kg = 2 * s;
        // Ar / Ai: 256 chunks each (2grp x 2KB)
        {
            int grp = tid >> 7, off = tid & 127;
            CP_ASYNC16(sb + grp * 2048 + off * 16,
                       (const char*)(g_xp + ((size_t)(kg + grp) * L_SEQ + bm) * 8) + off * 16);
            CP_ASYNC16(sb + 4096 + grp * 2048 + off * 16,
                       (const char*)(g_xp + ((size_t)(16 + kg + grp) * L_SEQ + bm) * 8) + off * 16);
        }
        // Br / Bi: 1024 chunks each (2grp x 8KB)
#pragma unroll
        for (int j = 0; j < 4; j++) {
            int c = tid + j * 256;
            int grp = c >> 9, off = c & 511;
            CP_ASYNC16(sb + 8192 + grp * 8192 + off * 16,
                       (const char*)(g_Cp + ((size_t)(kg + grp) * 512 + bn) * 8) + off * 16);
            CP_ASYNC16(sb + 24576 + grp * 8192 + off * 16,
                       (const char*)(g_Cp + ((size_t)(16 + kg + grp) * 512 + bn) * 8) + off * 16);
        }
    };

    copy_step(0, 0); CP_COMMIT();

    for (int s = 0; s < 8; s++) {
        CP_WAIT0();
        __syncthreads();
        if (s + 1 < 8) { copy_step(s + 1, (s + 1) & 1); CP_COMMIT(); }

        const uint32_t* cur = sm2 + (s & 1) * G2_BUFW;
#pragma unroll
        for (int k16 = 0; k16 < 2; k16++) {
            uint32_t ar[2][4], ai[2][4];
#pragma unroll
            for (int mt = 0; mt < 2; mt++) {
                int row = wm * 32 + mt * 16 + g;
                const uint32_t* pr = cur + k16 * 512 + row * 8 + 2 * t;
                uint2 lo = *(const uint2*)pr;
                uint2 hi = *(const uint2*)(pr + 64);
                ar[mt][0] = lo.x; ar[mt][2] = lo.y; ar[mt][1] = hi.x; ar[mt][3] = hi.y;
                const uint32_t* pi = cur + 1024 + k16 * 512 + row * 8 + 2 * t;
                uint2 lo2 = *(const uint2*)pi;
                uint2 hi2 = *(const uint2*)(pi + 64);
                ai[mt][0] = lo2.x; ai[mt][2] = lo2.y; ai[mt][1] = hi2.x; ai[mt][3] = hi2.y;
            }
#pragma unroll
            for (int nt = 0; nt < 8; nt++) {
                int row = wn * 64 + nt * 8 + g;
                uint2 br = *(const uint2*)(cur + 2048 + k16 * 2048 + row * 8 + 2 * t);
                uint2 bi = *(const uint2*)(cur + 6144 + k16 * 2048 + row * 8 + 2 * t);
#pragma unroll
                for (int mt = 0; mt < 2; mt++) {
                    mma_bf16(acc[mt][nt], ar[mt], br.x, br.y);
                    mma_bf16(acc[mt][nt], ai[mt], bi.x, bi.y);
                }
            }
        }
    }

    // epilogue: y = 2*acc + D*u
#pragma unroll
    for (int mt = 0; mt < 2; mt++) {
#pragma unroll
        for (int rh = 0; rh < 2; rh++) {
            int l = bm + wm * 32 + mt * 16 + g + rh * 8;
#pragma unroll
            for (int nt = 0; nt < 8; nt++) {
                int h0 = bn + wn * 64 + nt * 8 + 2 * t;
                float2 uu = *(const float2*)(u + (size_t)l * H_DIM + h0);
                float2 dd = *(const float2*)(Dg + h0);
                float2 o;
                o.x = 2.0f * acc[mt][nt][rh * 2 + 0] + dd.x * uu.x;
                o.y = 2.0f * acc[mt][nt][rh * 2 + 1] + dd.y * uu.y;
                *(float2*)(out + (size_t)l * H_DIM + h0) = o;
            }
        }
    }
}

// ======================== launch ========================
extern "C" void kernel_launch(void* const* d_in, const int* in_sizes, int n_in,
                              void* d_out, int out_size)
{
    const float* u   = (const float*)d_in[0];  // (L, H)
    const float* dtv = (const float*)d_in[1];  // (L,)
    const float* Lre = (const float*)d_in[2];  // (P,)
    const float* Lim = (const float*)d_in[3];  // (P,)
    const float* Bre = (const float*)d_in[4];  // (P, H)
    const float* Bim = (const float*)d_in[5];  // (P, H)
    const float* Cre = (const float*)d_in[6];  // (H, P)
    const float* Cim = (const float*)d_in[7];  // (H, P)
    const float* Dg  = (const float*)d_in[8];  // (H,)
    const float* lst = (const float*)d_in[9];  // (P,)
    float* out = (float*)d_out;                // (L, H)

    static int attr_done = 0;
    if (!attr_done) {
        cudaFuncSetAttribute(gemm1, cudaFuncAttributeMaxDynamicSharedMemorySize, G1_SMEM_BYTES);
        cudaFuncSetAttribute(gemm2, cudaFuncAttributeMaxDynamicSharedMemorySize, G2_SMEM_BYTES);
        attr_done = 1;
    }

    convert_u_p<<<(32 * L_SEQ) / 256, 256>>>(u);
    convert_B_p<<<dim3(32, 2), 256>>>(Bre, Bim);
    convert_C_p<<<dim3(16, 2), 512>>>(Cre, Cim);
    gemm1<<<dim3(P_DIM / 64, L_SEQ / 128), 256, G1_SMEM_BYTES>>>(dtv, Lre, Lim, lst);
    scan_agg<<<dim3(NCHUNK, P_DIM), SCAN_T>>>(dtv, Lre, Lim, lst);
    chunk_prefix<<<P_DIM, 32>>>();
    scan_apply<<<dim3(NCHUNK, P_DIM), SCAN_T>>>(dtv, Lre, Lim, lst);
    pack_x<<<(2 * 16 * (L_SEQ / 4)) / 256, 256>>>();
    gemm2<<<dim3(H_DIM / 256, L_SEQ / 64), 256, G2_SMEM_BYTES>>>(u, Dg, out);
}

// round 14
// speedup vs baseline: 3.1778x; 1.0370x over previous
#include <cuda_runtime.h>
#include <math.h>
#include <stdint.h>

#define L_SEQ 32768
#define H_DIM 512
#define P_DIM 256
#define VPT 8
#define SCAN_T 256
#define CHUNK (SCAN_T * VPT)        // 2048
#define NCHUNK (L_SEQ / CHUNK)      // 16

// fp32 scratch planes [P][L]: Bu written by gemm1, read by scan.
__device__ float g_x_re[(size_t)P_DIM * L_SEQ];
__device__ float g_x_im[(size_t)P_DIM * L_SEQ];
__device__ float g_agg[P_DIM * NCHUNK * 4];
__device__ float g_pre[P_DIM * NCHUNK * 2];

// pre-permuted bf16 operand images (smem-tile layout: [k16-group][row][8 words])
__device__ uint32_t g_up[(size_t)32 * L_SEQ * 8];        // u:  kg 0..31 (h), row l
__device__ uint32_t g_Bp[2 * 32 * 256 * 8];              // B:  plane, kg (h), row p
__device__ uint32_t g_Cp[2 * 16 * 512 * 8];              // C:  plane, kg (p), row h
// bf16 scanned state planes [P][L] (scan_apply -> pack_x)
__device__ uint16_t g_xrbf[(size_t)P_DIM * L_SEQ];
__device__ uint16_t g_xibf[(size_t)P_DIM * L_SEQ];
// packed gemm2 A image: [plane][kg 0..15][l][8 words], im plane pre-negated
__device__ uint32_t g_xp[(size_t)2 * 16 * L_SEQ * 8];

// ---------------- common helpers ----------------

__device__ __forceinline__ void combine_right(float& Ar, float& Ai, float& br, float& bi,
                                              float pAr, float pAi, float pbr, float pbi)
{
    float nAr = Ar*pAr - Ai*pAi;
    float nAi = Ar*pAi + Ai*pAr;
    float nbr = Ar*pbr - Ai*pbi + br;
    float nbi = Ar*pbi + Ai*pbr + bi;
    Ar = nAr; Ai = nAi; br = nbr; bi = nbi;
}

__device__ __forceinline__ void combine_left(float& Ar, float& Ai, float& br, float& bi,
                                             float rAr, float rAi, float rbr, float rbi)
{
    float nAr = rAr*Ar - rAi*Ai;
    float nAi = rAr*Ai + rAi*Ar;
    float nbr = rAr*br - rAi*bi + rbr;
    float nbi = rAr*bi + rAi*br + rbi;
    Ar = nAr; Ai = nAi; br = nbr; bi = nbi;
}

__device__ __forceinline__ void lambda_bar(float lre, float lim, float Dl, float& Ar, float& Ai)
{
    float e = expf(lre * Dl);
    float s, c;
    sincosf(lim * Dl, &s, &c);
    Ar = e * c;
    Ai = e * s;
}

__device__ __forceinline__ uint32_t packbf(float lo, float hi)
{
    uint32_t r;
    asm("cvt.rn.bf16x2.f32 %0, %1, %2;" : "=r"(r) : "f"(hi), "f"(lo));
    return r;
}

__device__ __forceinline__ void mma_bf16(float* d, const uint32_t* a, uint32_t b0, uint32_t b1)
{
    asm volatile(
        "mma.sync.aligned.m16n8k16.row.col.f32.bf16.bf16.f32 "
        "{%0,%1,%2,%3}, {%4,%5,%6,%7}, {%8,%9}, {%0,%1,%2,%3};"
        : "+f"(d[0]), "+f"(d[1]), "+f"(d[2]), "+f"(d[3])
        : "r"(a[0]), "r"(a[1]), "r"(a[2]), "r"(a[3]), "r"(b0), "r"(b1));
}

__device__ __forceinline__ constexpr int kperm(int w) { return (w < 4) ? (2 * w) : (2 * (w - 4) + 1); }

__device__ __forceinline__ uint32_t smem_u32(const void* p) {
    uint32_t a;
    asm("{ .reg .u64 t; cvta.to.shared.u64 t, %1; cvt.u32.u64 %0, t; }" : "=r"(a) : "l"(p));
    return a;
}

#define CP_ASYNC16(dst, src) \
    asm volatile("cp.async.cg.shared.global [%0], [%1], 16;" :: "r"(dst), "l"(src) : "memory")
#define CP_COMMIT() asm volatile("cp.async.commit_group;" ::: "memory")
#define CP_WAIT1()  asm volatile("cp.async.wait_group 1;" ::: "memory")
#define CP_WAIT0()  asm volatile("cp.async.wait_group 0;" ::: "memory")

// ======================== converters (permuting) ========================
__global__ __launch_bounds__(256) void convert_u_p(const float* __restrict__ u)
{
    int id = blockIdx.x * 256 + threadIdx.x;   // 32 kg x 32768 l
    int kg = id >> 15;
    int l  = id & 32767;
    const float* src = u + (size_t)l * H_DIM + kg * 16;
    float4 v0 = *(const float4*)(src + 0);
    float4 v1 = *(const float4*)(src + 4);
    float4 v2 = *(const float4*)(src + 8);
    float4 v3 = *(const float4*)(src + 12);
    uint32_t w[8];
    w[kperm(0)] = packbf(v0.x, v0.y); w[kperm(1)] = packbf(v0.z, v0.w);
    w[kperm(2)] = packbf(v1.x, v1.y); w[kperm(3)] = packbf(v1.z, v1.w);
    w[kperm(4)] = packbf(v2.x, v2.y); w[kperm(5)] = packbf(v2.z, v2.w);
    w[kperm(6)] = packbf(v3.x, v3.y); w[kperm(7)] = packbf(v3.z, v3.w);
    uint32_t* dst = g_up + ((size_t)kg * L_SEQ + l) * 8;
    *(uint4*)(dst)     = make_uint4(w[0], w[1], w[2], w[3]);
    *(uint4*)(dst + 4) = make_uint4(w[4], w[5], w[6], w[7]);
}

__global__ __launch_bounds__(256) void convert_B_p(
    const float* __restrict__ Bre, const float* __restrict__ Bim)
{
    int kg = blockIdx.x;      // 0..31 (h groups)
    int pl = blockIdx.y;      // 0..1
    int p  = threadIdx.x;     // 0..255
    const float* src = (pl ? Bim : Bre) + (size_t)p * H_DIM + kg * 16;
    float4 v0 = *(const float4*)(src + 0);
    float4 v1 = *(const float4*)(src + 4);
    float4 v2 = *(const float4*)(src + 8);
    float4 v3 = *(const float4*)(src + 12);
    uint32_t w[8];
    w[kperm(0)] = packbf(v0.x, v0.y); w[kperm(1)] = packbf(v0.z, v0.w);
    w[kperm(2)] = packbf(v1.x, v1.y); w[kperm(3)] = packbf(v1.z, v1.w);
    w[kperm(4)] = packbf(v2.x, v2.y); w[kperm(5)] = packbf(v2.z, v2.w);
    w[kperm(6)] = packbf(v3.x, v3.y); w[kperm(7)] = packbf(v3.z, v3.w);
    uint32_t* dst = g_Bp + ((size_t)(pl * 32 + kg) * 256 + p) * 8;
    *(uint4*)(dst)     = make_uint4(w[0], w[1], w[2], w[3]);
    *(uint4*)(dst + 4) = make_uint4(w[4], w[5], w[6], w[7]);
}

__global__ __launch_bounds__(512) void convert_C_p(
    const float* __restrict__ Cre, const float* __restrict__ Cim)
{
    int kg = blockIdx.x;      // 0..15 (p groups)
    int pl = blockIdx.y;
    int h  = threadIdx.x;     // 0..511
    const float* src = (pl ? Cim : Cre) + (size_t)h * P_DIM + kg * 16;
    float4 v0 = *(const float4*)(src + 0);
    float4 v1 = *(const float4*)(src + 4);
    float4 v2 = *(const float4*)(src + 8);
    float4 v3 = *(const float4*)(src + 12);
    uint32_t w[8];
    w[kperm(0)] = packbf(v0.x, v0.y); w[kperm(1)] = packbf(v0.z, v0.w);
    w[kperm(2)] = packbf(v1.x, v1.y); w[kperm(3)] = packbf(v1.z, v1.w);
    w[kperm(4)] = packbf(v2.x, v2.y); w[kperm(5)] = packbf(v2.z, v2.w);
    w[kperm(6)] = packbf(v3.x, v3.y); w[kperm(7)] = packbf(v3.z, v3.w);
    uint32_t* dst = g_Cp + ((size_t)(pl * 16 + kg) * 512 + h) * 8;
    *(uint4*)(dst)     = make_uint4(w[0], w[1], w[2], w[3]);
    *(uint4*)(dst + 4) = make_uint4(w[4], w[5], w[6], w[7]);
}

// ======================== GEMM1: 256 thr, 3 CTA/SM, 3-stage cp.async ========================
// Bu = gamma_bar * (u @ B^T). BM=128 l, BN=32 p, BK=32 h. 16 steps.
// Warp grid 4m x 2n, warp tile 32l x 16p -> 32 acc regs/thread.
// Buffer (words): A[0..2047] (2grp x 128row x 8), Br[2048..2559] (2grp x 32 x 8), Bi[2560..3071]
#define G1_BUFW 3072
#define G1_SMEM_BYTES (3 * G1_BUFW * 4)   // 36864

__global__ __launch_bounds__(256, 3) void gemm1(
    const float* __restrict__ dtv, const float* __restrict__ Lre_g, const float* __restrict__ Lim_g,
    const float* __restrict__ logstep)
{
    extern __shared__ uint32_t sm1[];
    const uint32_t smb = smem_u32(sm1);
    const int tid = threadIdx.x;
    const int wid = tid >> 5, lane = tid & 31;
    const int g = lane >> 2, t = lane & 3;
    const int wm = wid >> 1, wn = wid & 1;     // 4x2 warps, warp tile 32l x 16p
    const int bm = blockIdx.y * 128;
    const int bn = blockIdx.x * 32;

    float accr[2][2][4];
    float acci[2][2][4];
#pragma unroll
    for (int i = 0; i < 2; i++)
#pragma unroll
        for (int j = 0; j < 2; j++)
#pragma unroll
            for (int r = 0; r < 4; r++) { accr[i][j][r] = 0.0f; acci[i][j][r] = 0.0f; }

    auto copy_step = [&](int s, int buf) {
        uint32_t sb = smb + buf * (G1_BUFW * 4);
        int kg = 2 * s;
        // A: 512 chunks (2grp x 4KB)
#pragma unroll
        for (int j = 0; j < 2; j++) {
            int c = tid + j * 256;
            int grp = c >> 8, off = c & 255;
            CP_ASYNC16(sb + grp * 4096 + off * 16,
                       (const char*)(g_up + ((size_t)(kg + grp) * L_SEQ + bm) * 8) + off * 16);
        }
        // Br/Bi: 256 chunks total (each thread one)
        {
            int bsel = tid >> 7, boff = tid & 127;
            int grp = boff >> 6, off = boff & 63;
            CP_ASYNC16(sb + 8192 + bsel * 2048 + grp * 1024 + off * 16,
                       (const char*)(g_Bp + ((size_t)(bsel * 32 + kg + grp) * 256 + bn) * 8) + off * 16);
        }
    };

    copy_step(0, 0); CP_COMMIT();
    copy_step(1, 1); CP_COMMIT();

    for (int s = 0; s < 16; s++) {
        if (s < 15) CP_WAIT1(); else CP_WAIT0();
        __syncthreads();
        if (s + 2 < 16) { copy_step(s + 2, (s + 2) % 3); CP_COMMIT(); }

        const uint32_t* cur = sm1 + (s % 3) * G1_BUFW;
#pragma unroll
        for (int k16 = 0; k16 < 2; k16++) {
            uint32_t a[2][4];
#pragma unroll
            for (int mt = 0; mt < 2; mt++) {
                int row = wm * 32 + mt * 16 + g;
                const uint32_t* p0 = cur + k16 * 1024 + row * 8 + 2 * t;
                uint2 lo = *(const uint2*)p0;
                uint2 hi = *(const uint2*)(p0 + 64);
                a[mt][0] = lo.x; a[mt][2] = lo.y;
                a[mt][1] = hi.x; a[mt][3] = hi.y;
            }
#pragma unroll
            for (int nt = 0; nt < 2; nt++) {
                int row = wn * 16 + nt * 8 + g;
                uint2 br = *(const uint2*)(cur + 2048 + k16 * 256 + row * 8 + 2 * t);
                uint2 bi = *(const uint2*)(cur + 2560 + k16 * 256 + row * 8 + 2 * t);
#pragma unroll
                for (int mt = 0; mt < 2; mt++) {
                    mma_bf16(accr[mt][nt], a[mt], br.x, br.y);
                    mma_bf16(acci[mt][nt], a[mt], bi.x, bi.y);
                }
            }
        }
    }

    // epilogue: gamma_bar multiply, store fp32 Bu to [P][L] planes
    float dts[2][2];
#pragma unroll
    for (int mt = 0; mt < 2; mt++)
#pragma unroll
        for (int rh = 0; rh < 2; rh++)
            dts[mt][rh] = dtv[bm + wm * 32 + mt * 16 + g + rh * 8];

#pragma unroll
    for (int nt = 0; nt < 2; nt++) {
#pragma unroll
        for (int c = 0; c < 2; c++) {
            int p = bn + wn * 16 + nt * 8 + 2 * t + c;
            float lre = Lre_g[p], lim = Lim_g[p];
            float stp = expf(logstep[p]);
            float inv = 1.0f / (lre * lre + lim * lim);
#pragma unroll
            for (int mt = 0; mt < 2; mt++) {
#pragma unroll
                for (int rh = 0; rh < 2; rh++) {
                    int l = bm + wm * 32 + mt * 16 + g + rh * 8;
                    float Dl = dts[mt][rh] * stp;
                    float Ar, Ai;
                    lambda_bar(lre, lim, Dl, Ar, Ai);
                    float gr = ((Ar - 1.0f) * lre + Ai * lim) * inv;
                    float gi = (Ai * lre - (Ar - 1.0f) * lim) * inv;
                    int reg = rh * 2 + c;
                    float ar = accr[mt][nt][reg], ai = acci[mt][nt][reg];
                    size_t o = (size_t)p * L_SEQ + l;
                    g_x_re[o] = gr * ar - gi * ai;
                    g_x_im[o] = gr * ai + gi * ar;
                }
            }
        }
    }
}

// ======================== Scan phase A ========================
__global__ __launch_bounds__(SCAN_T) void scan_agg(
    const float* __restrict__ dtv, const float* __restrict__ Lre_g,
    const float* __restrict__ Lim_g, const float* __restrict__ logstep)
{
    const int p = blockIdx.y;
    const int chunk = blockIdx.x;
    const int tid = threadIdx.x;
    const int l0 = chunk * CHUNK + tid * VPT;

    const float lre = Lre_g[p], lim = Lim_g[p];
    const float stp = expf(logstep[p]);
    const float* xr = g_x_re + (size_t)p * L_SEQ + l0;
    const float* xi = g_x_im + (size_t)p * L_SEQ + l0;

    float dt[VPT], bvr[VPT], bvi[VPT];
    {
        float4 d0 = *(const float4*)(dtv + l0);
        float4 d1 = *(const float4*)(dtv + l0 + 4);
        dt[0]=d0.x; dt[1]=d0.y; dt[2]=d0.z; dt[3]=d0.w;
        dt[4]=d1.x; dt[5]=d1.y; dt[6]=d1.z; dt[7]=d1.w;
        float4 r0 = *(const float4*)(xr), r1 = *(const float4*)(xr + 4);
        bvr[0]=r0.x; bvr[1]=r0.y; bvr[2]=r0.z; bvr[3]=r0.w;
        bvr[4]=r1.x; bvr[5]=r1.y; bvr[6]=r1.z; bvr[7]=r1.w;
        float4 i0 = *(const float4*)(xi), i1 = *(const float4*)(xi + 4);
        bvi[0]=i0.x; bvi[1]=i0.y; bvi[2]=i0.z; bvi[3]=i0.w;
        bvi[4]=i1.x; bvi[5]=i1.y; bvi[6]=i1.z; bvi[7]=i1.w;
    }

    float Ar, Ai, br, bi;
    lambda_bar(lre, lim, dt[0] * stp, Ar, Ai);
    br = bvr[0]; bi = bvi[0];
#pragma unroll
    for (int e = 1; e < VPT; e++) {
        float Aer, Aei;
        lambda_bar(lre, lim, dt[e] * stp, Aer, Aei);
        float nAr = Aer*Ar - Aei*Ai;
        float nAi = Aer*Ai + Aei*Ar;
        float nbr = Aer*br - Aei*bi + bvr[e];
        float nbi = Aer*bi + Aei*br + bvi[e];
        Ar = nAr; Ai = nAi; br = nbr; bi = nbi;
    }

#pragma unroll
    for (int off = 1; off < 32; off <<= 1) {
        float rAr = __shfl_down_sync(0xFFFFFFFFu, Ar, off);
        float rAi = __shfl_down_sync(0xFFFFFFFFu, Ai, off);
        float rbr = __shfl_down_sync(0xFFFFFFFFu, br, off);
        float rbi = __shfl_down_sync(0xFFFFFFFFu, bi, off);
        combine_left(Ar, Ai, br, bi, rAr, rAi, rbr, rbi);
    }

    __shared__ float sA_r[8], sA_i[8], sb_r[8], sb_i[8];
    int lane = tid & 31, wid = tid >> 5;
    if (lane == 0) { sA_r[wid] = Ar; sA_i[wid] = Ai; sb_r[wid] = br; sb_i[wid] = bi; }
    __syncthreads();

    if (wid == 0) {
        float aAr = (lane < 8) ? sA_r[lane] : 1.0f;
        float aAi = (lane < 8) ? sA_i[lane] : 0.0f;
        float abr = (lane < 8) ? sb_r[lane] : 0.0f;
        float abi = (lane < 8) ? sb_i[lane] : 0.0f;
#pragma unroll
        for (int off = 1; off < 8; off <<= 1) {
            float rAr = __shfl_down_sync(0xFFFFFFFFu, aAr, off);
            float rAi = __shfl_down_sync(0xFFFFFFFFu, aAi, off);
            float rbr = __shfl_down_sync(0xFFFFFFFFu, abr, off);
            float rbi = __shfl_down_sync(0xFFFFFFFFu, abi, off);
            combine_left(aAr, aAi, abr, abi, rAr, rAi, rbr, rbi);
        }
        if (lane == 0) {
            size_t o = ((size_t)p * NCHUNK + chunk) * 4;
            g_agg[o + 0] = aAr; g_agg[o + 1] = aAi;
            g_agg[o + 2] = abr; g_agg[o + 3] = abi;
        }
    }
}

// ======================== Scan phase B ========================
__global__ __launch_bounds__(32) void chunk_prefix()
{
    const int p = blockIdx.x;
    const int lane = threadIdx.x;

    float Ar = 1.0f, Ai = 0.0f, br = 0.0f, bi = 0.0f;
    if (lane < NCHUNK) {
        size_t o = ((size_t)p * NCHUNK + lane) * 4;
        Ar = g_agg[o + 0]; Ai = g_agg[o + 1];
        br = g_agg[o + 2]; bi = g_agg[o + 3];
    }

#pragma unroll
    for (int off = 1; off < NCHUNK; off <<= 1) {
        float pAr = __shfl_up_sync(0xFFFFFFFFu, Ar, off);
        float pAi = __shfl_up_sync(0xFFFFFFFFu, Ai, off);
        float pbr = __shfl_up_sync(0xFFFFFFFFu, br, off);
        float pbi = __shfl_up_sync(0xFFFFFFFFu, bi, off);
        if (lane >= off) combine_right(Ar, Ai, br, bi, pAr, pAi, pbr, pbi);
    }

    float er = __shfl_up_sync(0xFFFFFFFFu, br, 1);
    float ei = __shfl_up_sync(0xFFFFFFFFu, bi, 1);
    if (lane == 0) { er = 0.0f; ei = 0.0f; }
    if (lane < NCHUNK) {
        size_t q = ((size_t)p * NCHUNK + lane) * 2;
        g_pre[q] = er; g_pre[q + 1] = ei;
    }
}

// ======================== Scan phase C ========================
__global__ __launch_bounds__(SCAN_T) void scan_apply(
    const float* __restrict__ dtv, const float* __restrict__ Lre_g,
    const float* __restrict__ Lim_g, const float* __restrict__ logstep)
{
    const int p = blockIdx.y;
    const int chunk = blockIdx.x;
    const int tid = threadIdx.x;
    const int l0 = chunk * CHUNK + tid * VPT;
    const int lane = tid & 31, wid = tid >> 5;

    const float lre = Lre_g[p], lim = Lim_g[p];
    const float stp = expf(logstep[p]);
    const float* xr = g_x_re + (size_t)p * L_SEQ + l0;
    const float* xi = g_x_im + (size_t)p * L_SEQ + l0;

    float dt[VPT], bvr[VPT], bvi[VPT];
    {
        float4 d0 = *(const float4*)(dtv + l0);
        float4 d1 = *(const float4*)(dtv + l0 + 4);
        dt[0]=d0.x; dt[1]=d0.y; dt[2]=d0.z; dt[3]=d0.w;
        dt[4]=d1.x; dt[5]=d1.y; dt[6]=d1.z; dt[7]=d1.w;
        float4 r0 = *(const float4*)(xr), r1 = *(const float4*)(xr + 4);
        bvr[0]=r0.x; bvr[1]=r0.y; bvr[2]=r0.z; bvr[3]=r0.w;
        bvr[4]=r1.x; bvr[5]=r1.y; bvr[6]=r1.z; bvr[7]=r1.w;
        float4 i0 = *(const float4*)(xi), i1 = *(const float4*)(xi + 4);
        bvi[0]=i0.x; bvi[1]=i0.y; bvi[2]=i0.z; bvi[3]=i0.w;
        bvi[4]=i1.x; bvi[5]=i1.y; bvi[6]=i1.z; bvi[7]=i1.w;
    }

    float IAr[VPT], IAi[VPT], Ibr[VPT], Ibi[VPT];
    {
        float Aer, Aei;
        lambda_bar(lre, lim, dt[0] * stp, Aer, Aei);
        IAr[0] = Aer; IAi[0] = Aei; Ibr[0] = bvr[0]; Ibi[0] = bvi[0];
#pragma unroll
        for (int e = 1; e < VPT; e++) {
            lambda_bar(lre, lim, dt[e] * stp, Aer, Aei);
            IAr[e] = Aer*IAr[e-1] - Aei*IAi[e-1];
            IAi[e] = Aer*IAi[e-1] + Aei*IAr[e-1];
            Ibr[e] = Aer*Ibr[e-1] - Aei*Ibi[e-1] + bvr[e];
            Ibi[e] = Aer*Ibi[e-1] + Aei*Ibr[e-1] + bvi[e];
        }
    }

    float Ar = IAr[VPT-1], Ai = IAi[VPT-1], br = Ibr[VPT-1], bi = Ibi[VPT-1];
#pragma unroll
    for (int off = 1; off < 32; off <<= 1) {
        float pAr = __shfl_up_sync(0xFFFFFFFFu, Ar, off);
        float pAi = __shfl_up_sync(0xFFFFFFFFu, Ai, off);
        float pbr = __shfl_up_sync(0xFFFFFFFFu, br, off);
        float pbi = __shfl_up_sync(0xFFFFFFFFu, bi, off);
        if (lane >= off) combine_right(Ar, Ai, br, bi, pAr, pAi, pbr, pbi);
    }

    float EwAr = __shfl_up_sync(0xFFFFFFFFu, Ar, 1);
    float EwAi = __shfl_up_sync(0xFFFFFFFFu, Ai, 1);
    float Ewbr = __shfl_up_sync(0xFFFFFFFFu, br, 1);
    float Ewbi = __shfl_up_sync(0xFFFFFFFFu, bi, 1);
    if (lane == 0) { EwAr = 1.0f; EwAi = 0.0f; Ewbr = 0.0f; Ewbi = 0.0f; }

    __shared__ float sW[8][4];
    if (lane == 31) { sW[wid][0] = Ar; sW[wid][1] = Ai; sW[wid][2] = br; sW[wid][3] = bi; }
    __syncthreads();

    float PAr = 1.0f, PAi = 0.0f, Pbr = 0.0f, Pbi = 0.0f;
#pragma unroll
    for (int w = 0; w < 7; w++) {
        if (w < wid) {
            float wAr = sW[w][0], wAi = sW[w][1], wbr = sW[w][2], wbi = sW[w][3];
            float nAr = wAr*PAr - wAi*PAi;
            float nAi = wAr*PAi + wAi*PAr;
            float nbr = wAr*Pbr - wAi*Pbi + wbr;
            float nbi = wAr*Pbi + wAi*Pbr + wbi;
            PAr = nAr; PAi = nAi; Pbr = nbr; Pbi = nbi;
        }
    }

    float EAr = EwAr*PAr - EwAi*PAi;
    float EAi = EwAr*PAi + EwAi*PAr;
    float Ebr = EwAr*Pbr - EwAi*Pbi + Ewbr;
    float Ebi = EwAr*Pbi + EwAi*Pbr + Ewbi;

    size_t q = ((size_t)p * NCHUNK + chunk) * 2;
    float pcr = g_pre[q], pci = g_pre[q + 1];
    float xpr = EAr*pcr - EAi*pci + Ebr;
    float xpi = EAr*pci + EAi*pcr + Ebi;

    float o_r[VPT], o_i[VPT];
#pragma unroll
    for (int e = 0; e < VPT; e++) {
        o_r[e] = IAr[e]*xpr - IAi[e]*xpi + Ibr[e];
        o_i[e] = IAr[e]*xpi + IAi[e]*xpr + Ibi[e];
    }
    *(uint4*)(g_xrbf + (size_t)p * L_SEQ + l0) =
        make_uint4(packbf(o_r[0], o_r[1]), packbf(o_r[2], o_r[3]),
                   packbf(o_r[4], o_r[5]), packbf(o_r[6], o_r[7]));
    *(uint4*)(g_xibf + (size_t)p * L_SEQ + l0) =
        make_uint4(packbf(o_i[0], o_i[1]), packbf(o_i[2], o_i[3]),
                   packbf(o_i[4], o_i[5]), packbf(o_i[6], o_i[7]));
}

// ======================== pack_x: build gemm2 A image (pair-packed, perm, im negated) ==========
__global__ __launch_bounds__(256) void pack_x()
{
    int id = blockIdx.x * 256 + threadIdx.x;   // 2 pl x 16 kg x 8192 l4
    int l4 = id & 8191;
    int kg = (id >> 13) & 15;
    int pl = id >> 17;
    const uint16_t* base = (pl ? g_xibf : g_xrbf) + (size_t)(kg * 16) * L_SEQ + l4 * 4;
    const uint32_t neg = pl ? 0x80008000u : 0u;

    ushort4 fe[8], fo[8];
#pragma unroll
    for (int jp = 0; jp < 8; jp++) {
        fe[jp] = *(const ushort4*)(base + (size_t)(2 * jp) * L_SEQ);
        fo[jp] = *(const ushort4*)(base + (size_t)(2 * jp + 1) * L_SEQ);
    }
    uint32_t* dst = g_xp + ((size_t)(pl * 16 + kg) * L_SEQ + l4 * 4) * 8;
#pragma unroll
    for (int li = 0; li < 4; li++) {
        uint32_t row[8];
#pragma unroll
        for (int jp = 0; jp < 8; jp++) {
            uint16_t e = (li == 0) ? fe[jp].x : (li == 1) ? fe[jp].y : (li == 2) ? fe[jp].z : fe[jp].w;
            uint16_t o = (li == 0) ? fo[jp].x : (li == 1) ? fo[jp].y : (li == 2) ? fo[jp].z : fo[jp].w;
            row[kperm(jp)] = (((uint32_t)e) | ((uint32_t)o << 16)) ^ neg;
        }
        *(uint4*)(dst + li * 8)     = make_uint4(row[0], row[1], row[2], row[3]);
        *(uint4*)(dst + li * 8 + 4) = make_uint4(row[4], row[5], row[6], row[7]);
    }
}

// ======================== GEMM2: 256 thr, 3 CTA/SM, 3-stage cp.async ========================
// y = 2*(xre Cre^T - xim Cim^T) + D*u. BM=64 l, BN=128 h, BK=32 p. 8 steps.
// Warp grid 2m x 4n, warp tile 32l x 32h -> 32 acc regs/thread.
// Buffer (words): Ar[0..1023] (2grp x 64 x 8), Ai[1024..2047],
//                 Br[2048..4095] (2grp x 128 x 8), Bi[4096..6143]
#define G2_BUFW 6144
#define G2_SMEM_BYTES (3 * G2_BUFW * 4)   // 73728

__global__ __launch_bounds__(256, 3) void gemm2(
    const float* __restrict__ u, const float* __restrict__ Dg,
    float* __restrict__ out)
{
    extern __shared__ uint32_t sm2[];
    const uint32_t smb = smem_u32(sm2);
    const int tid = threadIdx.x;
    const int wid = tid >> 5, lane = tid & 31;
    const int g = lane >> 2, t = lane & 3;
    const int wm = wid >> 2, wn = wid & 3;        // 2x4 warps, warp tile 32l x 32h
    const int bn = blockIdx.x * 128;
    const int bm = blockIdx.y * 64;

    float acc[2][4][4];
#pragma unroll
    for (int i = 0; i < 2; i++)
#pragma unroll
        for (int j = 0; j < 4; j++)
#pragma unroll
            for (int r = 0; r < 4; r++) acc[i][j][r] = 0.0f;

    auto copy_step = [&](int s, int buf) {
        uint32_t sb = smb + buf * (G2_BUFW * 4);
        int kg = 2 * s;
        // A: 512 chunks (Ar 256, Ai 256)
#pragma unroll
        for (int j = 0; j < 2; j++) {
            int c = tid + j * 256;
            int sel = c >> 8, cc = c & 255;
            int grp = cc >> 7, off = cc & 127;
            CP_ASYNC16(sb + sel * 4096 + grp * 2048 + off * 16,
                       (const char*)(g_xp + ((size_t)(sel * 16 + kg + grp) * L_SEQ + bm) * 8) + off * 16);
        }
        // B: 1024 chunks (Br 512, Bi 512)
#pragma unroll
        for (int j = 0; j < 4; j++) {
            int c = tid + j * 256;
            int sel = c >> 9, cc = c & 511;
            int grp = cc >> 8, off = cc & 255;
            CP_ASYNC16(sb + 8192 + sel * 8192 + grp * 4096 + off * 16,
                       (const char*)(g_Cp + ((size_t)(sel * 16 + kg + grp) * 512 + bn) * 8) + off * 16);
        }
    };

    copy_step(0, 0); CP_COMMIT();
    copy_step(1, 1); CP_COMMIT();

    for (int s = 0; s < 8; s++) {
        if (s < 7) CP_WAIT1(); else CP_WAIT0();
        __syncthreads();
        if (s + 2 < 8) { copy_step(s + 2, (s + 2) % 3); CP_COMMIT(); }

        const uint32_t* cur = sm2 + (s % 3) * G2_BUFW;
#pragma unroll
        for (int k16 = 0; k16 < 2; k16++) {
            uint32_t ar[2][4], ai[2][4];
#pragma unroll
            for (int mt = 0; mt < 2; mt++) {
                int row = wm * 32 + mt * 16 + g;
                const uint32_t* pr = cur + k16 * 512 + row * 8 + 2 * t;
                uint2 lo = *(const uint2*)pr;
                uint2 hi = *(const uint2*)(pr + 64);
                ar[mt][0] = lo.x; ar[mt][2] = lo.y; ar[mt][1] = hi.x; ar[mt][3] = hi.y;
                const uint32_t* pi = cur + 1024 + k16 * 512 + row * 8 + 2 * t;
                uint2 lo2 = *(const uint2*)pi;
                uint2 hi2 = *(const uint2*)(pi + 64);
                ai[mt][0] = lo2.x; ai[mt][2] = lo2.y; ai[mt][1] = hi2.x; ai[mt][3] = hi2.y;
            }
#pragma unroll
            for (int nt = 0; nt < 4; nt++) {
                int row = wn * 32 + nt * 8 + g;
                uint2 br = *(const uint2*)(cur + 2048 + k16 * 1024 + row * 8 + 2 * t);
                uint2 bi = *(const uint2*)(cur + 4096 + k16 * 1024 + row * 8 + 2 * t);
#pragma unroll
                for (int mt = 0; mt < 2; mt++) {
                    mma_bf16(acc[mt][nt], ar[mt], br.x, br.y);
                    mma_bf16(acc[mt][nt], ai[mt], bi.x, bi.y);
                }
            }
        }
    }

    // epilogue: y = 2*acc + D*u
#pragma unroll
    for (int mt = 0; mt < 2; mt++) {
#pragma unroll
        for (int rh = 0; rh < 2; rh++) {
            int l = bm + wm * 32 + mt * 16 + g + rh * 8;
#pragma unroll
            for (int nt = 0; nt < 4; nt++) {
                int h0 = bn + wn * 32 + nt * 8 + 2 * t;
                float2 uu = *(const float2*)(u + (size_t)l * H_DIM + h0);
                float2 dd = *(const float2*)(Dg + h0);
                float2 o;
                o.x = 2.0f * acc[mt][nt][rh * 2 + 0] + dd.x * uu.x;
                o.y = 2.0f * acc[mt][nt][rh * 2 + 1] + dd.y * uu.y;
                *(float2*)(out + (size_t)l * H_DIM + h0) = o;
            }
        }
    }
}

// ======================== launch ========================
extern "C" void kernel_launch(void* const* d_in, const int* in_sizes, int n_in,
                              void* d_out, int out_size)
{
    const float* u   = (const float*)d_in[0];  // (L, H)
    const float* dtv = (const float*)d_in[1];  // (L,)
    const float* Lre = (const float*)d_in[2];  // (P,)
    const float* Lim = (const float*)d_in[3];  // (P,)
    const float* Bre = (const float*)d_in[4];  // (P, H)
    const float* Bim = (const float*)d_in[5];  // (P, H)
    const float* Cre = (const float*)d_in[6];  // (H, P)
    const float* Cim = (const float*)d_in[7];  // (H, P)
    const float* Dg  = (const float*)d_in[8];  // (H,)
    const float* lst = (const float*)d_in[9];  // (P,)
    float* out = (float*)d_out;                // (L, H)

    static int attr_done = 0;
    if (!attr_done) {
        cudaFuncSetAttribute(gemm1, cudaFuncAttributeMaxDynamicSharedMemorySize, G1_SMEM_BYTES);
        cudaFuncSetAttribute(gemm2, cudaFuncAttributeMaxDynamicSharedMemorySize, G2_SMEM_BYTES);
        attr_done = 1;
    }

    convert_u_p<<<(32 * L_SEQ) / 256, 256>>>(u);
    convert_B_p<<<dim3(32, 2), 256>>>(Bre, Bim);
    convert_C_p<<<dim3(16, 2), 512>>>(Cre, Cim);
    gemm1<<<dim3(P_DIM / 32, L_SEQ / 128), 256, G1_SMEM_BYTES>>>(dtv, Lre, Lim, lst);
    scan_agg<<<dim3(NCHUNK, P_DIM), SCAN_T>>>(dtv, Lre, Lim, lst);
    chunk_prefix<<<P_DIM, 32>>>();
    scan_apply<<<dim3(NCHUNK, P_DIM), SCAN_T>>>(dtv, Lre, Lim, lst);
    pack_x<<<(2 * 16 * (L_SEQ / 4)) / 256, 256>>>();
    gemm2<<<dim3(H_DIM / 128, L_SEQ / 64), 256, G2_SMEM_BYTES>>>(u, Dg, out);
}

// round 15
// speedup vs baseline: 3.4595x; 1.0886x over previous
#include <cuda_runtime.h>
#include <math.h>
#include <stdint.h>

#define L_SEQ 32768
#define H_DIM 512
#define P_DIM 256
#define VPT 8
#define SCAN_T 256
#define CHUNK (SCAN_T * VPT)        // 2048
#define NCHUNK (L_SEQ / CHUNK)      // 16

// fp32 scratch planes [P][L]: Bu written by gemm1, read by scan.
__device__ float g_x_re[(size_t)P_DIM * L_SEQ];
__device__ float g_x_im[(size_t)P_DIM * L_SEQ];
__device__ float g_agg[P_DIM * NCHUNK * 4];
__device__ float g_pre[P_DIM * NCHUNK * 2];

// pre-converted bf16 operand images, NATURAL word order: [k16-group][row][8 words]
__device__ uint32_t g_up[(size_t)32 * L_SEQ * 8];        // u:  kg 0..31 (h), row l
__device__ uint32_t g_Bp[2 * 32 * 256 * 8];              // B:  plane, kg (h), row p
__device__ uint32_t g_Cp[2 * 16 * 512 * 8];              // C:  plane, kg (p), row h
// bf16 scanned state planes [P][L] (scan_apply -> pack_x)
__device__ uint16_t g_xrbf[(size_t)P_DIM * L_SEQ];
__device__ uint16_t g_xibf[(size_t)P_DIM * L_SEQ];
// packed gemm2 A image: [plane][kg 0..15][l][8 words], im plane pre-negated
__device__ uint32_t g_xp[(size_t)2 * 16 * L_SEQ * 8];

// ---------------- common helpers ----------------

__device__ __forceinline__ void combine_right(float& Ar, float& Ai, float& br, float& bi,
                                              float pAr, float pAi, float pbr, float pbi)
{
    float nAr = Ar*pAr - Ai*pAi;
    float nAi = Ar*pAi + Ai*pAr;
    float nbr = Ar*pbr - Ai*pbi + br;
    float nbi = Ar*pbi + Ai*pbr + bi;
    Ar = nAr; Ai = nAi; br = nbr; bi = nbi;
}

__device__ __forceinline__ void combine_left(float& Ar, float& Ai, float& br, float& bi,
                                             float rAr, float rAi, float rbr, float rbi)
{
    float nAr = rAr*Ar - rAi*Ai;
    float nAi = rAr*Ai + rAi*Ar;
    float nbr = rAr*br - rAi*bi + rbr;
    float nbi = rAr*bi + rAi*br + rbi;
    Ar = nAr; Ai = nAi; br = nbr; bi = nbi;
}

__device__ __forceinline__ void lambda_bar(float lre, float lim, float Dl, float& Ar, float& Ai)
{
    float e = expf(lre * Dl);
    float s, c;
    sincosf(lim * Dl, &s, &c);
    Ar = e * c;
    Ai = e * s;
}

__device__ __forceinline__ uint32_t packbf(float lo, float hi)
{
    uint32_t r;
    asm("cvt.rn.bf16x2.f32 %0, %1, %2;" : "=r"(r) : "f"(hi), "f"(lo));
    return r;
}

__device__ __forceinline__ void mma_bf16(float* d, const uint32_t* a, uint32_t b0, uint32_t b1)
{
    asm volatile(
        "mma.sync.aligned.m16n8k16.row.col.f32.bf16.bf16.f32 "
        "{%0,%1,%2,%3}, {%4,%5,%6,%7}, {%8,%9}, {%0,%1,%2,%3};"
        : "+f"(d[0]), "+f"(d[1]), "+f"(d[2]), "+f"(d[3])
        : "r"(a[0]), "r"(a[1]), "r"(a[2]), "r"(a[3]), "r"(b0), "r"(b1));
}

#define LDSM_X4(r0, r1, r2, r3, addr) \
    asm volatile("ldmatrix.sync.aligned.m8n8.x4.shared.b16 {%0,%1,%2,%3}, [%4];" \
                 : "=r"(r0), "=r"(r1), "=r"(r2), "=r"(r3) : "r"(addr))

__device__ __forceinline__ uint32_t smem_u32(const void* p) {
    uint32_t a;
    asm("{ .reg .u64 t; cvta.to.shared.u64 t, %1; cvt.u32.u64 %0, t; }" : "=r"(a) : "l"(p));
    return a;
}

// byte offset of (row, k-half) within a kg region; 16B-granule XOR swizzle
__device__ __forceinline__ uint32_t swz(int row, int half)
{
    return (uint32_t)(row * 32 + ((half ^ ((row >> 2) & 1)) << 4));
}

#define CP_ASYNC16(dst, src) \
    asm volatile("cp.async.cg.shared.global [%0], [%1], 16;" :: "r"(dst), "l"(src) : "memory")
#define CP_COMMIT() asm volatile("cp.async.commit_group;" ::: "memory")
#define CP_WAIT1()  asm volatile("cp.async.wait_group 1;" ::: "memory")
#define CP_WAIT0()  asm volatile("cp.async.wait_group 0;" ::: "memory")

// chunk-index swizzle (chunk = row*2 + half)
__device__ __forceinline__ int cswz(int c) { return c ^ ((c >> 3) & 1); }

// ======================== converters (natural word order) ========================
__global__ __launch_bounds__(256) void convert_u_p(const float* __restrict__ u)
{
    int id = blockIdx.x * 256 + threadIdx.x;   // 32 kg x 32768 l
    int kg = id >> 15;
    int l  = id & 32767;
    const float* src = u + (size_t)l * H_DIM + kg * 16;
    float4 v0 = *(const float4*)(src + 0);
    float4 v1 = *(const float4*)(src + 4);
    float4 v2 = *(const float4*)(src + 8);
    float4 v3 = *(const float4*)(src + 12);
    uint32_t* dst = g_up + ((size_t)kg * L_SEQ + l) * 8;
    *(uint4*)(dst)     = make_uint4(packbf(v0.x, v0.y), packbf(v0.z, v0.w),
                                    packbf(v1.x, v1.y), packbf(v1.z, v1.w));
    *(uint4*)(dst + 4) = make_uint4(packbf(v2.x, v2.y), packbf(v2.z, v2.w),
                                    packbf(v3.x, v3.y), packbf(v3.z, v3.w));
}

__global__ __launch_bounds__(256) void convert_B_p(
    const float* __restrict__ Bre, const float* __restrict__ Bim)
{
    int kg = blockIdx.x;      // 0..31 (h groups)
    int pl = blockIdx.y;      // 0..1
    int p  = threadIdx.x;     // 0..255
    const float* src = (pl ? Bim : Bre) + (size_t)p * H_DIM + kg * 16;
    float4 v0 = *(const float4*)(src + 0);
    float4 v1 = *(const float4*)(src + 4);
    float4 v2 = *(const float4*)(src + 8);
    float4 v3 = *(const float4*)(src + 12);
    uint32_t* dst = g_Bp + ((size_t)(pl * 32 + kg) * 256 + p) * 8;
    *(uint4*)(dst)     = make_uint4(packbf(v0.x, v0.y), packbf(v0.z, v0.w),
                                    packbf(v1.x, v1.y), packbf(v1.z, v1.w));
    *(uint4*)(dst + 4) = make_uint4(packbf(v2.x, v2.y), packbf(v2.z, v2.w),
                                    packbf(v3.x, v3.y), packbf(v3.z, v3.w));
}

__global__ __launch_bounds__(512) void convert_C_p(
    const float* __restrict__ Cre, const float* __restrict__ Cim)
{
    int kg = blockIdx.x;      // 0..15 (p groups)
    int pl = blockIdx.y;
    int h  = threadIdx.x;     // 0..511
    const float* src = (pl ? Cim : Cre) + (size_t)h * P_DIM + kg * 16;
    float4 v0 = *(const float4*)(src + 0);
    float4 v1 = *(const float4*)(src + 4);
    float4 v2 = *(const float4*)(src + 8);
    float4 v3 = *(const float4*)(src + 12);
    uint32_t* dst = g_Cp + ((size_t)(pl * 16 + kg) * 512 + h) * 8;
    *(uint4*)(dst)     = make_uint4(packbf(v0.x, v0.y), packbf(v0.z, v0.w),
                                    packbf(v1.x, v1.y), packbf(v1.z, v1.w));
    *(uint4*)(dst + 4) = make_uint4(packbf(v2.x, v2.y), packbf(v2.z, v2.w),
                                    packbf(v3.x, v3.y), packbf(v3.z, v3.w));
}

// ======================== GEMM1: 256 thr, 3 CTA/SM, 3-stage cp.async + ldmatrix ===============
// Bu = gamma_bar * (u @ B^T). BM=128 l, BN=32 p, BK=32 h. 16 steps.
// Warp grid 4m x 2n, warp tile 32l x 16p.
// Buffer bytes: A[0..8191] (2kg x 128row x 32B), Br[8192..10239], Bi[10240..12287]
#define G1_BUFB 12288
#define G1_SMEM_BYTES (3 * G1_BUFB)   // 36864

__global__ __launch_bounds__(256, 3) void gemm1(
    const float* __restrict__ dtv, const float* __restrict__ Lre_g, const float* __restrict__ Lim_g,
    const float* __restrict__ logstep)
{
    extern __shared__ uint32_t sm1[];
    const uint32_t smb = smem_u32(sm1);
    const int tid = threadIdx.x;
    const int wid = tid >> 5, lane = tid & 31;
    const int g = lane >> 2, t = lane & 3;
    const int wm = wid >> 1, wn = wid & 1;     // 4x2 warps, warp tile 32l x 16p
    const int bm = blockIdx.y * 128;
    const int bn = blockIdx.x * 32;

    // ldmatrix per-thread address offsets
    const int qr = lane & 7, sel = lane >> 3;   // sel 0..3
    // A x4 (per mt): r0=(m0,h0) r1=(m8,h0) r2=(m0,h1) r3=(m8,h1)
    const uint32_t aoff0 = swz(wm * 32 + 0 * 16 + (sel & 1) * 8 + qr, sel >> 1);
    const uint32_t aoff1 = swz(wm * 32 + 1 * 16 + (sel & 1) * 8 + qr, sel >> 1);
    // B x4 (2 n-tiles): r0=(nt0,h0) r1=(nt0,h1) r2=(nt1,h0) r3=(nt1,h1)
    const uint32_t boff  = swz(wn * 16 + (sel >> 1) * 8 + qr, sel & 1);

    float accr[2][2][4];
    float acci[2][2][4];
#pragma unroll
    for (int i = 0; i < 2; i++)
#pragma unroll
        for (int j = 0; j < 2; j++)
#pragma unroll
            for (int r = 0; r < 4; r++) { accr[i][j][r] = 0.0f; acci[i][j][r] = 0.0f; }

    auto copy_step = [&](int s, int buf) {
        uint32_t sb = smb + buf * G1_BUFB;
        int kg = 2 * s;
        // A: 512 chunks (2kg x 4KB)
#pragma unroll
        for (int j = 0; j < 2; j++) {
            int c = tid + j * 256;
            int grp = c >> 8, off = c & 255;
            CP_ASYNC16(sb + grp * 4096 + cswz(off) * 16,
                       (const char*)(g_up + ((size_t)(kg + grp) * L_SEQ + bm) * 8) + off * 16);
        }
        // Br/Bi: 256 chunks total
        {
            int bsel = tid >> 7, boff2 = tid & 127;
            int grp = boff2 >> 6, off = boff2 & 63;
            CP_ASYNC16(sb + 8192 + bsel * 2048 + grp * 1024 + cswz(off) * 16,
                       (const char*)(g_Bp + ((size_t)(bsel * 32 + kg + grp) * 256 + bn) * 8) + off * 16);
        }
    };

    copy_step(0, 0); CP_COMMIT();
    copy_step(1, 1); CP_COMMIT();

    for (int s = 0; s < 16; s++) {
        if (s < 15) CP_WAIT1(); else CP_WAIT0();
        __syncthreads();
        if (s + 2 < 16) { copy_step(s + 2, (s + 2) % 3); CP_COMMIT(); }

        const uint32_t curb = smb + (s % 3) * G1_BUFB;
#pragma unroll
        for (int k16 = 0; k16 < 2; k16++) {
            uint32_t a[2][4];
            LDSM_X4(a[0][0], a[0][1], a[0][2], a[0][3], curb + k16 * 4096 + aoff0);
            LDSM_X4(a[1][0], a[1][1], a[1][2], a[1][3], curb + k16 * 4096 + aoff1);
            uint32_t brg[4], big[4];
            uint32_t bb = curb + 8192 + k16 * 1024 + boff;
            LDSM_X4(brg[0], brg[1], brg[2], brg[3], bb);
            LDSM_X4(big[0], big[1], big[2], big[3], bb + 2048);
#pragma unroll
            for (int nt = 0; nt < 2; nt++) {
#pragma unroll
                for (int mt = 0; mt < 2; mt++) {
                    mma_bf16(accr[mt][nt], a[mt], brg[nt * 2], brg[nt * 2 + 1]);
                    mma_bf16(acci[mt][nt], a[mt], big[nt * 2], big[nt * 2 + 1]);
                }
            }
        }
    }

    // epilogue: gamma_bar multiply, store fp32 Bu to [P][L] planes
    float dts[2][2];
#pragma unroll
    for (int mt = 0; mt < 2; mt++)
#pragma unroll
        for (int rh = 0; rh < 2; rh++)
            dts[mt][rh] = dtv[bm + wm * 32 + mt * 16 + g + rh * 8];

#pragma unroll
    for (int nt = 0; nt < 2; nt++) {
#pragma unroll
        for (int c = 0; c < 2; c++) {
            int p = bn + wn * 16 + nt * 8 + 2 * t + c;
            float lre = Lre_g[p], lim = Lim_g[p];
            float stp = expf(logstep[p]);
            float inv = 1.0f / (lre * lre + lim * lim);
#pragma unroll
            for (int mt = 0; mt < 2; mt++) {
#pragma unroll
                for (int rh = 0; rh < 2; rh++) {
                    int l = bm + wm * 32 + mt * 16 + g + rh * 8;
                    float Dl = dts[mt][rh] * stp;
                    float Ar, Ai;
                    lambda_bar(lre, lim, Dl, Ar, Ai);
                    float gr = ((Ar - 1.0f) * lre + Ai * lim) * inv;
                    float gi = (Ai * lre - (Ar - 1.0f) * lim) * inv;
                    int reg = rh * 2 + c;
                    float ar = accr[mt][nt][reg], ai = acci[mt][nt][reg];
                    size_t o = (size_t)p * L_SEQ + l;
                    g_x_re[o] = gr * ar - gi * ai;
                    g_x_im[o] = gr * ai + gi * ar;
                }
            }
        }
    }
}

// ======================== Scan phase A ========================
__global__ __launch_bounds__(SCAN_T) void scan_agg(
    const float* __restrict__ dtv, const float* __restrict__ Lre_g,
    const float* __restrict__ Lim_g, const float* __restrict__ logstep)
{
    const int p = blockIdx.y;
    const int chunk = blockIdx.x;
    const int tid = threadIdx.x;
    const int l0 = chunk * CHUNK + tid * VPT;

    const float lre = Lre_g[p], lim = Lim_g[p];
    const float stp = expf(logstep[p]);
    const float* xr = g_x_re + (size_t)p * L_SEQ + l0;
    const float* xi = g_x_im + (size_t)p * L_SEQ + l0;

    float dt[VPT], bvr[VPT], bvi[VPT];
    {
        float4 d0 = *(const float4*)(dtv + l0);
        float4 d1 = *(const float4*)(dtv + l0 + 4);
        dt[0]=d0.x; dt[1]=d0.y; dt[2]=d0.z; dt[3]=d0.w;
        dt[4]=d1.x; dt[5]=d1.y; dt[6]=d1.z; dt[7]=d1.w;
        float4 r0 = *(const float4*)(xr), r1 = *(const float4*)(xr + 4);
        bvr[0]=r0.x; bvr[1]=r0.y; bvr[2]=r0.z; bvr[3]=r0.w;
        bvr[4]=r1.x; bvr[5]=r1.y; bvr[6]=r1.z; bvr[7]=r1.w;
        float4 i0 = *(const float4*)(xi), i1 = *(const float4*)(xi + 4);
        bvi[0]=i0.x; bvi[1]=i0.y; bvi[2]=i0.z; bvi[3]=i0.w;
        bvi[4]=i1.x; bvi[5]=i1.y; bvi[6]=i1.z; bvi[7]=i1.w;
    }

    float Ar, Ai, br, bi;
    lambda_bar(lre, lim, dt[0] * stp, Ar, Ai);
    br = bvr[0]; bi = bvi[0];
#pragma unroll
    for (int e = 1; e < VPT; e++) {
        float Aer, Aei;
        lambda_bar(lre, lim, dt[e] * stp, Aer, Aei);
        float nAr = Aer*Ar - Aei*Ai;
        float nAi = Aer*Ai + Aei*Ar;
        float nbr = Aer*br - Aei*bi + bvr[e];
        float nbi = Aer*bi + Aei*br + bvi[e];
        Ar = nAr; Ai = nAi; br = nbr; bi = nbi;
    }

#pragma unroll
    for (int off = 1; off < 32; off <<= 1) {
        float rAr = __shfl_down_sync(0xFFFFFFFFu, Ar, off);
        float rAi = __shfl_down_sync(0xFFFFFFFFu, Ai, off);
        float rbr = __shfl_down_sync(0xFFFFFFFFu, br, off);
        float rbi = __shfl_down_sync(0xFFFFFFFFu, bi, off);
        combine_left(Ar, Ai, br, bi, rAr, rAi, rbr, rbi);
    }

    __shared__ float sA_r[8], sA_i[8], sb_r[8], sb_i[8];
    int lane = tid & 31, wid = tid >> 5;
    if (lane == 0) { sA_r[wid] = Ar; sA_i[wid] = Ai; sb_r[wid] = br; sb_i[wid] = bi; }
    __syncthreads();

    if (wid == 0) {
        float aAr = (lane < 8) ? sA_r[lane] : 1.0f;
        float aAi = (lane < 8) ? sA_i[lane] : 0.0f;
        float abr = (lane < 8) ? sb_r[lane] : 0.0f;
        float abi = (lane < 8) ? sb_i[lane] : 0.0f;
#pragma unroll
        for (int off = 1; off < 8; off <<= 1) {
            float rAr = __shfl_down_sync(0xFFFFFFFFu, aAr, off);
            float rAi = __shfl_down_sync(0xFFFFFFFFu, aAi, off);
            float rbr = __shfl_down_sync(0xFFFFFFFFu, abr, off);
            float rbi = __shfl_down_sync(0xFFFFFFFFu, abi, off);
            combine_left(aAr, aAi, abr, abi, rAr, rAi, rbr, rbi);
        }
        if (lane == 0) {
            size_t o = ((size_t)p * NCHUNK + chunk) * 4;
            g_agg[o + 0] = aAr; g_agg[o + 1] = aAi;
            g_agg[o + 2] = abr; g_agg[o + 3] = abi;
        }
    }
}

// ======================== Scan phase B ========================
__global__ __launch_bounds__(32) void chunk_prefix()
{
    const int p = blockIdx.x;
    const int lane = threadIdx.x;

    float Ar = 1.0f, Ai = 0.0f, br = 0.0f, bi = 0.0f;
    if (lane < NCHUNK) {
        size_t o = ((size_t)p * NCHUNK + lane) * 4;
        Ar = g_agg[o + 0]; Ai = g_agg[o + 1];
        br = g_agg[o + 2]; bi = g_agg[o + 3];
    }

#pragma unroll
    for (int off = 1; off < NCHUNK; off <<= 1) {
        float pAr = __shfl_up_sync(0xFFFFFFFFu, Ar, off);
        float pAi = __shfl_up_sync(0xFFFFFFFFu, Ai, off);
        float pbr = __shfl_up_sync(0xFFFFFFFFu, br, off);
        float pbi = __shfl_up_sync(0xFFFFFFFFu, bi, off);
        if (lane >= off) combine_right(Ar, Ai, br, bi, pAr, pAi, pbr, pbi);
    }

    float er = __shfl_up_sync(0xFFFFFFFFu, br, 1);
    float ei = __shfl_up_sync(0xFFFFFFFFu, bi, 1);
    if (lane == 0) { er = 0.0f; ei = 0.0f; }
    if (lane < NCHUNK) {
        size_t q = ((size_t)p * NCHUNK + lane) * 2;
        g_pre[q] = er; g_pre[q + 1] = ei;
    }
}

// ======================== Scan phase C ========================
__global__ __launch_bounds__(SCAN_T) void scan_apply(
    const float* __restrict__ dtv, const float* __restrict__ Lre_g,
    const float* __restrict__ Lim_g, const float* __restrict__ logstep)
{
    const int p = blockIdx.y;
    const int chunk = blockIdx.x;
    const int tid = threadIdx.x;
    const int l0 = chunk * CHUNK + tid * VPT;
    const int lane = tid & 31, wid = tid >> 5;

    const float lre = Lre_g[p], lim = Lim_g[p];
    const float stp = expf(logstep[p]);
    const float* xr = g_x_re + (size_t)p * L_SEQ + l0;
    const float* xi = g_x_im + (size_t)p * L_SEQ + l0;

    float dt[VPT], bvr[VPT], bvi[VPT];
    {
        float4 d0 = *(const float4*)(dtv + l0);
        float4 d1 = *(const float4*)(dtv + l0 + 4);
        dt[0]=d0.x; dt[1]=d0.y; dt[2]=d0.z; dt[3]=d0.w;
        dt[4]=d1.x; dt[5]=d1.y; dt[6]=d1.z; dt[7]=d1.w;
        float4 r0 = *(const float4*)(xr), r1 = *(const float4*)(xr + 4);
        bvr[0]=r0.x; bvr[1]=r0.y; bvr[2]=r0.z; bvr[3]=r0.w;
        bvr[4]=r1.x; bvr[5]=r1.y; bvr[6]=r1.z; bvr[7]=r1.w;
        float4 i0 = *(const float4*)(xi), i1 = *(const float4*)(xi + 4);
        bvi[0]=i0.x; bvi[1]=i0.y; bvi[2]=i0.z; bvi[3]=i0.w;
        bvi[4]=i1.x; bvi[5]=i1.y; bvi[6]=i1.z; bvi[7]=i1.w;
    }

    float IAr[VPT], IAi[VPT], Ibr[VPT], Ibi[VPT];
    {
        float Aer, Aei;
        lambda_bar(lre, lim, dt[0] * stp, Aer, Aei);
        IAr[0] = Aer; IAi[0] = Aei; Ibr[0] = bvr[0]; Ibi[0] = bvi[0];
#pragma unroll
        for (int e = 1; e < VPT; e++) {
            lambda_bar(lre, lim, dt[e] * stp, Aer, Aei);
            IAr[e] = Aer*IAr[e-1] - Aei*IAi[e-1];
            IAi[e] = Aer*IAi[e-1] + Aei*IAr[e-1];
            Ibr[e] = Aer*Ibr[e-1] - Aei*Ibi[e-1] + bvr[e];
            Ibi[e] = Aer*Ibi[e-1] + Aei*Ibr[e-1] + bvi[e];
        }
    }

    float Ar = IAr[VPT-1], Ai = IAi[VPT-1], br = Ibr[VPT-1], bi = Ibi[VPT-1];
#pragma unroll
    for (int off = 1; off < 32; off <<= 1) {
        float pAr = __shfl_up_sync(0xFFFFFFFFu, Ar, off);
        float pAi = __shfl_up_sync(0xFFFFFFFFu, Ai, off);
        float pbr = __shfl_up_sync(0xFFFFFFFFu, br, off);
        float pbi = __shfl_up_sync(0xFFFFFFFFu, bi, off);
        if (lane >= off) combine_right(Ar, Ai, br, bi, pAr, pAi, pbr, pbi);
    }

    float EwAr = __shfl_up_sync(0xFFFFFFFFu, Ar, 1);
    float EwAi = __shfl_up_sync(0xFFFFFFFFu, Ai, 1);
    float Ewbr = __shfl_up_sync(0xFFFFFFFFu, br, 1);
    float Ewbi = __shfl_up_sync(0xFFFFFFFFu, bi, 1);
    if (lane == 0) { EwAr = 1.0f; EwAi = 0.0f; Ewbr = 0.0f; Ewbi = 0.0f; }

    __shared__ float sW[8][4];
    if (lane == 31) { sW[wid][0] = Ar; sW[wid][1] = Ai; sW[wid][2] = br; sW[wid][3] = bi; }
    __syncthreads();

    float PAr = 1.0f, PAi = 0.0f, Pbr = 0.0f, Pbi = 0.0f;
#pragma unroll
    for (int w = 0; w < 7; w++) {
        if (w < wid) {
            float wAr = sW[w][0], wAi = sW[w][1], wbr = sW[w][2], wbi = sW[w][3];
            float nAr = wAr*PAr - wAi*PAi;
            float nAi = wAr*PAi + wAi*PAr;
            float nbr = wAr*Pbr - wAi*Pbi + wbr;
            float nbi = wAr*Pbi + wAi*Pbr + wbi;
            PAr = nAr; PAi = nAi; Pbr = nbr; Pbi = nbi;
        }
    }

    float EAr = EwAr*PAr - EwAi*PAi;
    float EAi = EwAr*PAi + EwAi*PAr;
    float Ebr = EwAr*Pbr - EwAi*Pbi + Ewbr;
    float Ebi = EwAr*Pbi + EwAi*Pbr + Ewbi;

    size_t q = ((size_t)p * NCHUNK + chunk) * 2;
    float pcr = g_pre[q], pci = g_pre[q + 1];
    float xpr = EAr*pcr - EAi*pci + Ebr;
    float xpi = EAr*pci + EAi*pcr + Ebi;

    float o_r[VPT], o_i[VPT];
#pragma unroll
    for (int e = 0; e < VPT; e++) {
        o_r[e] = IAr[e]*xpr - IAi[e]*xpi + Ibr[e];
        o_i[e] = IAr[e]*xpi + IAi[e]*xpr + Ibi[e];
    }
    *(uint4*)(g_xrbf + (size_t)p * L_SEQ + l0) =
        make_uint4(packbf(o_r[0], o_r[1]), packbf(o_r[2], o_r[3]),
                   packbf(o_r[4], o_r[5]), packbf(o_r[6], o_r[7]));
    *(uint4*)(g_xibf + (size_t)p * L_SEQ + l0) =
        make_uint4(packbf(o_i[0], o_i[1]), packbf(o_i[2], o_i[3]),
                   packbf(o_i[4], o_i[5]), packbf(o_i[6], o_i[7]));
}

// ======================== pack_x: build gemm2 A image (pair-packed natural, im negated) ========
__global__ __launch_bounds__(256) void pack_x()
{
    int id = blockIdx.x * 256 + threadIdx.x;   // 2 pl x 16 kg x 8192 l4
    int l4 = id & 8191;
    int kg = (id >> 13) & 15;
    int pl = id >> 17;
    const uint16_t* base = (pl ? g_xibf : g_xrbf) + (size_t)(kg * 16) * L_SEQ + l4 * 4;
    const uint32_t neg = pl ? 0x80008000u : 0u;

    ushort4 fe[8], fo[8];
#pragma unroll
    for (int jp = 0; jp < 8; jp++) {
        fe[jp] = *(const ushort4*)(base + (size_t)(2 * jp) * L_SEQ);
        fo[jp] = *(const ushort4*)(base + (size_t)(2 * jp + 1) * L_SEQ);
    }
    uint32_t* dst = g_xp + ((size_t)(pl * 16 + kg) * L_SEQ + l4 * 4) * 8;
#pragma unroll
    for (int li = 0; li < 4; li++) {
        uint32_t row[8];
#pragma unroll
        for (int jp = 0; jp < 8; jp++) {
            uint16_t e = (li == 0) ? fe[jp].x : (li == 1) ? fe[jp].y : (li == 2) ? fe[jp].z : fe[jp].w;
            uint16_t o = (li == 0) ? fo[jp].x : (li == 1) ? fo[jp].y : (li == 2) ? fo[jp].z : fo[jp].w;
            row[jp] = (((uint32_t)e) | ((uint32_t)o << 16)) ^ neg;
        }
        *(uint4*)(dst + li * 8)     = make_uint4(row[0], row[1], row[2], row[3]);
        *(uint4*)(dst + li * 8 + 4) = make_uint4(row[4], row[5], row[6], row[7]);
    }
}

// ======================== GEMM2: 256 thr, 3 CTA/SM, 3-stage cp.async + ldmatrix ===============
// y = 2*(xre Cre^T - xim Cim^T) + D*u. BM=64 l, BN=128 h, BK=32 p. 8 steps.
// Warp grid 2m x 4n, warp tile 32l x 32h.
// Buffer bytes: Ar[0..4095] (2kg x 64row x 32B), Ai[4096..8191],
//               Br[8192..16383] (2kg x 128row x 32B), Bi[16384..24575]
#define G2_BUFB 24576
#define G2_SMEM_BYTES (3 * G2_BUFB)   // 73728

__global__ __launch_bounds__(256, 3) void gemm2(
    const float* __restrict__ u, const float* __restrict__ Dg,
    float* __restrict__ out)
{
    extern __shared__ uint32_t sm2[];
    const uint32_t smb = smem_u32(sm2);
    const int tid = threadIdx.x;
    const int wid = tid >> 5, lane = tid & 31;
    const int g = lane >> 2, t = lane & 3;
    const int wm = wid >> 2, wn = wid & 3;        // 2x4 warps, warp tile 32l x 32h
    const int bn = blockIdx.x * 128;
    const int bm = blockIdx.y * 64;

    const int qr = lane & 7, sel = lane >> 3;
    const uint32_t aoff0 = swz(wm * 32 + 0 * 16 + (sel & 1) * 8 + qr, sel >> 1);
    const uint32_t aoff1 = swz(wm * 32 + 1 * 16 + (sel & 1) * 8 + qr, sel >> 1);
    // B: two x4 loads cover n-tiles 0,1 and 2,3
    const uint32_t boff0 = swz(wn * 32 + (sel >> 1) * 8 + qr, sel & 1);
    const uint32_t boff1 = swz(wn * 32 + 16 + (sel >> 1) * 8 + qr, sel & 1);

    float acc[2][4][4];
#pragma unroll
    for (int i = 0; i < 2; i++)
#pragma unroll
        for (int j = 0; j < 4; j++)
#pragma unroll
            for (int r = 0; r < 4; r++) acc[i][j][r] = 0.0f;

    auto copy_step = [&](int s, int buf) {
        uint32_t sb = smb + buf * G2_BUFB;
        int kg = 2 * s;
        // A: 512 chunks (Ar 256, Ai 256; each kg 128 chunks)
#pragma unroll
        for (int j = 0; j < 2; j++) {
            int c = tid + j * 256;
            int sel2 = c >> 8, cc = c & 255;
            int grp = cc >> 7, off = cc & 127;
            CP_ASYNC16(sb + sel2 * 4096 + grp * 2048 + cswz(off) * 16,
                       (const char*)(g_xp + ((size_t)(sel2 * 16 + kg + grp) * L_SEQ + bm) * 8) + off * 16);
        }
        // B: 1024 chunks (Br 512, Bi 512; each kg 256 chunks)
#pragma unroll
        for (int j = 0; j < 4; j++) {
            int c = tid + j * 256;
            int sel2 = c >> 9, cc = c & 511;
            int grp = cc >> 8, off = cc & 255;
            CP_ASYNC16(sb + 8192 + sel2 * 8192 + grp * 4096 + cswz(off) * 16,
                       (const char*)(g_Cp + ((size_t)(sel2 * 16 + kg + grp) * 512 + bn) * 8) + off * 16);
        }
    };

    copy_step(0, 0); CP_COMMIT();
    copy_step(1, 1); CP_COMMIT();

    for (int s = 0; s < 8; s++) {
        if (s < 7) CP_WAIT1(); else CP_WAIT0();
        __syncthreads();
        if (s + 2 < 8) { copy_step(s + 2, (s + 2) % 3); CP_COMMIT(); }

        const uint32_t curb = smb + (s % 3) * G2_BUFB;
#pragma unroll
        for (int k16 = 0; k16 < 2; k16++) {
            uint32_t ar[2][4], ai[2][4];
            LDSM_X4(ar[0][0], ar[0][1], ar[0][2], ar[0][3], curb + k16 * 2048 + aoff0);
            LDSM_X4(ar[1][0], ar[1][1], ar[1][2], ar[1][3], curb + k16 * 2048 + aoff1);
            LDSM_X4(ai[0][0], ai[0][1], ai[0][2], ai[0][3], curb + 4096 + k16 * 2048 + aoff0);
            LDSM_X4(ai[1][0], ai[1][1], ai[1][2], ai[1][3], curb + 4096 + k16 * 2048 + aoff1);
            uint32_t brg[8], big[8];
            uint32_t bb = curb + 8192 + k16 * 4096;
            LDSM_X4(brg[0], brg[1], brg[2], brg[3], bb + boff0);
            LDSM_X4(brg[4], brg[5], brg[6], brg[7], bb + boff1);
            LDSM_X4(big[0], big[1], big[2], big[3], bb + 8192 + boff0);
            LDSM_X4(big[4], big[5], big[6], big[7], bb + 8192 + boff1);
#pragma unroll
            for (int nt = 0; nt < 4; nt++) {
#pragma unroll
                for (int mt = 0; mt < 2; mt++) {
                    mma_bf16(acc[mt][nt], ar[mt], brg[nt * 2], brg[nt * 2 + 1]);
                    mma_bf16(acc[mt][nt], ai[mt], big[nt * 2], big[nt * 2 + 1]);
                }
            }
        }
    }

    // epilogue: y = 2*acc + D*u
#pragma unroll
    for (int mt = 0; mt < 2; mt++) {
#pragma unroll
        for (int rh = 0; rh < 2; rh++) {
            int l = bm + wm * 32 + mt * 16 + g + rh * 8;
#pragma unroll
            for (int nt = 0; nt < 4; nt++) {
                int h0 = bn + wn * 32 + nt * 8 + 2 * t;
                float2 uu = *(const float2*)(u + (size_t)l * H_DIM + h0);
                float2 dd = *(const float2*)(Dg + h0);
                float2 o;
                o.x = 2.0f * acc[mt][nt][rh * 2 + 0] + dd.x * uu.x;
                o.y = 2.0f * acc[mt][nt][rh * 2 + 1] + dd.y * uu.y;
                *(float2*)(out + (size_t)l * H_DIM + h0) = o;
            }
        }
    }
}

// ======================== launch ========================
extern "C" void kernel_launch(void* const* d_in, const int* in_sizes, int n_in,
                              void* d_out, int out_size)
{
    const float* u   = (const float*)d_in[0];  // (L, H)
    const float* dtv = (const float*)d_in[1];  // (L,)
    const float* Lre = (const float*)d_in[2];  // (P,)
    const float* Lim = (const float*)d_in[3];  // (P,)
    const float* Bre = (const float*)d_in[4];  // (P, H)
    const float* Bim = (const float*)d_in[5];  // (P, H)
    const float* Cre = (const float*)d_in[6];  // (H, P)
    const float* Cim = (const float*)d_in[7];  // (H, P)
    const float* Dg  = (const float*)d_in[8];  // (H,)
    const float* lst = (const float*)d_in[9];  // (P,)
    float* out = (float*)d_out;                // (L, H)

    static int attr_done = 0;
    if (!attr_done) {
        cudaFuncSetAttribute(gemm1, cudaFuncAttributeMaxDynamicSharedMemorySize, G1_SMEM_BYTES);
        cudaFuncSetAttribute(gemm2, cudaFuncAttributeMaxDynamicSharedMemorySize, G2_SMEM_BYTES);
        attr_done = 1;
    }

    convert_u_p<<<(32 * L_SEQ) / 256, 256>>>(u);
    convert_B_p<<<dim3(32, 2), 256>>>(Bre, Bim);
    convert_C_p<<<dim3(16, 2), 512>>>(Cre, Cim);
    gemm1<<<dim3(P_DIM / 32, L_SEQ / 128), 256, G1_SMEM_BYTES>>>(dtv, Lre, Lim, lst);
    scan_agg<<<dim3(NCHUNK, P_DIM), SCAN_T>>>(dtv, Lre, Lim, lst);
    chunk_prefix<<<P_DIM, 32>>>();
    scan_apply<<<dim3(NCHUNK, P_DIM), SCAN_T>>>(dtv, Lre, Lim, lst);
    pack_x<<<(2 * 16 * (L_SEQ / 4)) / 256, 256>>>();
    gemm2<<<dim3(H_DIM / 128, L_SEQ / 64), 256, G2_SMEM_BYTES>>>(u, Dg, out);
}